// round 1
// baseline (speedup 1.0000x reference)
#include <cuda_runtime.h>
#include <math.h>

#define N_NODES  10000
#define IN_SIZE  512
#define H_SIZE   512
#define OUT_SIZE 64
#define N_EDGES  163840

// ---------------- scratch (no allocations allowed) ----------------
__device__ float g_deg [N_NODES];
__device__ float g_dinv[N_NODES];
__device__ float g_h1  [N_NODES * H_SIZE];    // x@W1, later reused for relu output
__device__ float g_agg1[N_NODES * H_SIZE];    // aggregated layer-1
__device__ float g_h2  [N_NODES * OUT_SIZE];  // h1r@W2
__device__ float g_agg2[N_NODES * OUT_SIZE];  // aggregated layer-2

// ---------------- degree / norm ----------------
__global__ void deg_init_kernel() {
    int n = blockIdx.x * blockDim.x + threadIdx.x;
    if (n < N_NODES) g_deg[n] = 1.0f;   // self-loop
}

__global__ void deg_count_kernel(const int* __restrict__ dst) {
    int e = blockIdx.x * blockDim.x + threadIdx.x;
    if (e < N_EDGES) atomicAdd(&g_deg[dst[e]], 1.0f);
}

__global__ void dinv_kernel() {
    int n = blockIdx.x * blockDim.x + threadIdx.x;
    if (n < N_NODES) g_dinv[n] = rsqrtf(g_deg[n]);
}

// ---------------- fp32 tiled GEMM with self-loop epilogue ----------------
// C = A[MxK] @ B[KxN];  Cagg = dinv[row]^2 * C   (self-loop init for scatter)
#define BM 64
#define BN 64
#define BK 16

__global__ __launch_bounds__(256) void gemm_epi_kernel(
    const float* __restrict__ A, const float* __restrict__ B,
    float* __restrict__ C, float* __restrict__ Cagg,
    const float* __restrict__ dinv, int M, int N, int K)
{
    __shared__ float As[BK][BM + 4];   // k-major, padded
    __shared__ float Bs[BK][BN];

    const int tid = threadIdx.x;
    const int tx = tid & 15;           // 0..15 -> col group
    const int ty = tid >> 4;           // 0..15 -> row group
    const int brow = blockIdx.y * BM;
    const int bcol = blockIdx.x * BN;

    const int aRow = tid >> 2;         // 0..63
    const int aK   = (tid & 3) * 4;    // 0,4,8,12
    const int bRow = ty;               // 0..15
    const int bCol = tx * 4;           // 0..60

    float acc[4][4];
    #pragma unroll
    for (int i = 0; i < 4; i++)
        #pragma unroll
        for (int j = 0; j < 4; j++) acc[i][j] = 0.0f;

    for (int kk = 0; kk < K; kk += BK) {
        float4 av = make_float4(0.f, 0.f, 0.f, 0.f);
        int gr = brow + aRow;
        if (gr < M) av = *(const float4*)&A[(size_t)gr * K + kk + aK];
        As[aK + 0][aRow] = av.x;
        As[aK + 1][aRow] = av.y;
        As[aK + 2][aRow] = av.z;
        As[aK + 3][aRow] = av.w;

        float4 bv = *(const float4*)&B[(size_t)(kk + bRow) * N + bcol + bCol];
        *(float4*)&Bs[bRow][bCol] = bv;
        __syncthreads();

        #pragma unroll
        for (int k = 0; k < BK; k++) {
            float4 a4 = *(const float4*)&As[k][ty * 4];
            float4 b4 = *(const float4*)&Bs[k][tx * 4];
            float a[4] = {a4.x, a4.y, a4.z, a4.w};
            float b[4] = {b4.x, b4.y, b4.z, b4.w};
            #pragma unroll
            for (int i = 0; i < 4; i++)
                #pragma unroll
                for (int j = 0; j < 4; j++)
                    acc[i][j] = fmaf(a[i], b[j], acc[i][j]);
        }
        __syncthreads();
    }

    #pragma unroll
    for (int i = 0; i < 4; i++) {
        int row = brow + ty * 4 + i;
        if (row >= M) break;
        float di  = dinv[row];
        float di2 = di * di;
        float4 c = make_float4(acc[i][0], acc[i][1], acc[i][2], acc[i][3]);
        *(float4*)&C[(size_t)row * N + bcol + tx * 4] = c;
        float4 g = make_float4(c.x * di2, c.y * di2, c.z * di2, c.w * di2);
        *(float4*)&Cagg[(size_t)row * N + bcol + tx * 4] = g;
    }
}

// ---------------- edge scatter (vector red) ----------------
__device__ __forceinline__ void red_add_v4(float* p, float4 v) {
    asm volatile("red.global.add.v4.f32 [%0], {%1, %2, %3, %4};"
                 :: "l"(p), "f"(v.x), "f"(v.y), "f"(v.z), "f"(v.w) : "memory");
}

// one block (128 threads) per edge, 512 features
__global__ __launch_bounds__(128) void scatter512_kernel(
    const int* __restrict__ src, const int* __restrict__ dst)
{
    int e = blockIdx.x;
    int s = src[e], d = dst[e];
    float norm = g_dinv[s] * g_dinv[d];
    int f = threadIdx.x * 4;
    float4 v = *(const float4*)&g_h1[(size_t)s * H_SIZE + f];
    v.x *= norm; v.y *= norm; v.z *= norm; v.w *= norm;
    red_add_v4(&g_agg1[(size_t)d * H_SIZE + f], v);
}

// 16 threads per edge, 64 features (float4 each)
__global__ __launch_bounds__(256) void scatter64_kernel(
    const int* __restrict__ src, const int* __restrict__ dst)
{
    int t = blockIdx.x * blockDim.x + threadIdx.x;
    int e = t >> 4;
    if (e >= N_EDGES) return;
    int f = (t & 15) * 4;
    int s = src[e], d = dst[e];
    float norm = g_dinv[s] * g_dinv[d];
    float4 v = *(const float4*)&g_h2[(size_t)s * OUT_SIZE + f];
    v.x *= norm; v.y *= norm; v.z *= norm; v.w *= norm;
    red_add_v4(&g_agg2[(size_t)d * OUT_SIZE + f], v);
}

// ---------------- bias + relu (writes back into g_h1) ----------------
__global__ void bias_relu_kernel(const float* __restrict__ b1) {
    int i = blockIdx.x * blockDim.x + threadIdx.x;
    if (i < N_NODES * H_SIZE)
        g_h1[i] = fmaxf(g_agg1[i] + b1[i & (H_SIZE - 1)], 0.0f);
}

// ---------------- bias + log_softmax, write both outputs ----------------
// one warp per row (64 cols -> 2 per lane)
__global__ void final_kernel(const float* __restrict__ b2, float* __restrict__ out) {
    int warp = (blockIdx.x * blockDim.x + threadIdx.x) >> 5;
    int lane = threadIdx.x & 31;
    if (warp >= N_NODES) return;
    const float* row = g_agg2 + (size_t)warp * OUT_SIZE;
    float v0 = row[lane]      + b2[lane];
    float v1 = row[lane + 32] + b2[lane + 32];
    out[(size_t)warp * OUT_SIZE + lane]      = v0;
    out[(size_t)warp * OUT_SIZE + lane + 32] = v1;
    float m = fmaxf(v0, v1);
    #pragma unroll
    for (int o = 16; o; o >>= 1) m = fmaxf(m, __shfl_xor_sync(0xffffffffu, m, o));
    float s = __expf(v0 - m) + __expf(v1 - m);
    #pragma unroll
    for (int o = 16; o; o >>= 1) s += __shfl_xor_sync(0xffffffffu, s, o);
    float lse = m + __logf(s);
    float* out2 = out + (size_t)N_NODES * OUT_SIZE;
    out2[(size_t)warp * OUT_SIZE + lane]      = v0 - lse;
    out2[(size_t)warp * OUT_SIZE + lane + 32] = v1 - lse;
}

// ---------------- launch ----------------
extern "C" void kernel_launch(void* const* d_in, const int* in_sizes, int n_in,
                              void* d_out, int out_size)
{
    const float* x  = (const float*)d_in[0];
    const int*   ei = (const int*)  d_in[1];
    const float* W1 = (const float*)d_in[2];
    const float* b1 = (const float*)d_in[3];
    const float* W2 = (const float*)d_in[4];
    const float* b2 = (const float*)d_in[5];
    float* out = (float*)d_out;

    const int* src = ei;
    const int* dst = ei + N_EDGES;

    float *p_dinv;
    cudaGetSymbolAddress((void**)&p_dinv, g_dinv);
    float *p_h1, *p_agg1, *p_h2, *p_agg2;
    cudaGetSymbolAddress((void**)&p_h1,   g_h1);
    cudaGetSymbolAddress((void**)&p_agg1, g_agg1);
    cudaGetSymbolAddress((void**)&p_h2,   g_h2);
    cudaGetSymbolAddress((void**)&p_agg2, g_agg2);

    // degrees / norms
    deg_init_kernel <<<(N_NODES + 255) / 256, 256>>>();
    deg_count_kernel<<<(N_EDGES + 255) / 256, 256>>>(dst);
    dinv_kernel     <<<(N_NODES + 255) / 256, 256>>>();

    // layer 1: h1 = x@W1, agg1 init = dinv^2 * h1 (self-loop)
    {
        dim3 grid(H_SIZE / BN, (N_NODES + BM - 1) / BM);
        gemm_epi_kernel<<<grid, 256>>>(x, W1, p_h1, p_agg1, p_dinv,
                                       N_NODES, H_SIZE, IN_SIZE);
    }
    scatter512_kernel<<<N_EDGES, 128>>>(src, dst);
    bias_relu_kernel <<<(N_NODES * H_SIZE + 255) / 256, 256>>>(b1);

    // layer 2: h2 = relu(h1)@W2, agg2 init = dinv^2 * h2
    {
        dim3 grid(OUT_SIZE / BN, (N_NODES + BM - 1) / BM);
        gemm_epi_kernel<<<grid, 256>>>(p_h1, W2, p_h2, p_agg2, p_dinv,
                                       N_NODES, OUT_SIZE, H_SIZE);
    }
    scatter64_kernel<<<(N_EDGES * 16 + 255) / 256, 256>>>(src, dst);

    // bias + write h, log_softmax
    final_kernel<<<(N_NODES + 7) / 8, 256>>>(b2, out);
}

// round 4
// speedup vs baseline: 1.1302x; 1.1302x over previous
#include <cuda_runtime.h>
#include <math.h>

#define N_NODES  10000
#define IN_SIZE  512
#define H_SIZE   512
#define OUT_SIZE 64
#define N_EDGES  163840

// ---------------- scratch (no allocations allowed) ----------------
__device__ float g_deg [N_NODES];
__device__ float g_dinv[N_NODES];
__device__ float g_xr  [N_NODES * IN_SIZE];   // tf32-rounded x
__device__ float g_w1r [IN_SIZE * H_SIZE];    // tf32-rounded W1
__device__ float g_w2r [H_SIZE * OUT_SIZE];   // tf32-rounded W2
__device__ float g_h1  [N_NODES * H_SIZE];    // x@W1 (fp32); later relu(agg1+b1) tf32-rounded
__device__ float g_agg1[N_NODES * H_SIZE];
__device__ float g_h2  [N_NODES * OUT_SIZE];
__device__ float g_agg2[N_NODES * OUT_SIZE];

// ---------------- degree / norm ----------------
__global__ void deg_init_kernel() {
    int n = blockIdx.x * blockDim.x + threadIdx.x;
    if (n < N_NODES) g_deg[n] = 1.0f;   // self-loop
}

__global__ void deg_count_kernel(const int* __restrict__ dst) {
    int e = blockIdx.x * blockDim.x + threadIdx.x;
    if (e < N_EDGES) atomicAdd(&g_deg[dst[e]], 1.0f);
}

__global__ void dinv_kernel() {
    int n = blockIdx.x * blockDim.x + threadIdx.x;
    if (n < N_NODES) g_dinv[n] = rsqrtf(g_deg[n]);
}

// ---------------- tf32 rounding (rna) ----------------
__device__ __forceinline__ unsigned to_tf32(float f) {
    unsigned o;
    asm("cvt.rna.tf32.f32 %0, %1;" : "=r"(o) : "f"(f));
    return o;
}

__global__ void round_tf32_kernel(const float* __restrict__ in, float* __restrict__ out, int n4) {
    int i = blockIdx.x * blockDim.x + threadIdx.x;
    if (i < n4) {
        float4 v = ((const float4*)in)[i];
        uint4 o;
        o.x = to_tf32(v.x); o.y = to_tf32(v.y);
        o.z = to_tf32(v.z); o.w = to_tf32(v.w);
        ((uint4*)out)[i] = o;
    }
}

// ---------------- tf32 tensor-core GEMM with self-loop epilogue ----------------
// C = A[MxK] @ B[KxN] (A,B pre-rounded to tf32); Cagg = dinv[row]^2 * C
__device__ __forceinline__ void mma_tf32(float* d,
    unsigned a0, unsigned a1, unsigned a2, unsigned a3,
    unsigned b0, unsigned b1)
{
    asm volatile(
        "mma.sync.aligned.m16n8k8.row.col.f32.tf32.tf32.f32 "
        "{%0,%1,%2,%3}, {%4,%5,%6,%7}, {%8,%9}, {%0,%1,%2,%3};"
        : "+f"(d[0]), "+f"(d[1]), "+f"(d[2]), "+f"(d[3])
        : "r"(a0), "r"(a1), "r"(a2), "r"(a3), "r"(b0), "r"(b1));
}

// Warp tile 64x32 (4x4 m16n8 tiles). Block: (T/32) warps as (T/32/WN) x WN grid.
template<int BM, int BN, int T, int WN>
__global__ __launch_bounds__(T) void gemm_tf32_kernel(
    const float* __restrict__ A, const float* __restrict__ B,
    float* __restrict__ C, float* __restrict__ Cagg,
    const float* __restrict__ dinv, int M, int N, int K)
{
    constexpr int BK = 32;
    constexpr int AS_STRIDE = 40;       // == 8 (mod 32): 2-phase LDS.64 frag loads
    constexpr int BS_STRIDE = BN + 4;   // == 4 (mod 16) in 8B units: conflict-free
    constexpr int NA = BM * BK / (4 * T);
    constexpr int NB = BK * BN / (4 * T);

    extern __shared__ float smem[];
    float* AsBase = smem;                         // [2][BM][AS_STRIDE]
    float* BsBase = smem + 2 * BM * AS_STRIDE;    // [2][BK][BS_STRIDE]

    const int tid  = threadIdx.x;
    const int wid  = tid >> 5;
    const int lane = tid & 31;
    const int lr   = lane >> 2;   // 0..7
    const int lc   = lane & 3;    // 0..3
    const int wm   = wid / WN;
    const int wn   = wid % WN;
    const int wrow = wm * 64;
    const int wcol = wn * 32;
    const int brow = blockIdx.y * BM;
    const int bcol = blockIdx.x * BN;

    float acc[4][4][4];
    #pragma unroll
    for (int i = 0; i < 4; i++)
        #pragma unroll
        for (int j = 0; j < 4; j++)
            #pragma unroll
            for (int q = 0; q < 4; q++) acc[i][j][q] = 0.0f;

    float4 ra[NA], rb[NB];

    // --- stage a K-tile from gmem into registers ---
    auto ldg_tile = [&](int kk) {
        #pragma unroll
        for (int p = 0; p < NA; p++) {
            int idx = tid + p * T;
            int r = idx >> 3, c4 = (idx & 7) << 2;
            int grow = brow + r;
            ra[p] = (grow < M) ? *(const float4*)&A[(size_t)grow * K + kk + c4]
                               : make_float4(0.f, 0.f, 0.f, 0.f);
        }
        #pragma unroll
        for (int p = 0; p < NB; p++) {
            int idx = tid + p * T;
            int k = idx / (BN / 4), n4 = (idx % (BN / 4)) << 2;
            rb[p] = *(const float4*)&B[(size_t)(kk + k) * N + bcol + n4];
        }
    };

    auto sts_tile = [&](int buf) {
        float* as = AsBase + buf * BM * AS_STRIDE;
        float* bs = BsBase + buf * BK * BS_STRIDE;
        #pragma unroll
        for (int p = 0; p < NA; p++) {
            int idx = tid + p * T;
            int r = idx >> 3, c4 = (idx & 7) << 2;
            *(float4*)&as[r * AS_STRIDE + c4] = ra[p];
        }
        #pragma unroll
        for (int p = 0; p < NB; p++) {
            int idx = tid + p * T;
            int k = idx / (BN / 4), n4 = (idx % (BN / 4)) << 2;
            float* bp = &bs[k * BS_STRIDE + n4];
            bp[0] = rb[p].x; bp[1] = rb[p].y; bp[2] = rb[p].z; bp[3] = rb[p].w;
        }
    };

    auto compute = [&](int buf) {
        const float* as = AsBase + buf * BM * AS_STRIDE;
        const float* bs = BsBase + buf * BK * BS_STRIDE;
        #pragma unroll
        for (int s = 0; s < 4; s++) {
            const int kb = s * 8 + lc * 2;   // k-pair (permuted k within k8: ok, A&B match)
            uint2 af[4][2];
            #pragma unroll
            for (int i = 0; i < 4; i++) {
                const float* p = &as[(wrow + i * 16 + lr) * AS_STRIDE + kb];
                af[i][0] = *(const uint2*)p;
                af[i][1] = *(const uint2*)(p + 8 * AS_STRIDE);
            }
            unsigned bf0[4], bf1[4];
            #pragma unroll
            for (int j = 0; j < 4; j++) {
                const float* p = &bs[kb * BS_STRIDE + wcol + j * 8 + lr];
                bf0[j] = __float_as_uint(p[0]);
                bf1[j] = __float_as_uint(p[BS_STRIDE]);
            }
            #pragma unroll
            for (int i = 0; i < 4; i++)
                #pragma unroll
                for (int j = 0; j < 4; j++)
                    mma_tf32(acc[i][j],
                             af[i][0].x, af[i][1].x, af[i][0].y, af[i][1].y,
                             bf0[j], bf1[j]);
        }
    };

    // --- pipelined mainloop (double-buffered smem, register-staged LDG) ---
    ldg_tile(0);
    sts_tile(0);
    __syncthreads();
    int buf = 0;
    const int ntiles = K / BK;
    for (int t = 0; t < ntiles; t++) {
        if (t + 1 < ntiles) ldg_tile((t + 1) * BK);
        compute(buf);
        if (t + 1 < ntiles) {
            sts_tile(buf ^ 1);
            __syncthreads();
            buf ^= 1;
        }
    }

    // --- epilogue: C and Cagg = dinv^2 * C ---
    #pragma unroll
    for (int i = 0; i < 4; i++) {
        int r0 = brow + wrow + i * 16 + lr;
        #pragma unroll
        for (int half = 0; half < 2; half++) {
            int r = r0 + half * 8;
            if (r < M) {
                float di  = dinv[r];
                float di2 = di * di;
                #pragma unroll
                for (int j = 0; j < 4; j++) {
                    int cc = bcol + wcol + j * 8 + lc * 2;
                    float2 v = make_float2(acc[i][j][half * 2 + 0], acc[i][j][half * 2 + 1]);
                    *(float2*)&C[(size_t)r * N + cc] = v;
                    *(float2*)&Cagg[(size_t)r * N + cc] = make_float2(v.x * di2, v.y * di2);
                }
            }
        }
    }
}

// ---------------- edge scatter (vector red) ----------------
__device__ __forceinline__ void red_add_v4(float* p, float4 v) {
    asm volatile("red.global.add.v4.f32 [%0], {%1, %2, %3, %4};"
                 :: "l"(p), "f"(v.x), "f"(v.y), "f"(v.z), "f"(v.w) : "memory");
}

// one block (128 threads) per edge, 512 features
__global__ __launch_bounds__(128) void scatter512_kernel(
    const int* __restrict__ src, const int* __restrict__ dst)
{
    int e = blockIdx.x;
    int s = src[e], d = dst[e];
    float norm = g_dinv[s] * g_dinv[d];
    int f = threadIdx.x * 4;
    float4 v = *(const float4*)&g_h1[(size_t)s * H_SIZE + f];
    v.x *= norm; v.y *= norm; v.z *= norm; v.w *= norm;
    red_add_v4(&g_agg1[(size_t)d * H_SIZE + f], v);
}

// 16 threads per edge, 64 features (float4 each)
__global__ __launch_bounds__(256) void scatter64_kernel(
    const int* __restrict__ src, const int* __restrict__ dst)
{
    int t = blockIdx.x * blockDim.x + threadIdx.x;
    int e = t >> 4;
    if (e >= N_EDGES) return;
    int f = (t & 15) * 4;
    int s = src[e], d = dst[e];
    float norm = g_dinv[s] * g_dinv[d];
    float4 v = *(const float4*)&g_h2[(size_t)s * OUT_SIZE + f];
    v.x *= norm; v.y *= norm; v.z *= norm; v.w *= norm;
    red_add_v4(&g_agg2[(size_t)d * OUT_SIZE + f], v);
}

// ---------------- bias + relu + tf32 round (writes into g_h1, GEMM2 input) ----------------
__global__ void bias_relu_round_kernel(const float* __restrict__ b1) {
    int i = blockIdx.x * blockDim.x + threadIdx.x;
    if (i < N_NODES * H_SIZE) {
        float v = fmaxf(g_agg1[i] + b1[i & (H_SIZE - 1)], 0.0f);
        g_h1[i] = __uint_as_float(to_tf32(v));
    }
}

// ---------------- bias + log_softmax, write both outputs ----------------
__global__ void final_kernel(const float* __restrict__ b2, float* __restrict__ out) {
    int warp = (blockIdx.x * blockDim.x + threadIdx.x) >> 5;
    int lane = threadIdx.x & 31;
    if (warp >= N_NODES) return;
    const float* row = g_agg2 + (size_t)warp * OUT_SIZE;
    float v0 = row[lane]      + b2[lane];
    float v1 = row[lane + 32] + b2[lane + 32];
    out[(size_t)warp * OUT_SIZE + lane]      = v0;
    out[(size_t)warp * OUT_SIZE + lane + 32] = v1;
    float m = fmaxf(v0, v1);
    #pragma unroll
    for (int o = 16; o; o >>= 1) m = fmaxf(m, __shfl_xor_sync(0xffffffffu, m, o));
    float s = __expf(v0 - m) + __expf(v1 - m);
    #pragma unroll
    for (int o = 16; o; o >>= 1) s += __shfl_xor_sync(0xffffffffu, s, o);
    float lse = m + __logf(s);
    float* out2 = out + (size_t)N_NODES * OUT_SIZE;
    out2[(size_t)warp * OUT_SIZE + lane]      = v0 - lse;
    out2[(size_t)warp * OUT_SIZE + lane + 32] = v1 - lse;
}

// ---------------- launch ----------------
extern "C" void kernel_launch(void* const* d_in, const int* in_sizes, int n_in,
                              void* d_out, int out_size)
{
    const float* x  = (const float*)d_in[0];
    const int*   ei = (const int*)  d_in[1];
    const float* W1 = (const float*)d_in[2];
    const float* b1 = (const float*)d_in[3];
    const float* W2 = (const float*)d_in[4];
    const float* b2 = (const float*)d_in[5];
    float* out = (float*)d_out;

    const int* src = ei;
    const int* dst = ei + N_EDGES;

    float *p_dinv, *p_xr, *p_w1r, *p_w2r, *p_h1, *p_agg1, *p_h2, *p_agg2;
    cudaGetSymbolAddress((void**)&p_dinv, g_dinv);
    cudaGetSymbolAddress((void**)&p_xr,   g_xr);
    cudaGetSymbolAddress((void**)&p_w1r,  g_w1r);
    cudaGetSymbolAddress((void**)&p_w2r,  g_w2r);
    cudaGetSymbolAddress((void**)&p_h1,   g_h1);
    cudaGetSymbolAddress((void**)&p_agg1, g_agg1);
    cudaGetSymbolAddress((void**)&p_h2,   g_h2);
    cudaGetSymbolAddress((void**)&p_agg2, g_agg2);

    const int SMEM1 = (2 * 128 * 40 + 2 * 32 * 132) * 4;  // 74752 B
    const int SMEM2 = (2 * 128 * 40 + 2 * 32 * 68)  * 4;  // 58368 B
    cudaFuncSetAttribute(gemm_tf32_kernel<128, 128, 256, 4>,
                         cudaFuncAttributeMaxDynamicSharedMemorySize, SMEM1);
    cudaFuncSetAttribute(gemm_tf32_kernel<128, 64, 128, 2>,
                         cudaFuncAttributeMaxDynamicSharedMemorySize, SMEM2);

    // degrees / norms
    deg_init_kernel <<<(N_NODES + 255) / 256, 256>>>();
    deg_count_kernel<<<(N_EDGES + 255) / 256, 256>>>(dst);
    dinv_kernel     <<<(N_NODES + 255) / 256, 256>>>();

    // tf32 pre-round of GEMM inputs
    round_tf32_kernel<<<(N_NODES * IN_SIZE / 4 + 255) / 256, 256>>>(x,  p_xr,  N_NODES * IN_SIZE / 4);
    round_tf32_kernel<<<(IN_SIZE * H_SIZE / 4 + 255) / 256, 256>>>(W1, p_w1r, IN_SIZE * H_SIZE / 4);
    round_tf32_kernel<<<(H_SIZE * OUT_SIZE / 4 + 255) / 256, 256>>>(W2, p_w2r, H_SIZE * OUT_SIZE / 4);

    // layer 1: h1 = x@W1 (tf32 tensor), agg1 init = dinv^2 * h1
    {
        dim3 grid(H_SIZE / 128, (N_NODES + 127) / 128);
        gemm_tf32_kernel<128, 128, 256, 4><<<grid, 256, SMEM1>>>(
            p_xr, p_w1r, p_h1, p_agg1, p_dinv, N_NODES, H_SIZE, IN_SIZE);
    }
    scatter512_kernel<<<N_EDGES, 128>>>(src, dst);
    bias_relu_round_kernel<<<(N_NODES * H_SIZE + 255) / 256, 256>>>(b1);

    // layer 2: h2 = relu(h1)@W2 (tf32 tensor), agg2 init = dinv^2 * h2
    {
        dim3 grid(OUT_SIZE / 64, (N_NODES + 127) / 128);
        gemm_tf32_kernel<128, 64, 128, 2><<<grid, 128, SMEM2>>>(
            p_h1, p_w2r, p_h2, p_agg2, p_dinv, N_NODES, OUT_SIZE, H_SIZE);
    }
    scatter64_kernel<<<(N_EDGES * 16 + 255) / 256, 256>>>(src, dst);

    // bias + write h, log_softmax
    final_kernel<<<(N_NODES + 7) / 8, 256>>>(b2, out);
}

// round 5
// speedup vs baseline: 2.2346x; 1.9772x over previous
#include <cuda_runtime.h>
#include <math.h>

#define N_NODES  10000
#define IN_SIZE  512
#define H_SIZE   512
#define OUT_SIZE 64
#define N_EDGES  163840

// ---------------- scratch (no allocations allowed) ----------------
__device__ int   g_cnt [N_NODES];        // in-degree (excl self-loop)
__device__ int   g_pos [N_NODES];        // fill cursor
__device__ int   g_off [N_NODES + 1];    // CSR offsets
__device__ int   g_csr_src[N_EDGES];     // src node per CSR slot
__device__ float g_csr_w  [N_EDGES];     // dinv[s]*dinv[d] per CSR slot
__device__ float g_dinv[N_NODES];
__device__ float g_h1  [N_NODES * H_SIZE];    // x@W1
__device__ float g_agg1[N_NODES * H_SIZE];    // relu(Â h1 + b1)  (GEMM2 input)
__device__ float g_h2  [N_NODES * OUT_SIZE];  // agg1@W2
__device__ float g_agg2[N_NODES * OUT_SIZE];  // Â h2

// ---------------- CSR build ----------------
__global__ void zero_kernel() {
    int n = blockIdx.x * blockDim.x + threadIdx.x;
    if (n < N_NODES) { g_cnt[n] = 0; g_pos[n] = 0; }
}

__global__ void count_kernel(const int* __restrict__ dst) {
    int e = blockIdx.x * blockDim.x + threadIdx.x;
    if (e < N_EDGES) atomicAdd(&g_cnt[dst[e]], 1);
}

// single-block exclusive scan of g_cnt -> g_off (10000 elements)
__global__ __launch_bounds__(256) void scan_kernel() {
    __shared__ int s[256];
    const int t = threadIdx.x;
    const int CH = (N_NODES + 255) / 256;   // 40
    int base = t * CH;
    int sum = 0;
    for (int i = 0; i < CH; i++) {
        int idx = base + i;
        if (idx < N_NODES) sum += g_cnt[idx];
    }
    s[t] = sum;
    __syncthreads();
    // inclusive Hillis-Steele
    for (int o = 1; o < 256; o <<= 1) {
        int v = (t >= o) ? s[t - o] : 0;
        __syncthreads();
        s[t] += v;
        __syncthreads();
    }
    int run = s[t] - sum;   // exclusive prefix of this chunk
    for (int i = 0; i < CH; i++) {
        int idx = base + i;
        if (idx < N_NODES) { g_off[idx] = run; run += g_cnt[idx]; }
    }
    if (t == 255) g_off[N_NODES] = N_EDGES;
}

__global__ void dinv_kernel() {
    int n = blockIdx.x * blockDim.x + threadIdx.x;
    if (n < N_NODES) g_dinv[n] = rsqrtf((float)(g_cnt[n] + 1));  // +1 self-loop
}

__global__ void fill_kernel(const int* __restrict__ src, const int* __restrict__ dst) {
    int e = blockIdx.x * blockDim.x + threadIdx.x;
    if (e >= N_EDGES) return;
    int s = src[e], d = dst[e];
    int slot = g_off[d] + atomicAdd(&g_pos[d], 1);
    g_csr_src[slot] = s;
    g_csr_w[slot]   = g_dinv[s] * g_dinv[d];
}

// ---------------- tf32 rounding (rna) ----------------
__device__ __forceinline__ unsigned to_tf32(float f) {
    unsigned o;
    asm("cvt.rna.tf32.f32 %0, %1;" : "=r"(o) : "f"(f));
    return o;
}
__device__ __forceinline__ float rtf(float f) { return __uint_as_float(to_tf32(f)); }

// ---------------- tf32 tensor-core GEMM (rounds A,B on the fly) ----------------
__device__ __forceinline__ void mma_tf32(float* d,
    unsigned a0, unsigned a1, unsigned a2, unsigned a3,
    unsigned b0, unsigned b1)
{
    asm volatile(
        "mma.sync.aligned.m16n8k8.row.col.f32.tf32.tf32.f32 "
        "{%0,%1,%2,%3}, {%4,%5,%6,%7}, {%8,%9}, {%0,%1,%2,%3};"
        : "+f"(d[0]), "+f"(d[1]), "+f"(d[2]), "+f"(d[3])
        : "r"(a0), "r"(a1), "r"(a2), "r"(a3), "r"(b0), "r"(b1));
}

template<int BM, int BN, int T, int WN>
__global__ __launch_bounds__(T) void gemm_tf32_kernel(
    const float* __restrict__ A, const float* __restrict__ B,
    float* __restrict__ C, int M, int N, int K)
{
    constexpr int BK = 32;
    constexpr int AS_STRIDE = 40;       // == 8 (mod 32): 2-phase LDS.64 frag loads
    constexpr int BS_STRIDE = BN + 4;   // == 4 (mod 16) in 8B units: conflict-free
    constexpr int NA = BM * BK / (4 * T);
    constexpr int NB = BK * BN / (4 * T);

    extern __shared__ float smem[];
    float* AsBase = smem;                         // [2][BM][AS_STRIDE]
    float* BsBase = smem + 2 * BM * AS_STRIDE;    // [2][BK][BS_STRIDE]

    const int tid  = threadIdx.x;
    const int wid  = tid >> 5;
    const int lane = tid & 31;
    const int lr   = lane >> 2;
    const int lc   = lane & 3;
    const int wm   = wid / WN;
    const int wn   = wid % WN;
    const int wrow = wm * 64;
    const int wcol = wn * 32;
    const int brow = blockIdx.y * BM;
    const int bcol = blockIdx.x * BN;

    float acc[4][4][4];
    #pragma unroll
    for (int i = 0; i < 4; i++)
        #pragma unroll
        for (int j = 0; j < 4; j++)
            #pragma unroll
            for (int q = 0; q < 4; q++) acc[i][j][q] = 0.0f;

    float4 ra[NA], rb[NB];

    auto ldg_tile = [&](int kk) {
        #pragma unroll
        for (int p = 0; p < NA; p++) {
            int idx = tid + p * T;
            int r = idx >> 3, c4 = (idx & 7) << 2;
            int grow = brow + r;
            ra[p] = (grow < M) ? *(const float4*)&A[(size_t)grow * K + kk + c4]
                               : make_float4(0.f, 0.f, 0.f, 0.f);
        }
        #pragma unroll
        for (int p = 0; p < NB; p++) {
            int idx = tid + p * T;
            int k = idx / (BN / 4), n4 = (idx % (BN / 4)) << 2;
            rb[p] = *(const float4*)&B[(size_t)(kk + k) * N + bcol + n4];
        }
    };

    auto sts_tile = [&](int buf) {
        float* as = AsBase + buf * BM * AS_STRIDE;
        float* bs = BsBase + buf * BK * BS_STRIDE;
        #pragma unroll
        for (int p = 0; p < NA; p++) {
            int idx = tid + p * T;
            int r = idx >> 3, c4 = (idx & 7) << 2;
            float* ap = &as[r * AS_STRIDE + c4];
            ap[0] = rtf(ra[p].x); ap[1] = rtf(ra[p].y);
            ap[2] = rtf(ra[p].z); ap[3] = rtf(ra[p].w);
        }
        #pragma unroll
        for (int p = 0; p < NB; p++) {
            int idx = tid + p * T;
            int k = idx / (BN / 4), n4 = (idx % (BN / 4)) << 2;
            float* bp = &bs[k * BS_STRIDE + n4];
            bp[0] = rtf(rb[p].x); bp[1] = rtf(rb[p].y);
            bp[2] = rtf(rb[p].z); bp[3] = rtf(rb[p].w);
        }
    };

    auto compute = [&](int buf) {
        const float* as = AsBase + buf * BM * AS_STRIDE;
        const float* bs = BsBase + buf * BK * BS_STRIDE;
        #pragma unroll
        for (int s = 0; s < 4; s++) {
            const int kb = s * 8 + lc * 2;
            uint2 af[4][2];
            #pragma unroll
            for (int i = 0; i < 4; i++) {
                const float* p = &as[(wrow + i * 16 + lr) * AS_STRIDE + kb];
                af[i][0] = *(const uint2*)p;
                af[i][1] = *(const uint2*)(p + 8 * AS_STRIDE);
            }
            unsigned bf0[4], bf1[4];
            #pragma unroll
            for (int j = 0; j < 4; j++) {
                const float* p = &bs[kb * BS_STRIDE + wcol + j * 8 + lr];
                bf0[j] = __float_as_uint(p[0]);
                bf1[j] = __float_as_uint(p[BS_STRIDE]);
            }
            #pragma unroll
            for (int i = 0; i < 4; i++)
                #pragma unroll
                for (int j = 0; j < 4; j++)
                    mma_tf32(acc[i][j],
                             af[i][0].x, af[i][1].x, af[i][0].y, af[i][1].y,
                             bf0[j], bf1[j]);
        }
    };

    ldg_tile(0);
    sts_tile(0);
    __syncthreads();
    int buf = 0;
    const int ntiles = K / BK;
    for (int t = 0; t < ntiles; t++) {
        if (t + 1 < ntiles) ldg_tile((t + 1) * BK);
        compute(buf);
        if (t + 1 < ntiles) {
            sts_tile(buf ^ 1);
            __syncthreads();
            buf ^= 1;
        }
    }

    #pragma unroll
    for (int i = 0; i < 4; i++) {
        int r0 = brow + wrow + i * 16 + lr;
        #pragma unroll
        for (int half = 0; half < 2; half++) {
            int r = r0 + half * 8;
            if (r < M) {
                #pragma unroll
                for (int j = 0; j < 4; j++) {
                    int cc = bcol + wcol + j * 8 + lc * 2;
                    *(float2*)&C[(size_t)r * N + cc] =
                        make_float2(acc[i][j][half * 2 + 0], acc[i][j][half * 2 + 1]);
                }
            }
        }
    }
}

// ---------------- gather aggregation, layer 1 (512 feat) ----------------
// block = one dst node, 128 threads (float4 each); epilogue: +bias, relu
__global__ __launch_bounds__(128) void agg1_kernel(const float* __restrict__ b1) {
    const int n = blockIdx.x;
    const int f = threadIdx.x * 4;
    const float di = g_dinv[n];
    const float w0 = di * di;

    float4 hv = *(const float4*)&g_h1[(size_t)n * H_SIZE + f];
    float4 acc = make_float4(hv.x * w0, hv.y * w0, hv.z * w0, hv.w * w0);

    const int beg = g_off[n], end = g_off[n + 1];
    int i = beg;
    for (; i + 1 < end; i += 2) {
        int   s0 = g_csr_src[i],     s1 = g_csr_src[i + 1];
        float w1 = g_csr_w[i],       w2 = g_csr_w[i + 1];
        float4 v0 = *(const float4*)&g_h1[(size_t)s0 * H_SIZE + f];
        float4 v1 = *(const float4*)&g_h1[(size_t)s1 * H_SIZE + f];
        acc.x = fmaf(w1, v0.x, acc.x); acc.y = fmaf(w1, v0.y, acc.y);
        acc.z = fmaf(w1, v0.z, acc.z); acc.w = fmaf(w1, v0.w, acc.w);
        acc.x = fmaf(w2, v1.x, acc.x); acc.y = fmaf(w2, v1.y, acc.y);
        acc.z = fmaf(w2, v1.z, acc.z); acc.w = fmaf(w2, v1.w, acc.w);
    }
    if (i < end) {
        int s0 = g_csr_src[i]; float w1 = g_csr_w[i];
        float4 v0 = *(const float4*)&g_h1[(size_t)s0 * H_SIZE + f];
        acc.x = fmaf(w1, v0.x, acc.x); acc.y = fmaf(w1, v0.y, acc.y);
        acc.z = fmaf(w1, v0.z, acc.z); acc.w = fmaf(w1, v0.w, acc.w);
    }

    float4 bb = *(const float4*)&b1[f];
    acc.x = fmaxf(acc.x + bb.x, 0.0f);
    acc.y = fmaxf(acc.y + bb.y, 0.0f);
    acc.z = fmaxf(acc.z + bb.z, 0.0f);
    acc.w = fmaxf(acc.w + bb.w, 0.0f);
    *(float4*)&g_agg1[(size_t)n * H_SIZE + f] = acc;
}

// ---------------- gather aggregation, layer 2 (64 feat) ----------------
// 16 threads per node (float4 each), 256-thread blocks = 16 nodes
__global__ __launch_bounds__(256) void agg2_kernel() {
    int t = blockIdx.x * blockDim.x + threadIdx.x;
    int n = t >> 4;
    if (n >= N_NODES) return;
    int f = (t & 15) * 4;
    const float di = g_dinv[n];
    const float w0 = di * di;

    float4 hv = *(const float4*)&g_h2[(size_t)n * OUT_SIZE + f];
    float4 acc = make_float4(hv.x * w0, hv.y * w0, hv.z * w0, hv.w * w0);

    const int beg = g_off[n], end = g_off[n + 1];
    int i = beg;
    for (; i + 1 < end; i += 2) {
        int   s0 = g_csr_src[i],     s1 = g_csr_src[i + 1];
        float w1 = g_csr_w[i],       w2 = g_csr_w[i + 1];
        float4 v0 = *(const float4*)&g_h2[(size_t)s0 * OUT_SIZE + f];
        float4 v1 = *(const float4*)&g_h2[(size_t)s1 * OUT_SIZE + f];
        acc.x = fmaf(w1, v0.x, acc.x); acc.y = fmaf(w1, v0.y, acc.y);
        acc.z = fmaf(w1, v0.z, acc.z); acc.w = fmaf(w1, v0.w, acc.w);
        acc.x = fmaf(w2, v1.x, acc.x); acc.y = fmaf(w2, v1.y, acc.y);
        acc.z = fmaf(w2, v1.z, acc.z); acc.w = fmaf(w2, v1.w, acc.w);
    }
    if (i < end) {
        int s0 = g_csr_src[i]; float w1 = g_csr_w[i];
        float4 v0 = *(const float4*)&g_h2[(size_t)s0 * OUT_SIZE + f];
        acc.x = fmaf(w1, v0.x, acc.x); acc.y = fmaf(w1, v0.y, acc.y);
        acc.z = fmaf(w1, v0.z, acc.z); acc.w = fmaf(w1, v0.w, acc.w);
    }
    *(float4*)&g_agg2[(size_t)n * OUT_SIZE + f] = acc;
}

// ---------------- bias + log_softmax, write both outputs ----------------
__global__ void final_kernel(const float* __restrict__ b2, float* __restrict__ out) {
    int warp = (blockIdx.x * blockDim.x + threadIdx.x) >> 5;
    int lane = threadIdx.x & 31;
    if (warp >= N_NODES) return;
    const float* row = g_agg2 + (size_t)warp * OUT_SIZE;
    float v0 = row[lane]      + b2[lane];
    float v1 = row[lane + 32] + b2[lane + 32];
    out[(size_t)warp * OUT_SIZE + lane]      = v0;
    out[(size_t)warp * OUT_SIZE + lane + 32] = v1;
    float m = fmaxf(v0, v1);
    #pragma unroll
    for (int o = 16; o; o >>= 1) m = fmaxf(m, __shfl_xor_sync(0xffffffffu, m, o));
    float s = __expf(v0 - m) + __expf(v1 - m);
    #pragma unroll
    for (int o = 16; o; o >>= 1) s += __shfl_xor_sync(0xffffffffu, s, o);
    float lse = m + __logf(s);
    float* out2 = out + (size_t)N_NODES * OUT_SIZE;
    out2[(size_t)warp * OUT_SIZE + lane]      = v0 - lse;
    out2[(size_t)warp * OUT_SIZE + lane + 32] = v1 - lse;
}

// ---------------- launch ----------------
extern "C" void kernel_launch(void* const* d_in, const int* in_sizes, int n_in,
                              void* d_out, int out_size)
{
    const float* x  = (const float*)d_in[0];
    const int*   ei = (const int*)  d_in[1];
    const float* W1 = (const float*)d_in[2];
    const float* b1 = (const float*)d_in[3];
    const float* W2 = (const float*)d_in[4];
    const float* b2 = (const float*)d_in[5];
    float* out = (float*)d_out;

    const int* src = ei;
    const int* dst = ei + N_EDGES;

    float *p_h1, *p_agg1, *p_h2;
    cudaGetSymbolAddress((void**)&p_h1,   g_h1);
    cudaGetSymbolAddress((void**)&p_agg1, g_agg1);
    cudaGetSymbolAddress((void**)&p_h2,   g_h2);

    const int SMEM1 = (2 * 128 * 40 + 2 * 32 * 132) * 4;  // 74752 B
    const int SMEM2 = (2 * 128 * 40 + 2 * 32 * 68)  * 4;  // 58368 B
    cudaFuncSetAttribute(gemm_tf32_kernel<128, 128, 256, 4>,
                         cudaFuncAttributeMaxDynamicSharedMemorySize, SMEM1);
    cudaFuncSetAttribute(gemm_tf32_kernel<128, 64, 128, 2>,
                         cudaFuncAttributeMaxDynamicSharedMemorySize, SMEM2);

    // ---- CSR build ----
    zero_kernel <<<(N_NODES + 255) / 256, 256>>>();
    count_kernel<<<(N_EDGES + 255) / 256, 256>>>(dst);
    scan_kernel <<<1, 256>>>();
    dinv_kernel <<<(N_NODES + 255) / 256, 256>>>();
    fill_kernel <<<(N_EDGES + 255) / 256, 256>>>(src, dst);

    // ---- layer 1 ----
    {
        dim3 grid(H_SIZE / 128, (N_NODES + 127) / 128);
        gemm_tf32_kernel<128, 128, 256, 4><<<grid, 256, SMEM1>>>(
            x, W1, p_h1, N_NODES, H_SIZE, IN_SIZE);
    }
    agg1_kernel<<<N_NODES, 128>>>(b1);

    // ---- layer 2 ----
    {
        dim3 grid(OUT_SIZE / 64, (N_NODES + 127) / 128);
        gemm_tf32_kernel<128, 64, 128, 2><<<grid, 128, SMEM2>>>(
            p_agg1, W2, p_h2, N_NODES, OUT_SIZE, H_SIZE);
    }
    agg2_kernel<<<(N_NODES * 16 + 255) / 256, 256>>>();

    // ---- bias + h, log_softmax ----
    final_kernel<<<(N_NODES + 7) / 8, 256>>>(b2, out);
}

// round 9
// speedup vs baseline: 2.2958x; 1.0274x over previous
#include <cuda_runtime.h>
#include <cooperative_groups.h>
#include <math.h>

namespace cg = cooperative_groups;

#define N_NODES  10000
#define IN_SIZE  512
#define H_SIZE   512
#define OUT_SIZE 64
#define N_EDGES  163840

// ---------------- scratch (no allocations allowed) ----------------
__device__ int   g_cnt [N_NODES];        // in-degree (excl self-loop)
__device__ int   g_pos [N_NODES];        // fill cursor
__device__ int   g_off [N_NODES + 1];    // CSR offsets
__device__ int2  g_csr [N_EDGES];        // (src, norm-as-bits) per CSR slot
__device__ float g_dinv[N_NODES];
__device__ float g_h1  [N_NODES * H_SIZE];    // x@W1
__device__ float g_agg1[N_NODES * H_SIZE];    // relu(Â h1 + b1)  (GEMM2 input)
__device__ float g_h2  [N_NODES * OUT_SIZE];  // agg1@W2

// ---------------- fused CSR build (cooperative) ----------------
__global__ __launch_bounds__(256) void csr_build_kernel(
    const int* __restrict__ src, const int* __restrict__ dst)
{
    cg::grid_group grid = cg::this_grid();
    const int tid = blockIdx.x * blockDim.x + threadIdx.x;
    const int nth = gridDim.x * blockDim.x;

    // phase 1: zero
    for (int n = tid; n < N_NODES; n += nth) { g_cnt[n] = 0; g_pos[n] = 0; }
    grid.sync();

    // phase 2: count in-degree
    for (int e = tid; e < N_EDGES; e += nth) atomicAdd(&g_cnt[dst[e]], 1);
    grid.sync();

    // phase 3a: dinv (all blocks) ; 3b: exclusive scan (block 0)
    for (int n = tid; n < N_NODES; n += nth)
        g_dinv[n] = rsqrtf((float)(g_cnt[n] + 1));   // +1 self-loop

    if (blockIdx.x == 0) {
        __shared__ int s[256];
        const int t = threadIdx.x;
        const int CH = (N_NODES + 255) / 256;   // 40
        int base = t * CH;
        int sum = 0;
        for (int i = 0; i < CH; i++) {
            int idx = base + i;
            if (idx < N_NODES) sum += g_cnt[idx];
        }
        s[t] = sum;
        __syncthreads();
        for (int o = 1; o < 256; o <<= 1) {
            int v = (t >= o) ? s[t - o] : 0;
            __syncthreads();
            s[t] += v;
            __syncthreads();
        }
        int run = s[t] - sum;
        for (int i = 0; i < CH; i++) {
            int idx = base + i;
            if (idx < N_NODES) { g_off[idx] = run; run += g_cnt[idx]; }
        }
        if (t == 255) g_off[N_NODES] = N_EDGES;
    }
    grid.sync();

    // phase 4: fill CSR slots with (src, dinv[s]*dinv[d])
    for (int e = tid; e < N_EDGES; e += nth) {
        int sN = src[e], d = dst[e];
        int slot = g_off[d] + atomicAdd(&g_pos[d], 1);
        g_csr[slot] = make_int2(sN, __float_as_int(g_dinv[sN] * g_dinv[d]));
    }
}

// ---------------- tf32 rounding (rna) ----------------
__device__ __forceinline__ unsigned to_tf32(float f) {
    unsigned o;
    asm("cvt.rna.tf32.f32 %0, %1;" : "=r"(o) : "f"(f));
    return o;
}
__device__ __forceinline__ float rtf(float f) { return __uint_as_float(to_tf32(f)); }

// ---------------- tf32 tensor-core GEMM (rounds A,B on the fly) ----------------
__device__ __forceinline__ void mma_tf32(float* d,
    unsigned a0, unsigned a1, unsigned a2, unsigned a3,
    unsigned b0, unsigned b1)
{
    asm volatile(
        "mma.sync.aligned.m16n8k8.row.col.f32.tf32.tf32.f32 "
        "{%0,%1,%2,%3}, {%4,%5,%6,%7}, {%8,%9}, {%0,%1,%2,%3};"
        : "+f"(d[0]), "+f"(d[1]), "+f"(d[2]), "+f"(d[3])
        : "r"(a0), "r"(a1), "r"(a2), "r"(a3), "r"(b0), "r"(b1));
}

template<int BM, int BN, int T, int WN>
__global__ __launch_bounds__(T) void gemm_tf32_kernel(
    const float* __restrict__ A, const float* __restrict__ B,
    float* __restrict__ C, int M, int N, int K)
{
    constexpr int BK = 32;
    constexpr int AS_STRIDE = 40;       // == 8 (mod 32): 2-phase LDS.64 frag loads
    constexpr int BS_STRIDE = BN + 4;   // == 4 (mod 16) in 8B units: conflict-free
    constexpr int NA = BM * BK / (4 * T);
    constexpr int NB = BK * BN / (4 * T);

    extern __shared__ float smem[];
    float* AsBase = smem;                         // [2][BM][AS_STRIDE]
    float* BsBase = smem + 2 * BM * AS_STRIDE;    // [2][BK][BS_STRIDE]

    const int tid  = threadIdx.x;
    const int wid  = tid >> 5;
    const int lane = tid & 31;
    const int lr   = lane >> 2;
    const int lc   = lane & 3;
    const int wm   = wid / WN;
    const int wn   = wid % WN;
    const int wrow = wm * 64;
    const int wcol = wn * 32;
    const int brow = blockIdx.y * BM;
    const int bcol = blockIdx.x * BN;

    float acc[4][4][4];
    #pragma unroll
    for (int i = 0; i < 4; i++)
        #pragma unroll
        for (int j = 0; j < 4; j++)
            #pragma unroll
            for (int q = 0; q < 4; q++) acc[i][j][q] = 0.0f;

    float4 ra[NA], rb[NB];

    auto ldg_tile = [&](int kk) {
        #pragma unroll
        for (int p = 0; p < NA; p++) {
            int idx = tid + p * T;
            int r = idx >> 3, c4 = (idx & 7) << 2;
            int grow = brow + r;
            ra[p] = (grow < M) ? *(const float4*)&A[(size_t)grow * K + kk + c4]
                               : make_float4(0.f, 0.f, 0.f, 0.f);
        }
        #pragma unroll
        for (int p = 0; p < NB; p++) {
            int idx = tid + p * T;
            int k = idx / (BN / 4), n4 = (idx % (BN / 4)) << 2;
            rb[p] = *(const float4*)&B[(size_t)(kk + k) * N + bcol + n4];
        }
    };

    auto sts_tile = [&](int buf) {
        float* as = AsBase + buf * BM * AS_STRIDE;
        float* bs = BsBase + buf * BK * BS_STRIDE;
        #pragma unroll
        for (int p = 0; p < NA; p++) {
            int idx = tid + p * T;
            int r = idx >> 3, c4 = (idx & 7) << 2;
            float* ap = &as[r * AS_STRIDE + c4];
            ap[0] = rtf(ra[p].x); ap[1] = rtf(ra[p].y);
            ap[2] = rtf(ra[p].z); ap[3] = rtf(ra[p].w);
        }
        #pragma unroll
        for (int p = 0; p < NB; p++) {
            int idx = tid + p * T;
            int k = idx / (BN / 4), n4 = (idx % (BN / 4)) << 2;
            float* bp = &bs[k * BS_STRIDE + n4];
            bp[0] = rtf(rb[p].x); bp[1] = rtf(rb[p].y);
            bp[2] = rtf(rb[p].z); bp[3] = rtf(rb[p].w);
        }
    };

    auto compute = [&](int buf) {
        const float* as = AsBase + buf * BM * AS_STRIDE;
        const float* bs = BsBase + buf * BK * BS_STRIDE;
        #pragma unroll
        for (int s = 0; s < 4; s++) {
            const int kb = s * 8 + lc * 2;
            uint2 af[4][2];
            #pragma unroll
            for (int i = 0; i < 4; i++) {
                const float* p = &as[(wrow + i * 16 + lr) * AS_STRIDE + kb];
                af[i][0] = *(const uint2*)p;
                af[i][1] = *(const uint2*)(p + 8 * AS_STRIDE);
            }
            unsigned bf0[4], bf1[4];
            #pragma unroll
            for (int j = 0; j < 4; j++) {
                const float* p = &bs[kb * BS_STRIDE + wcol + j * 8 + lr];
                bf0[j] = __float_as_uint(p[0]);
                bf1[j] = __float_as_uint(p[BS_STRIDE]);
            }
            #pragma unroll
            for (int i = 0; i < 4; i++)
                #pragma unroll
                for (int j = 0; j < 4; j++)
                    mma_tf32(acc[i][j],
                             af[i][0].x, af[i][1].x, af[i][0].y, af[i][1].y,
                             bf0[j], bf1[j]);
        }
    };

    ldg_tile(0);
    sts_tile(0);
    __syncthreads();
    int buf = 0;
    const int ntiles = K / BK;
    for (int t = 0; t < ntiles; t++) {
        if (t + 1 < ntiles) ldg_tile((t + 1) * BK);
        compute(buf);
        if (t + 1 < ntiles) {
            sts_tile(buf ^ 1);
            __syncthreads();
            buf ^= 1;
        }
    }

    #pragma unroll
    for (int i = 0; i < 4; i++) {
        int r0 = brow + wrow + i * 16 + lr;
        #pragma unroll
        for (int half = 0; half < 2; half++) {
            int r = r0 + half * 8;
            if (r < M) {
                #pragma unroll
                for (int j = 0; j < 4; j++) {
                    int cc = bcol + wcol + j * 8 + lc * 2;
                    *(float2*)&C[(size_t)r * N + cc] =
                        make_float2(acc[i][j][half * 2 + 0], acc[i][j][half * 2 + 1]);
                }
            }
        }
    }
}

// ---------------- gather aggregation, layer 1 (512 feat) ----------------
// block = one dst node, 128 threads (float4 each); epilogue: +bias, relu
__global__ __launch_bounds__(128) void agg1_kernel(const float* __restrict__ b1) {
    const int n = blockIdx.x;
    const int f = threadIdx.x * 4;
    const float di = g_dinv[n];
    const float w0 = di * di;

    float4 hv = *(const float4*)&g_h1[(size_t)n * H_SIZE + f];
    float4 acc = make_float4(hv.x * w0, hv.y * w0, hv.z * w0, hv.w * w0);

    const int beg = g_off[n], end = g_off[n + 1];
    int i = beg;
    for (; i + 3 < end; i += 4) {
        int2 e0 = g_csr[i],     e1 = g_csr[i + 1];
        int2 e2 = g_csr[i + 2], e3 = g_csr[i + 3];
        float w1 = __int_as_float(e0.y), w2 = __int_as_float(e1.y);
        float w3 = __int_as_float(e2.y), w4 = __int_as_float(e3.y);
        float4 v0 = *(const float4*)&g_h1[(size_t)e0.x * H_SIZE + f];
        float4 v1 = *(const float4*)&g_h1[(size_t)e1.x * H_SIZE + f];
        float4 v2 = *(const float4*)&g_h1[(size_t)e2.x * H_SIZE + f];
        float4 v3 = *(const float4*)&g_h1[(size_t)e3.x * H_SIZE + f];
        acc.x = fmaf(w1, v0.x, acc.x); acc.y = fmaf(w1, v0.y, acc.y);
        acc.z = fmaf(w1, v0.z, acc.z); acc.w = fmaf(w1, v0.w, acc.w);
        acc.x = fmaf(w2, v1.x, acc.x); acc.y = fmaf(w2, v1.y, acc.y);
        acc.z = fmaf(w2, v1.z, acc.z); acc.w = fmaf(w2, v1.w, acc.w);
        acc.x = fmaf(w3, v2.x, acc.x); acc.y = fmaf(w3, v2.y, acc.y);
        acc.z = fmaf(w3, v2.z, acc.z); acc.w = fmaf(w3, v2.w, acc.w);
        acc.x = fmaf(w4, v3.x, acc.x); acc.y = fmaf(w4, v3.y, acc.y);
        acc.z = fmaf(w4, v3.z, acc.z); acc.w = fmaf(w4, v3.w, acc.w);
    }
    for (; i < end; i++) {
        int2 e0 = g_csr[i];
        float w1 = __int_as_float(e0.y);
        float4 v0 = *(const float4*)&g_h1[(size_t)e0.x * H_SIZE + f];
        acc.x = fmaf(w1, v0.x, acc.x); acc.y = fmaf(w1, v0.y, acc.y);
        acc.z = fmaf(w1, v0.z, acc.z); acc.w = fmaf(w1, v0.w, acc.w);
    }

    float4 bb = *(const float4*)&b1[f];
    acc.x = fmaxf(acc.x + bb.x, 0.0f);
    acc.y = fmaxf(acc.y + bb.y, 0.0f);
    acc.z = fmaxf(acc.z + bb.z, 0.0f);
    acc.w = fmaxf(acc.w + bb.w, 0.0f);
    *(float4*)&g_agg1[(size_t)n * H_SIZE + f] = acc;
}

// ---------------- fused: layer-2 gather + bias + log_softmax ----------------
// one warp per node; lane owns feats {lane, lane+32}
__global__ __launch_bounds__(256) void agg2_final_kernel(
    const float* __restrict__ b2, float* __restrict__ out)
{
    int warp = (blockIdx.x * blockDim.x + threadIdx.x) >> 5;
    int lane = threadIdx.x & 31;
    if (warp >= N_NODES) return;

    const float di = g_dinv[warp];
    const float w0 = di * di;
    const float* hrow = &g_h2[(size_t)warp * OUT_SIZE];
    float v0 = hrow[lane]      * w0;
    float v1 = hrow[lane + 32] * w0;

    const int beg = g_off[warp], end = g_off[warp + 1];
    int i = beg;
    for (; i + 1 < end; i += 2) {
        int2 e0 = g_csr[i], e1 = g_csr[i + 1];
        float wa = __int_as_float(e0.y), wb = __int_as_float(e1.y);
        const float* r0 = &g_h2[(size_t)e0.x * OUT_SIZE];
        const float* r1 = &g_h2[(size_t)e1.x * OUT_SIZE];
        float a0 = r0[lane], a1 = r0[lane + 32];
        float c0 = r1[lane], c1 = r1[lane + 32];
        v0 = fmaf(wa, a0, v0); v1 = fmaf(wa, a1, v1);
        v0 = fmaf(wb, c0, v0); v1 = fmaf(wb, c1, v1);
    }
    if (i < end) {
        int2 e0 = g_csr[i];
        float wa = __int_as_float(e0.y);
        const float* r0 = &g_h2[(size_t)e0.x * OUT_SIZE];
        v0 = fmaf(wa, r0[lane], v0);
        v1 = fmaf(wa, r0[lane + 32], v1);
    }

    v0 += b2[lane];
    v1 += b2[lane + 32];
    out[(size_t)warp * OUT_SIZE + lane]      = v0;
    out[(size_t)warp * OUT_SIZE + lane + 32] = v1;

    float m = fmaxf(v0, v1);
    #pragma unroll
    for (int o = 16; o; o >>= 1) m = fmaxf(m, __shfl_xor_sync(0xffffffffu, m, o));
    float s = __expf(v0 - m) + __expf(v1 - m);
    #pragma unroll
    for (int o = 16; o; o >>= 1) s += __shfl_xor_sync(0xffffffffu, s, o);
    float lse = m + __logf(s);
    float* out2 = out + (size_t)N_NODES * OUT_SIZE;
    out2[(size_t)warp * OUT_SIZE + lane]      = v0 - lse;
    out2[(size_t)warp * OUT_SIZE + lane + 32] = v1 - lse;
}

// ---------------- launch ----------------
extern "C" void kernel_launch(void* const* d_in, const int* in_sizes, int n_in,
                              void* d_out, int out_size)
{
    const float* x  = (const float*)d_in[0];
    const int*   ei = (const int*)  d_in[1];
    const float* W1 = (const float*)d_in[2];
    const float* b1 = (const float*)d_in[3];
    const float* W2 = (const float*)d_in[4];
    const float* b2 = (const float*)d_in[5];
    float* out = (float*)d_out;

    const int* src = ei;
    const int* dst = ei + N_EDGES;

    float *p_h1, *p_agg1, *p_h2;
    cudaGetSymbolAddress((void**)&p_h1,   g_h1);
    cudaGetSymbolAddress((void**)&p_agg1, g_agg1);
    cudaGetSymbolAddress((void**)&p_h2,   g_h2);

    const int SMEM1 = (2 * 128 * 40 + 2 * 32 * 132) * 4;  // 74752 B
    const int SMEM2 = (2 * 128 * 40 + 2 * 32 * 68)  * 4;  // 58368 B
    cudaFuncSetAttribute(gemm_tf32_kernel<128, 128, 256, 4>,
                         cudaFuncAttributeMaxDynamicSharedMemorySize, SMEM1);
    cudaFuncSetAttribute(gemm_tf32_kernel<128, 64, 128, 2>,
                         cudaFuncAttributeMaxDynamicSharedMemorySize, SMEM2);

    // ---- fused CSR build (cooperative, one launch) ----
    {
        void* args[] = { (void*)&src, (void*)&dst };
        cudaLaunchCooperativeKernel((void*)csr_build_kernel,
                                    dim3(148), dim3(256), args, 0, 0);
    }

    // ---- layer 1 ----
    {
        dim3 grid(H_SIZE / 128, (N_NODES + 127) / 128);
        gemm_tf32_kernel<128, 128, 256, 4><<<grid, 256, SMEM1>>>(
            x, W1, p_h1, N_NODES, H_SIZE, IN_SIZE);
    }
    agg1_kernel<<<N_NODES, 128>>>(b1);

    // ---- layer 2 ----
    {
        dim3 grid(OUT_SIZE / 64, (N_NODES + 127) / 128);
        gemm_tf32_kernel<128, 64, 128, 2><<<grid, 128, SMEM2>>>(
            p_agg1, W2, p_h2, N_NODES, OUT_SIZE, H_SIZE);
    }

    // ---- fused layer-2 gather + bias + log_softmax ----
    agg2_final_kernel<<<(N_NODES * 32 + 255) / 256, 256>>>(b2, out);
}

// round 10
// speedup vs baseline: 2.3578x; 1.0270x over previous
#include <cuda_runtime.h>
#include <cooperative_groups.h>
#include <math.h>

namespace cg = cooperative_groups;

#define N_NODES  10000
#define IN_SIZE  512
#define H_SIZE   512
#define OUT_SIZE 64
#define N_EDGES  163840

// ---------------- scratch (no allocations allowed) ----------------
__device__ int   g_cnt [N_NODES];
__device__ int   g_pos [N_NODES];
__device__ int   g_off [N_NODES + 1];
__device__ int2  g_csr [N_EDGES];        // (src, norm-as-bits)
__device__ float g_dinv[N_NODES];
__device__ float g_h1  [N_NODES * H_SIZE];    // x@W1
__device__ float g_agg1[N_NODES * H_SIZE];    // relu(Â h1 + b1)
__device__ float g_h2  [N_NODES * OUT_SIZE];  // agg1@W2 (split-K accumulated)

// ---------------- fused CSR build (cooperative) ----------------
__global__ __launch_bounds__(256) void csr_build_kernel(
    const int* __restrict__ src, const int* __restrict__ dst)
{
    cg::grid_group grid = cg::this_grid();
    const int tid = blockIdx.x * blockDim.x + threadIdx.x;
    const int nth = gridDim.x * blockDim.x;

    for (int n = tid; n < N_NODES; n += nth) { g_cnt[n] = 0; g_pos[n] = 0; }
    grid.sync();

    for (int e = tid; e < N_EDGES; e += nth) atomicAdd(&g_cnt[dst[e]], 1);
    grid.sync();

    for (int n = tid; n < N_NODES; n += nth)
        g_dinv[n] = rsqrtf((float)(g_cnt[n] + 1));

    if (blockIdx.x == 0) {
        __shared__ int s[256];
        const int t = threadIdx.x;
        const int CH = (N_NODES + 255) / 256;
        int base = t * CH;
        int sum = 0;
        for (int i = 0; i < CH; i++) {
            int idx = base + i;
            if (idx < N_NODES) sum += g_cnt[idx];
        }
        s[t] = sum;
        __syncthreads();
        for (int o = 1; o < 256; o <<= 1) {
            int v = (t >= o) ? s[t - o] : 0;
            __syncthreads();
            s[t] += v;
            __syncthreads();
        }
        int run = s[t] - sum;
        for (int i = 0; i < CH; i++) {
            int idx = base + i;
            if (idx < N_NODES) { g_off[idx] = run; run += g_cnt[idx]; }
        }
        if (t == 255) g_off[N_NODES] = N_EDGES;
    }
    grid.sync();

    for (int e = tid; e < N_EDGES; e += nth) {
        int sN = src[e], d = dst[e];
        int slot = g_off[d] + atomicAdd(&g_pos[d], 1);
        g_csr[slot] = make_int2(sN, __float_as_int(g_dinv[sN] * g_dinv[d]));
    }
}

// ---------------- zero h2 (needed for split-K red.add) ----------------
__global__ void zero_h2_kernel() {
    int i = blockIdx.x * blockDim.x + threadIdx.x;
    if (i < N_NODES * OUT_SIZE / 4)
        ((float4*)g_h2)[i] = make_float4(0.f, 0.f, 0.f, 0.f);
}

// ---------------- tf32 rounding (rna) ----------------
__device__ __forceinline__ unsigned to_tf32(float f) {
    unsigned o;
    asm("cvt.rna.tf32.f32 %0, %1;" : "=r"(o) : "f"(f));
    return o;
}
__device__ __forceinline__ float rtf(float f) { return __uint_as_float(to_tf32(f)); }

__device__ __forceinline__ void red_add_v2(float* p, float2 v) {
    asm volatile("red.global.add.v2.f32 [%0], {%1, %2};"
                 :: "l"(p), "f"(v.x), "f"(v.y) : "memory");
}

// ---------------- tf32 tensor-core GEMM (rounds A,B on the fly) ----------------
__device__ __forceinline__ void mma_tf32(float* d,
    unsigned a0, unsigned a1, unsigned a2, unsigned a3,
    unsigned b0, unsigned b1)
{
    asm volatile(
        "mma.sync.aligned.m16n8k8.row.col.f32.tf32.tf32.f32 "
        "{%0,%1,%2,%3}, {%4,%5,%6,%7}, {%8,%9}, {%0,%1,%2,%3};"
        : "+f"(d[0]), "+f"(d[1]), "+f"(d[2]), "+f"(d[3])
        : "r"(a0), "r"(a1), "r"(a2), "r"(a3), "r"(b0), "r"(b1));
}

// SPLIT>1: blockIdx.z selects a K-chunk; epilogue red-adds into C (pre-zeroed).
template<int BM, int BN, int T, int WN, int SPLIT>
__global__ __launch_bounds__(T) void gemm_tf32_kernel(
    const float* __restrict__ A, const float* __restrict__ B,
    float* __restrict__ C, int M, int N, int K)
{
    constexpr int BK = 32;
    constexpr int AS_STRIDE = 40;       // == 8 (mod 32): 2-phase LDS.64 frag loads
    constexpr int BS_STRIDE = BN + 4;   // == 4 (mod 16) in 8B units: conflict-free
    constexpr int NA = BM * BK / (4 * T);
    constexpr int NB = BK * BN / (4 * T);

    extern __shared__ float smem[];
    float* AsBase = smem;                         // [2][BM][AS_STRIDE]
    float* BsBase = smem + 2 * BM * AS_STRIDE;    // [2][BK][BS_STRIDE]

    const int tid  = threadIdx.x;
    const int wid  = tid >> 5;
    const int lane = tid & 31;
    const int lr   = lane >> 2;
    const int lc   = lane & 3;
    const int wm   = wid / WN;
    const int wn   = wid % WN;
    const int wrow = wm * 64;
    const int wcol = wn * 32;
    const int brow = blockIdx.y * BM;
    const int bcol = blockIdx.x * BN;
    const int k0   = blockIdx.z * (K / SPLIT);

    float acc[4][4][4];
    #pragma unroll
    for (int i = 0; i < 4; i++)
        #pragma unroll
        for (int j = 0; j < 4; j++)
            #pragma unroll
            for (int q = 0; q < 4; q++) acc[i][j][q] = 0.0f;

    float4 ra[NA], rb[NB];

    auto ldg_tile = [&](int kk) {
        #pragma unroll
        for (int p = 0; p < NA; p++) {
            int idx = tid + p * T;
            int r = idx >> 3, c4 = (idx & 7) << 2;
            int grow = brow + r;
            ra[p] = (grow < M) ? *(const float4*)&A[(size_t)grow * K + kk + c4]
                               : make_float4(0.f, 0.f, 0.f, 0.f);
        }
        #pragma unroll
        for (int p = 0; p < NB; p++) {
            int idx = tid + p * T;
            int k = idx / (BN / 4), n4 = (idx % (BN / 4)) << 2;
            rb[p] = *(const float4*)&B[(size_t)(kk + k) * N + bcol + n4];
        }
    };

    auto sts_tile = [&](int buf) {
        float* as = AsBase + buf * BM * AS_STRIDE;
        float* bs = BsBase + buf * BK * BS_STRIDE;
        #pragma unroll
        for (int p = 0; p < NA; p++) {
            int idx = tid + p * T;
            int r = idx >> 3, c4 = (idx & 7) << 2;
            float* ap = &as[r * AS_STRIDE + c4];
            ap[0] = rtf(ra[p].x); ap[1] = rtf(ra[p].y);
            ap[2] = rtf(ra[p].z); ap[3] = rtf(ra[p].w);
        }
        #pragma unroll
        for (int p = 0; p < NB; p++) {
            int idx = tid + p * T;
            int k = idx / (BN / 4), n4 = (idx % (BN / 4)) << 2;
            float* bp = &bs[k * BS_STRIDE + n4];
            bp[0] = rtf(rb[p].x); bp[1] = rtf(rb[p].y);
            bp[2] = rtf(rb[p].z); bp[3] = rtf(rb[p].w);
        }
    };

    auto compute = [&](int buf) {
        const float* as = AsBase + buf * BM * AS_STRIDE;
        const float* bs = BsBase + buf * BK * BS_STRIDE;
        #pragma unroll
        for (int s = 0; s < 4; s++) {
            const int kb = s * 8 + lc * 2;
            uint2 af[4][2];
            #pragma unroll
            for (int i = 0; i < 4; i++) {
                const float* p = &as[(wrow + i * 16 + lr) * AS_STRIDE + kb];
                af[i][0] = *(const uint2*)p;
                af[i][1] = *(const uint2*)(p + 8 * AS_STRIDE);
            }
            unsigned bf0[4], bf1[4];
            #pragma unroll
            for (int j = 0; j < 4; j++) {
                const float* p = &bs[kb * BS_STRIDE + wcol + j * 8 + lr];
                bf0[j] = __float_as_uint(p[0]);
                bf1[j] = __float_as_uint(p[BS_STRIDE]);
            }
            #pragma unroll
            for (int i = 0; i < 4; i++)
                #pragma unroll
                for (int j = 0; j < 4; j++)
                    mma_tf32(acc[i][j],
                             af[i][0].x, af[i][1].x, af[i][0].y, af[i][1].y,
                             bf0[j], bf1[j]);
        }
    };

    ldg_tile(k0);
    sts_tile(0);
    __syncthreads();
    int buf = 0;
    const int ntiles = K / SPLIT / BK;
    for (int t = 0; t < ntiles; t++) {
        if (t + 1 < ntiles) ldg_tile(k0 + (t + 1) * BK);
        compute(buf);
        if (t + 1 < ntiles) {
            sts_tile(buf ^ 1);
            __syncthreads();
            buf ^= 1;
        }
    }

    #pragma unroll
    for (int i = 0; i < 4; i++) {
        int r0 = brow + wrow + i * 16 + lr;
        #pragma unroll
        for (int half = 0; half < 2; half++) {
            int r = r0 + half * 8;
            if (r < M) {
                #pragma unroll
                for (int j = 0; j < 4; j++) {
                    int cc = bcol + wcol + j * 8 + lc * 2;
                    float2 v = make_float2(acc[i][j][half * 2 + 0], acc[i][j][half * 2 + 1]);
                    if (SPLIT == 1)
                        *(float2*)&C[(size_t)r * N + cc] = v;
                    else
                        red_add_v2(&C[(size_t)r * N + cc], v);
                }
            }
        }
    }
}

// ---------------- gather aggregation, layer 1 (512 feat) ----------------
__global__ __launch_bounds__(128) void agg1_kernel(const float* __restrict__ b1) {
    const int n = blockIdx.x;
    const int f = threadIdx.x * 4;
    const float di = g_dinv[n];
    const float w0 = di * di;

    float4 hv = *(const float4*)&g_h1[(size_t)n * H_SIZE + f];
    float4 acc = make_float4(hv.x * w0, hv.y * w0, hv.z * w0, hv.w * w0);

    const int beg = g_off[n], end = g_off[n + 1];
    int i = beg;
    for (; i + 3 < end; i += 4) {
        int2 e0 = g_csr[i],     e1 = g_csr[i + 1];
        int2 e2 = g_csr[i + 2], e3 = g_csr[i + 3];
        float w1 = __int_as_float(e0.y), w2 = __int_as_float(e1.y);
        float w3 = __int_as_float(e2.y), w4 = __int_as_float(e3.y);
        float4 v0 = *(const float4*)&g_h1[(size_t)e0.x * H_SIZE + f];
        float4 v1 = *(const float4*)&g_h1[(size_t)e1.x * H_SIZE + f];
        float4 v2 = *(const float4*)&g_h1[(size_t)e2.x * H_SIZE + f];
        float4 v3 = *(const float4*)&g_h1[(size_t)e3.x * H_SIZE + f];
        acc.x = fmaf(w1, v0.x, acc.x); acc.y = fmaf(w1, v0.y, acc.y);
        acc.z = fmaf(w1, v0.z, acc.z); acc.w = fmaf(w1, v0.w, acc.w);
        acc.x = fmaf(w2, v1.x, acc.x); acc.y = fmaf(w2, v1.y, acc.y);
        acc.z = fmaf(w2, v1.z, acc.z); acc.w = fmaf(w2, v1.w, acc.w);
        acc.x = fmaf(w3, v2.x, acc.x); acc.y = fmaf(w3, v2.y, acc.y);
        acc.z = fmaf(w3, v2.z, acc.z); acc.w = fmaf(w3, v2.w, acc.w);
        acc.x = fmaf(w4, v3.x, acc.x); acc.y = fmaf(w4, v3.y, acc.y);
        acc.z = fmaf(w4, v3.z, acc.z); acc.w = fmaf(w4, v3.w, acc.w);
    }
    for (; i < end; i++) {
        int2 e0 = g_csr[i];
        float w1 = __int_as_float(e0.y);
        float4 v0 = *(const float4*)&g_h1[(size_t)e0.x * H_SIZE + f];
        acc.x = fmaf(w1, v0.x, acc.x); acc.y = fmaf(w1, v0.y, acc.y);
        acc.z = fmaf(w1, v0.z, acc.z); acc.w = fmaf(w1, v0.w, acc.w);
    }

    float4 bb = *(const float4*)&b1[f];
    acc.x = fmaxf(acc.x + bb.x, 0.0f);
    acc.y = fmaxf(acc.y + bb.y, 0.0f);
    acc.z = fmaxf(acc.z + bb.z, 0.0f);
    acc.w = fmaxf(acc.w + bb.w, 0.0f);
    *(float4*)&g_agg1[(size_t)n * H_SIZE + f] = acc;
}

// ---------------- fused: layer-2 gather + bias + log_softmax ----------------
__global__ __launch_bounds__(256) void agg2_final_kernel(
    const float* __restrict__ b2, float* __restrict__ out)
{
    int warp = (blockIdx.x * blockDim.x + threadIdx.x) >> 5;
    int lane = threadIdx.x & 31;
    if (warp >= N_NODES) return;

    const float di = g_dinv[warp];
    const float w0 = di * di;
    const float* hrow = &g_h2[(size_t)warp * OUT_SIZE];
    float v0 = hrow[lane]      * w0;
    float v1 = hrow[lane + 32] * w0;

    const int beg = g_off[warp], end = g_off[warp + 1];
    int i = beg;
    for (; i + 1 < end; i += 2) {
        int2 e0 = g_csr[i], e1 = g_csr[i + 1];
        float wa = __int_as_float(e0.y), wb = __int_as_float(e1.y);
        const float* r0 = &g_h2[(size_t)e0.x * OUT_SIZE];
        const float* r1 = &g_h2[(size_t)e1.x * OUT_SIZE];
        float a0 = r0[lane], a1 = r0[lane + 32];
        float c0 = r1[lane], c1 = r1[lane + 32];
        v0 = fmaf(wa, a0, v0); v1 = fmaf(wa, a1, v1);
        v0 = fmaf(wb, c0, v0); v1 = fmaf(wb, c1, v1);
    }
    if (i < end) {
        int2 e0 = g_csr[i];
        float wa = __int_as_float(e0.y);
        const float* r0 = &g_h2[(size_t)e0.x * OUT_SIZE];
        v0 = fmaf(wa, r0[lane], v0);
        v1 = fmaf(wa, r0[lane + 32], v1);
    }

    v0 += b2[lane];
    v1 += b2[lane + 32];
    out[(size_t)warp * OUT_SIZE + lane]      = v0;
    out[(size_t)warp * OUT_SIZE + lane + 32] = v1;

    float m = fmaxf(v0, v1);
    #pragma unroll
    for (int o = 16; o; o >>= 1) m = fmaxf(m, __shfl_xor_sync(0xffffffffu, m, o));
    float s = __expf(v0 - m) + __expf(v1 - m);
    #pragma unroll
    for (int o = 16; o; o >>= 1) s += __shfl_xor_sync(0xffffffffu, s, o);
    float lse = m + __logf(s);
    float* out2 = out + (size_t)N_NODES * OUT_SIZE;
    out2[(size_t)warp * OUT_SIZE + lane]      = v0 - lse;
    out2[(size_t)warp * OUT_SIZE + lane + 32] = v1 - lse;
}

// ---------------- launch ----------------
extern "C" void kernel_launch(void* const* d_in, const int* in_sizes, int n_in,
                              void* d_out, int out_size)
{
    const float* x  = (const float*)d_in[0];
    const int*   ei = (const int*)  d_in[1];
    const float* W1 = (const float*)d_in[2];
    const float* b1 = (const float*)d_in[3];
    const float* W2 = (const float*)d_in[4];
    const float* b2 = (const float*)d_in[5];
    float* out = (float*)d_out;

    const int* src = ei;
    const int* dst = ei + N_EDGES;

    float *p_h1, *p_agg1, *p_h2;
    cudaGetSymbolAddress((void**)&p_h1,   g_h1);
    cudaGetSymbolAddress((void**)&p_agg1, g_agg1);
    cudaGetSymbolAddress((void**)&p_h2,   g_h2);

    const int SMEM1 = (2 * 128 * 40 + 2 * 32 * 132) * 4;  // 74752 B
    const int SMEM2 = (2 * 128 * 40 + 2 * 32 * 68)  * 4;  // 58368 B
    cudaFuncSetAttribute(gemm_tf32_kernel<128, 128, 256, 4, 1>,
                         cudaFuncAttributeMaxDynamicSharedMemorySize, SMEM1);
    cudaFuncSetAttribute(gemm_tf32_kernel<128, 64, 128, 2, 4>,
                         cudaFuncAttributeMaxDynamicSharedMemorySize, SMEM2);

    // one-time side-stream resources (no device memory; work per call identical)
    static cudaStream_t s2 = nullptr;
    static cudaEvent_t evFork = nullptr, evJoin = nullptr;
    if (s2 == nullptr) {
        cudaStreamCreateWithFlags(&s2, cudaStreamNonBlocking);
        cudaEventCreateWithFlags(&evFork, cudaEventDisableTiming);
        cudaEventCreateWithFlags(&evJoin, cudaEventDisableTiming);
    }

    // ---- fork: CSR build + h2 zero on s2, concurrent with GEMM1 ----
    cudaEventRecord(evFork, 0);
    cudaStreamWaitEvent(s2, evFork, 0);

    zero_h2_kernel<<<(N_NODES * OUT_SIZE / 4 + 255) / 256, 256, 0, s2>>>();
    {
        void* args[] = { (void*)&src, (void*)&dst };
        cudaLaunchCooperativeKernel((void*)csr_build_kernel,
                                    dim3(148), dim3(256), args, 0, s2);
    }
    cudaEventRecord(evJoin, s2);

    // ---- layer 1 GEMM (default stream, overlaps with s2) ----
    {
        dim3 grid(H_SIZE / 128, (N_NODES + 127) / 128);
        gemm_tf32_kernel<128, 128, 256, 4, 1><<<grid, 256, SMEM1>>>(
            x, W1, p_h1, N_NODES, H_SIZE, IN_SIZE);
    }

    // ---- join, then agg1 ----
    cudaStreamWaitEvent(0, evJoin, 0);
    agg1_kernel<<<N_NODES, 128>>>(b1);

    // ---- layer 2 GEMM, split-K=4 (red.add into zeroed h2) ----
    {
        dim3 grid(OUT_SIZE / 64, (N_NODES + 127) / 128, 4);
        gemm_tf32_kernel<128, 64, 128, 2, 4><<<grid, 128, SMEM2>>>(
            p_agg1, W2, p_h2, N_NODES, OUT_SIZE, H_SIZE);
    }

    // ---- fused layer-2 gather + bias + log_softmax ----
    agg2_final_kernel<<<(N_NODES * 32 + 255) / 256, 256>>>(b2, out);
}

// round 11
// speedup vs baseline: 2.3990x; 1.0175x over previous
#include <cuda_runtime.h>
#include <cooperative_groups.h>
#include <math.h>

namespace cg = cooperative_groups;

#define N_NODES  10000
#define IN_SIZE  512
#define H_SIZE   512
#define OUT_SIZE 64
#define N_EDGES  163840

// ---------------- scratch (no allocations allowed) ----------------
__device__ int   g_cnt [N_NODES];
__device__ int   g_pos [N_NODES];
__device__ int   g_off [N_NODES + 1];
__device__ int2  g_csr [N_EDGES];        // (src, norm-as-bits)
__device__ float g_dinv[N_NODES];
__device__ float g_h1  [N_NODES * H_SIZE];    // x@W1
__device__ float g_agg1[N_NODES * H_SIZE];    // relu(Â h1 + b1)
__device__ float g_h2  [N_NODES * OUT_SIZE];  // agg1@W2 (split-K accumulated)

// ---------------- fused CSR build (cooperative) ----------------
__global__ __launch_bounds__(256) void csr_build_kernel(
    const int* __restrict__ src, const int* __restrict__ dst)
{
    cg::grid_group grid = cg::this_grid();
    const int tid = blockIdx.x * blockDim.x + threadIdx.x;
    const int nth = gridDim.x * blockDim.x;

    for (int n = tid; n < N_NODES; n += nth) { g_cnt[n] = 0; g_pos[n] = 0; }
    grid.sync();

    for (int e = tid; e < N_EDGES; e += nth) atomicAdd(&g_cnt[dst[e]], 1);
    grid.sync();

    for (int n = tid; n < N_NODES; n += nth)
        g_dinv[n] = rsqrtf((float)(g_cnt[n] + 1));

    if (blockIdx.x == 0) {
        __shared__ int s[256];
        const int t = threadIdx.x;
        const int CH = (N_NODES + 255) / 256;
        int base = t * CH;
        int sum = 0;
        for (int i = 0; i < CH; i++) {
            int idx = base + i;
            if (idx < N_NODES) sum += g_cnt[idx];
        }
        s[t] = sum;
        __syncthreads();
        for (int o = 1; o < 256; o <<= 1) {
            int v = (t >= o) ? s[t - o] : 0;
            __syncthreads();
            s[t] += v;
            __syncthreads();
        }
        int run = s[t] - sum;
        for (int i = 0; i < CH; i++) {
            int idx = base + i;
            if (idx < N_NODES) { g_off[idx] = run; run += g_cnt[idx]; }
        }
        if (t == 255) g_off[N_NODES] = N_EDGES;
    }
    grid.sync();

    for (int e = tid; e < N_EDGES; e += nth) {
        int sN = src[e], d = dst[e];
        int slot = g_off[d] + atomicAdd(&g_pos[d], 1);
        g_csr[slot] = make_int2(sN, __float_as_int(g_dinv[sN] * g_dinv[d]));
    }
}

// ---------------- zero h2 (needed for split-K red.add) ----------------
__global__ void zero_h2_kernel() {
    int i = blockIdx.x * blockDim.x + threadIdx.x;
    if (i < N_NODES * OUT_SIZE / 4)
        ((float4*)g_h2)[i] = make_float4(0.f, 0.f, 0.f, 0.f);
}

// ---------------- tf32 rounding (rna) ----------------
__device__ __forceinline__ unsigned to_tf32(float f) {
    unsigned o;
    asm("cvt.rna.tf32.f32 %0, %1;" : "=r"(o) : "f"(f));
    return o;
}
__device__ __forceinline__ float rtf(float f) { return __uint_as_float(to_tf32(f)); }

__device__ __forceinline__ void red_add_v2(float* p, float2 v) {
    asm volatile("red.global.add.v2.f32 [%0], {%1, %2};"
                 :: "l"(p), "f"(v.x), "f"(v.y) : "memory");
}

// ---------------- tf32 tensor-core GEMM (rounds A,B on the fly) ----------------
__device__ __forceinline__ void mma_tf32(float* d,
    unsigned a0, unsigned a1, unsigned a2, unsigned a3,
    unsigned b0, unsigned b1)
{
    asm volatile(
        "mma.sync.aligned.m16n8k8.row.col.f32.tf32.tf32.f32 "
        "{%0,%1,%2,%3}, {%4,%5,%6,%7}, {%8,%9}, {%0,%1,%2,%3};"
        : "+f"(d[0]), "+f"(d[1]), "+f"(d[2]), "+f"(d[3])
        : "r"(a0), "r"(a1), "r"(a2), "r"(a3), "r"(b0), "r"(b1));
}

// SPLIT>1: blockIdx.z selects a K-chunk; epilogue red-adds into C (pre-zeroed).
template<int BM, int BN, int T, int WN, int SPLIT>
__global__ __launch_bounds__(T) void gemm_tf32_kernel(
    const float* __restrict__ A, const float* __restrict__ B,
    float* __restrict__ C, int M, int N, int K)
{
    constexpr int BK = 32;
    constexpr int AS_STRIDE = 40;       // == 8 (mod 32): 2-phase LDS.64 frag loads
    constexpr int BS_STRIDE = BN + 4;   // == 4 (mod 16) in 8B units: conflict-free
    constexpr int NA = BM * BK / (4 * T);
    constexpr int NB = BK * BN / (4 * T);

    extern __shared__ float smem[];
    float* AsBase = smem;                         // [2][BM][AS_STRIDE]
    float* BsBase = smem + 2 * BM * AS_STRIDE;    // [2][BK][BS_STRIDE]

    const int tid  = threadIdx.x;
    const int wid  = tid >> 5;
    const int lane = tid & 31;
    const int lr   = lane >> 2;
    const int lc   = lane & 3;
    const int wm   = wid / WN;
    const int wn   = wid % WN;
    const int wrow = wm * 64;
    const int wcol = wn * 32;
    const int brow = blockIdx.y * BM;
    const int bcol = blockIdx.x * BN;
    const int k0   = blockIdx.z * (K / SPLIT);

    float acc[4][4][4];
    #pragma unroll
    for (int i = 0; i < 4; i++)
        #pragma unroll
        for (int j = 0; j < 4; j++)
            #pragma unroll
            for (int q = 0; q < 4; q++) acc[i][j][q] = 0.0f;

    float4 ra[NA], rb[NB];

    auto ldg_tile = [&](int kk) {
        #pragma unroll
        for (int p = 0; p < NA; p++) {
            int idx = tid + p * T;
            int r = idx >> 3, c4 = (idx & 7) << 2;
            int grow = brow + r;
            ra[p] = (grow < M) ? *(const float4*)&A[(size_t)grow * K + kk + c4]
                               : make_float4(0.f, 0.f, 0.f, 0.f);
        }
        #pragma unroll
        for (int p = 0; p < NB; p++) {
            int idx = tid + p * T;
            int k = idx / (BN / 4), n4 = (idx % (BN / 4)) << 2;
            rb[p] = *(const float4*)&B[(size_t)(kk + k) * N + bcol + n4];
        }
    };

    auto sts_tile = [&](int buf) {
        float* as = AsBase + buf * BM * AS_STRIDE;
        float* bs = BsBase + buf * BK * BS_STRIDE;
        #pragma unroll
        for (int p = 0; p < NA; p++) {
            int idx = tid + p * T;
            int r = idx >> 3, c4 = (idx & 7) << 2;
            float* ap = &as[r * AS_STRIDE + c4];
            ap[0] = rtf(ra[p].x); ap[1] = rtf(ra[p].y);
            ap[2] = rtf(ra[p].z); ap[3] = rtf(ra[p].w);
        }
        #pragma unroll
        for (int p = 0; p < NB; p++) {
            int idx = tid + p * T;
            int k = idx / (BN / 4), n4 = (idx % (BN / 4)) << 2;
            float* bp = &bs[k * BS_STRIDE + n4];
            bp[0] = rtf(rb[p].x); bp[1] = rtf(rb[p].y);
            bp[2] = rtf(rb[p].z); bp[3] = rtf(rb[p].w);
        }
    };

    auto compute = [&](int buf) {
        const float* as = AsBase + buf * BM * AS_STRIDE;
        const float* bs = BsBase + buf * BK * BS_STRIDE;
        #pragma unroll
        for (int s = 0; s < 4; s++) {
            const int kb = s * 8 + lc * 2;
            uint2 af[4][2];
            #pragma unroll
            for (int i = 0; i < 4; i++) {
                const float* p = &as[(wrow + i * 16 + lr) * AS_STRIDE + kb];
                af[i][0] = *(const uint2*)p;
                af[i][1] = *(const uint2*)(p + 8 * AS_STRIDE);
            }
            unsigned bf0[4], bf1[4];
            #pragma unroll
            for (int j = 0; j < 4; j++) {
                const float* p = &bs[kb * BS_STRIDE + wcol + j * 8 + lr];
                bf0[j] = __float_as_uint(p[0]);
                bf1[j] = __float_as_uint(p[BS_STRIDE]);
            }
            #pragma unroll
            for (int i = 0; i < 4; i++)
                #pragma unroll
                for (int j = 0; j < 4; j++)
                    mma_tf32(acc[i][j],
                             af[i][0].x, af[i][1].x, af[i][0].y, af[i][1].y,
                             bf0[j], bf1[j]);
        }
    };

    ldg_tile(k0);
    sts_tile(0);
    __syncthreads();
    int buf = 0;
    const int ntiles = K / SPLIT / BK;
    for (int t = 0; t < ntiles; t++) {
        if (t + 1 < ntiles) ldg_tile(k0 + (t + 1) * BK);
        compute(buf);
        if (t + 1 < ntiles) {
            sts_tile(buf ^ 1);
            __syncthreads();
            buf ^= 1;
        }
    }

    #pragma unroll
    for (int i = 0; i < 4; i++) {
        int r0 = brow + wrow + i * 16 + lr;
        #pragma unroll
        for (int half = 0; half < 2; half++) {
            int r = r0 + half * 8;
            if (r < M) {
                #pragma unroll
                for (int j = 0; j < 4; j++) {
                    int cc = bcol + wcol + j * 8 + lc * 2;
                    float2 v = make_float2(acc[i][j][half * 2 + 0], acc[i][j][half * 2 + 1]);
                    if (SPLIT == 1)
                        *(float2*)&C[(size_t)r * N + cc] = v;
                    else
                        red_add_v2(&C[(size_t)r * N + cc], v);
                }
            }
        }
    }
}

// ---------------- gather aggregation, layer 1 (512 feat) ----------------
// block = one dst node, 128 threads (float4 each).
// Edges loaded cooperatively (one per lane, coalesced), distributed via shfl;
// feature gathers software-pipelined 8-deep for MLP.
__global__ __launch_bounds__(128) void agg1_kernel(const float* __restrict__ b1) {
    const int n    = blockIdx.x;
    const int lane = threadIdx.x & 31;
    const int f    = threadIdx.x * 4;
    const float di = g_dinv[n];
    const float w0 = di * di;

    float4 hv = *(const float4*)&g_h1[(size_t)n * H_SIZE + f];
    float4 acc = make_float4(hv.x * w0, hv.y * w0, hv.z * w0, hv.w * w0);

    const int beg = g_off[n], end = g_off[n + 1];
    for (int base = beg; base < end; base += 32) {
        int idx = base + lane;
        int2 ew = (idx < end) ? g_csr[idx] : make_int2(0, 0);
        const int cnt = min(32, end - base);
        int j = 0;
        for (; j + 8 <= cnt; j += 8) {
            float4 v[8];
            float  wt[8];
            #pragma unroll
            for (int q = 0; q < 8; q++) {
                int   s = __shfl_sync(0xffffffffu, ew.x, j + q);
                wt[q]   = __int_as_float(__shfl_sync(0xffffffffu, ew.y, j + q));
                v[q]    = *(const float4*)&g_h1[(size_t)s * H_SIZE + f];
            }
            #pragma unroll
            for (int q = 0; q < 8; q++) {
                acc.x = fmaf(wt[q], v[q].x, acc.x);
                acc.y = fmaf(wt[q], v[q].y, acc.y);
                acc.z = fmaf(wt[q], v[q].z, acc.z);
                acc.w = fmaf(wt[q], v[q].w, acc.w);
            }
        }
        if (j + 4 <= cnt) {
            float4 v[4];
            float  wt[4];
            #pragma unroll
            for (int q = 0; q < 4; q++) {
                int   s = __shfl_sync(0xffffffffu, ew.x, j + q);
                wt[q]   = __int_as_float(__shfl_sync(0xffffffffu, ew.y, j + q));
                v[q]    = *(const float4*)&g_h1[(size_t)s * H_SIZE + f];
            }
            #pragma unroll
            for (int q = 0; q < 4; q++) {
                acc.x = fmaf(wt[q], v[q].x, acc.x);
                acc.y = fmaf(wt[q], v[q].y, acc.y);
                acc.z = fmaf(wt[q], v[q].z, acc.z);
                acc.w = fmaf(wt[q], v[q].w, acc.w);
            }
            j += 4;
        }
        for (; j < cnt; j++) {
            int   s  = __shfl_sync(0xffffffffu, ew.x, j);
            float wt = __int_as_float(__shfl_sync(0xffffffffu, ew.y, j));
            float4 v = *(const float4*)&g_h1[(size_t)s * H_SIZE + f];
            acc.x = fmaf(wt, v.x, acc.x); acc.y = fmaf(wt, v.y, acc.y);
            acc.z = fmaf(wt, v.z, acc.z); acc.w = fmaf(wt, v.w, acc.w);
        }
    }

    float4 bb = *(const float4*)&b1[f];
    acc.x = fmaxf(acc.x + bb.x, 0.0f);
    acc.y = fmaxf(acc.y + bb.y, 0.0f);
    acc.z = fmaxf(acc.z + bb.z, 0.0f);
    acc.w = fmaxf(acc.w + bb.w, 0.0f);
    *(float4*)&g_agg1[(size_t)n * H_SIZE + f] = acc;
}

// ---------------- fused: layer-2 gather + bias + log_softmax ----------------
// one warp per node; lane owns feats {lane, lane+32}; shfl-distributed edges,
// 4-deep pipelined gather (8 loads in flight).
__global__ __launch_bounds__(256) void agg2_final_kernel(
    const float* __restrict__ b2, float* __restrict__ out)
{
    int warp = (blockIdx.x * blockDim.x + threadIdx.x) >> 5;
    int lane = threadIdx.x & 31;
    if (warp >= N_NODES) return;

    const float di = g_dinv[warp];
    const float w0 = di * di;
    const float* hrow = &g_h2[(size_t)warp * OUT_SIZE];
    float v0 = hrow[lane]      * w0;
    float v1 = hrow[lane + 32] * w0;

    const int beg = g_off[warp], end = g_off[warp + 1];
    for (int base = beg; base < end; base += 32) {
        int idx = base + lane;
        int2 ew = (idx < end) ? g_csr[idx] : make_int2(0, 0);
        const int cnt = min(32, end - base);
        int j = 0;
        for (; j + 4 <= cnt; j += 4) {
            float a0[4], a1[4], wt[4];
            #pragma unroll
            for (int q = 0; q < 4; q++) {
                int   s = __shfl_sync(0xffffffffu, ew.x, j + q);
                wt[q]   = __int_as_float(__shfl_sync(0xffffffffu, ew.y, j + q));
                const float* r = &g_h2[(size_t)s * OUT_SIZE];
                a0[q] = r[lane];
                a1[q] = r[lane + 32];
            }
            #pragma unroll
            for (int q = 0; q < 4; q++) {
                v0 = fmaf(wt[q], a0[q], v0);
                v1 = fmaf(wt[q], a1[q], v1);
            }
        }
        for (; j < cnt; j++) {
            int   s  = __shfl_sync(0xffffffffu, ew.x, j);
            float wt = __int_as_float(__shfl_sync(0xffffffffu, ew.y, j));
            const float* r = &g_h2[(size_t)s * OUT_SIZE];
            v0 = fmaf(wt, r[lane], v0);
            v1 = fmaf(wt, r[lane + 32], v1);
        }
    }

    v0 += b2[lane];
    v1 += b2[lane + 32];
    out[(size_t)warp * OUT_SIZE + lane]      = v0;
    out[(size_t)warp * OUT_SIZE + lane + 32] = v1;

    float m = fmaxf(v0, v1);
    #pragma unroll
    for (int o = 16; o; o >>= 1) m = fmaxf(m, __shfl_xor_sync(0xffffffffu, m, o));
    float s = __expf(v0 - m) + __expf(v1 - m);
    #pragma unroll
    for (int o = 16; o; o >>= 1) s += __shfl_xor_sync(0xffffffffu, s, o);
    float lse = m + __logf(s);
    float* out2 = out + (size_t)N_NODES * OUT_SIZE;
    out2[(size_t)warp * OUT_SIZE + lane]      = v0 - lse;
    out2[(size_t)warp * OUT_SIZE + lane + 32] = v1 - lse;
}

// ---------------- launch ----------------
extern "C" void kernel_launch(void* const* d_in, const int* in_sizes, int n_in,
                              void* d_out, int out_size)
{
    const float* x  = (const float*)d_in[0];
    const int*   ei = (const int*)  d_in[1];
    const float* W1 = (const float*)d_in[2];
    const float* b1 = (const float*)d_in[3];
    const float* W2 = (const float*)d_in[4];
    const float* b2 = (const float*)d_in[5];
    float* out = (float*)d_out;

    const int* src = ei;
    const int* dst = ei + N_EDGES;

    float *p_h1, *p_agg1, *p_h2;
    cudaGetSymbolAddress((void**)&p_h1,   g_h1);
    cudaGetSymbolAddress((void**)&p_agg1, g_agg1);
    cudaGetSymbolAddress((void**)&p_h2,   g_h2);

    const int SMEM1 = (2 * 128 * 40 + 2 * 32 * 132) * 4;  // 74752 B
    const int SMEM2 = (2 * 128 * 40 + 2 * 32 * 68)  * 4;  // 58368 B
    cudaFuncSetAttribute(gemm_tf32_kernel<128, 128, 256, 4, 1>,
                         cudaFuncAttributeMaxDynamicSharedMemorySize, SMEM1);
    cudaFuncSetAttribute(gemm_tf32_kernel<128, 64, 128, 2, 4>,
                         cudaFuncAttributeMaxDynamicSharedMemorySize, SMEM2);

    // one-time side-stream resources (no device memory; work per call identical)
    static cudaStream_t s2 = nullptr;
    static cudaEvent_t evFork = nullptr, evJoin = nullptr;
    if (s2 == nullptr) {
        cudaStreamCreateWithFlags(&s2, cudaStreamNonBlocking);
        cudaEventCreateWithFlags(&evFork, cudaEventDisableTiming);
        cudaEventCreateWithFlags(&evJoin, cudaEventDisableTiming);
    }

    // ---- fork: CSR build + h2 zero on s2, concurrent with GEMM1 ----
    cudaEventRecord(evFork, 0);
    cudaStreamWaitEvent(s2, evFork, 0);

    zero_h2_kernel<<<(N_NODES * OUT_SIZE / 4 + 255) / 256, 256, 0, s2>>>();
    {
        void* args[] = { (void*)&src, (void*)&dst };
        cudaLaunchCooperativeKernel((void*)csr_build_kernel,
                                    dim3(148), dim3(256), args, 0, s2);
    }
    cudaEventRecord(evJoin, s2);

    // ---- layer 1 GEMM (default stream, overlaps with s2) ----
    {
        dim3 grid(H_SIZE / 128, (N_NODES + 127) / 128);
        gemm_tf32_kernel<128, 128, 256, 4, 1><<<grid, 256, SMEM1>>>(
            x, W1, p_h1, N_NODES, H_SIZE, IN_SIZE);
    }

    // ---- join, then agg1 ----
    cudaStreamWaitEvent(0, evJoin, 0);
    agg1_kernel<<<N_NODES, 128>>>(b1);

    // ---- layer 2 GEMM, split-K=4 (red.add into zeroed h2) ----
    {
        dim3 grid(OUT_SIZE / 64, (N_NODES + 127) / 128, 4);
        gemm_tf32_kernel<128, 64, 128, 2, 4><<<grid, 128, SMEM2>>>(
            p_agg1, W2, p_h2, N_NODES, OUT_SIZE, H_SIZE);
    }

    // ---- fused layer-2 gather + bias + log_softmax ----
    agg2_final_kernel<<<(N_NODES * 32 + 255) / 256, 256>>>(b2, out);
}

// round 12
// speedup vs baseline: 2.4544x; 1.0231x over previous
#include <cuda_runtime.h>
#include <cuda_fp16.h>
#include <cooperative_groups.h>
#include <math.h>

namespace cg = cooperative_groups;

#define N_NODES  10000
#define IN_SIZE  512
#define H_SIZE   512
#define OUT_SIZE 64
#define N_EDGES  163840

// ---------------- scratch (no allocations allowed) ----------------
__device__ int    g_cnt [N_NODES];
__device__ int    g_pos [N_NODES];
__device__ int    g_off [N_NODES + 1];
__device__ int2   g_csr [N_EDGES];        // (src, norm-as-bits)
__device__ float  g_dinv[N_NODES];
__device__ __half g_h1h[N_NODES * H_SIZE];    // x@W1 in fp16 (gather payload)
__device__ float  g_agg1[N_NODES * H_SIZE];   // relu(Â h1 + b1)
__device__ float  g_h2  [N_NODES * OUT_SIZE]; // agg1@W2 (split-K accumulated)

// ---------------- fused CSR build (cooperative) ----------------
__global__ __launch_bounds__(256) void csr_build_kernel(
    const int* __restrict__ src, const int* __restrict__ dst)
{
    cg::grid_group grid = cg::this_grid();
    const int tid = blockIdx.x * blockDim.x + threadIdx.x;
    const int nth = gridDim.x * blockDim.x;

    for (int n = tid; n < N_NODES; n += nth) { g_cnt[n] = 0; g_pos[n] = 0; }
    grid.sync();

    for (int e = tid; e < N_EDGES; e += nth) atomicAdd(&g_cnt[dst[e]], 1);
    grid.sync();

    for (int n = tid; n < N_NODES; n += nth)
        g_dinv[n] = rsqrtf((float)(g_cnt[n] + 1));

    if (blockIdx.x == 0) {
        __shared__ int s[256];
        const int t = threadIdx.x;
        const int CH = (N_NODES + 255) / 256;
        int base = t * CH;
        int sum = 0;
        for (int i = 0; i < CH; i++) {
            int idx = base + i;
            if (idx < N_NODES) sum += g_cnt[idx];
        }
        s[t] = sum;
        __syncthreads();
        for (int o = 1; o < 256; o <<= 1) {
            int v = (t >= o) ? s[t - o] : 0;
            __syncthreads();
            s[t] += v;
            __syncthreads();
        }
        int run = s[t] - sum;
        for (int i = 0; i < CH; i++) {
            int idx = base + i;
            if (idx < N_NODES) { g_off[idx] = run; run += g_cnt[idx]; }
        }
        if (t == 255) g_off[N_NODES] = N_EDGES;
    }
    grid.sync();

    for (int e = tid; e < N_EDGES; e += nth) {
        int sN = src[e], d = dst[e];
        int slot = g_off[d] + atomicAdd(&g_pos[d], 1);
        g_csr[slot] = make_int2(sN, __float_as_int(g_dinv[sN] * g_dinv[d]));
    }
}

// ---------------- zero h2 (needed for split-K red.add) ----------------
__global__ void zero_h2_kernel() {
    int i = blockIdx.x * blockDim.x + threadIdx.x;
    if (i < N_NODES * OUT_SIZE / 4)
        ((float4*)g_h2)[i] = make_float4(0.f, 0.f, 0.f, 0.f);
}

// ---------------- tf32 rounding (rna) ----------------
__device__ __forceinline__ unsigned to_tf32(float f) {
    unsigned o;
    asm("cvt.rna.tf32.f32 %0, %1;" : "=r"(o) : "f"(f));
    return o;
}
__device__ __forceinline__ float rtf(float f) { return __uint_as_float(to_tf32(f)); }

__device__ __forceinline__ void red_add_v2(float* p, float2 v) {
    asm volatile("red.global.add.v2.f32 [%0], {%1, %2};"
                 :: "l"(p), "f"(v.x), "f"(v.y) : "memory");
}

// ---------------- tf32 tensor-core GEMM (rounds A,B on the fly) ----------------
__device__ __forceinline__ void mma_tf32(float* d,
    unsigned a0, unsigned a1, unsigned a2, unsigned a3,
    unsigned b0, unsigned b1)
{
    asm volatile(
        "mma.sync.aligned.m16n8k8.row.col.f32.tf32.tf32.f32 "
        "{%0,%1,%2,%3}, {%4,%5,%6,%7}, {%8,%9}, {%0,%1,%2,%3};"
        : "+f"(d[0]), "+f"(d[1]), "+f"(d[2]), "+f"(d[3])
        : "r"(a0), "r"(a1), "r"(a2), "r"(a3), "r"(b0), "r"(b1));
}

// HALF_OUT: C is __half* (fp16 store). SPLIT>1: red.add into fp32 C (pre-zeroed).
template<int BM, int BN, int T, int WN, int SPLIT, bool HALF_OUT>
__global__ __launch_bounds__(T) void gemm_tf32_kernel(
    const float* __restrict__ A, const float* __restrict__ B,
    void* __restrict__ Cv, int M, int N, int K)
{
    constexpr int BK = 32;
    constexpr int AS_STRIDE = 40;       // == 8 (mod 32): 2-phase LDS.64 frag loads
    constexpr int BS_STRIDE = BN + 4;   // == 4 (mod 16) in 8B units: conflict-free
    constexpr int NA = BM * BK / (4 * T);
    constexpr int NB = BK * BN / (4 * T);

    extern __shared__ float smem[];
    float* AsBase = smem;                         // [2][BM][AS_STRIDE]
    float* BsBase = smem + 2 * BM * AS_STRIDE;    // [2][BK][BS_STRIDE]

    const int tid  = threadIdx.x;
    const int wid  = tid >> 5;
    const int lane = tid & 31;
    const int lr   = lane >> 2;
    const int lc   = lane & 3;
    const int wm   = wid / WN;
    const int wn   = wid % WN;
    const int wrow = wm * 64;
    const int wcol = wn * 32;
    const int brow = blockIdx.y * BM;
    const int bcol = blockIdx.x * BN;
    const int k0   = blockIdx.z * (K / SPLIT);

    float acc[4][4][4];
    #pragma unroll
    for (int i = 0; i < 4; i++)
        #pragma unroll
        for (int j = 0; j < 4; j++)
            #pragma unroll
            for (int q = 0; q < 4; q++) acc[i][j][q] = 0.0f;

    float4 ra[NA], rb[NB];

    auto ldg_tile = [&](int kk) {
        #pragma unroll
        for (int p = 0; p < NA; p++) {
            int idx = tid + p * T;
            int r = idx >> 3, c4 = (idx & 7) << 2;
            int grow = brow + r;
            ra[p] = (grow < M) ? *(const float4*)&A[(size_t)grow * K + kk + c4]
                               : make_float4(0.f, 0.f, 0.f, 0.f);
        }
        #pragma unroll
        for (int p = 0; p < NB; p++) {
            int idx = tid + p * T;
            int k = idx / (BN / 4), n4 = (idx % (BN / 4)) << 2;
            rb[p] = *(const float4*)&B[(size_t)(kk + k) * N + bcol + n4];
        }
    };

    auto sts_tile = [&](int buf) {
        float* as = AsBase + buf * BM * AS_STRIDE;
        float* bs = BsBase + buf * BK * BS_STRIDE;
        #pragma unroll
        for (int p = 0; p < NA; p++) {
            int idx = tid + p * T;
            int r = idx >> 3, c4 = (idx & 7) << 2;
            float* ap = &as[r * AS_STRIDE + c4];
            ap[0] = rtf(ra[p].x); ap[1] = rtf(ra[p].y);
            ap[2] = rtf(ra[p].z); ap[3] = rtf(ra[p].w);
        }
        #pragma unroll
        for (int p = 0; p < NB; p++) {
            int idx = tid + p * T;
            int k = idx / (BN / 4), n4 = (idx % (BN / 4)) << 2;
            float* bp = &bs[k * BS_STRIDE + n4];
            bp[0] = rtf(rb[p].x); bp[1] = rtf(rb[p].y);
            bp[2] = rtf(rb[p].z); bp[3] = rtf(rb[p].w);
        }
    };

    auto compute = [&](int buf) {
        const float* as = AsBase + buf * BM * AS_STRIDE;
        const float* bs = BsBase + buf * BK * BS_STRIDE;
        #pragma unroll
        for (int s = 0; s < 4; s++) {
            const int kb = s * 8 + lc * 2;
            uint2 af[4][2];
            #pragma unroll
            for (int i = 0; i < 4; i++) {
                const float* p = &as[(wrow + i * 16 + lr) * AS_STRIDE + kb];
                af[i][0] = *(const uint2*)p;
                af[i][1] = *(const uint2*)(p + 8 * AS_STRIDE);
            }
            unsigned bf0[4], bf1[4];
            #pragma unroll
            for (int j = 0; j < 4; j++) {
                const float* p = &bs[kb * BS_STRIDE + wcol + j * 8 + lr];
                bf0[j] = __float_as_uint(p[0]);
                bf1[j] = __float_as_uint(p[BS_STRIDE]);
            }
            #pragma unroll
            for (int i = 0; i < 4; i++)
                #pragma unroll
                for (int j = 0; j < 4; j++)
                    mma_tf32(acc[i][j],
                             af[i][0].x, af[i][1].x, af[i][0].y, af[i][1].y,
                             bf0[j], bf1[j]);
        }
    };

    ldg_tile(k0);
    sts_tile(0);
    __syncthreads();
    int buf = 0;
    const int ntiles = K / SPLIT / BK;
    for (int t = 0; t < ntiles; t++) {
        if (t + 1 < ntiles) ldg_tile(k0 + (t + 1) * BK);
        compute(buf);
        if (t + 1 < ntiles) {
            sts_tile(buf ^ 1);
            __syncthreads();
            buf ^= 1;
        }
    }

    #pragma unroll
    for (int i = 0; i < 4; i++) {
        int r0 = brow + wrow + i * 16 + lr;
        #pragma unroll
        for (int half = 0; half < 2; half++) {
            int r = r0 + half * 8;
            if (r < M) {
                #pragma unroll
                for (int j = 0; j < 4; j++) {
                    int cc = bcol + wcol + j * 8 + lc * 2;
                    float2 v = make_float2(acc[i][j][half * 2 + 0], acc[i][j][half * 2 + 1]);
                    if (HALF_OUT) {
                        __half* C = (__half*)Cv;
                        *(__half2*)&C[(size_t)r * N + cc] = __floats2half2_rn(v.x, v.y);
                    } else if (SPLIT == 1) {
                        float* C = (float*)Cv;
                        *(float2*)&C[(size_t)r * N + cc] = v;
                    } else {
                        float* C = (float*)Cv;
                        red_add_v2(&C[(size_t)r * N + cc], v);
                    }
                }
            }
        }
    }
}

// ---------------- gather aggregation, layer 1 (512 feat, fp16 payload) ----------------
// block = one dst node, 128 threads (4 halves = uint2 each).
// Edges loaded coalesced (one per lane), shfl-distributed; 8-deep pipelined gather.
__global__ __launch_bounds__(128) void agg1_kernel(const float* __restrict__ b1) {
    const int n    = blockIdx.x;
    const int lane = threadIdx.x & 31;
    const int f    = threadIdx.x * 4;       // half index
    const float di = g_dinv[n];
    const float w0 = di * di;

    uint2 sv = *(const uint2*)&g_h1h[(size_t)n * H_SIZE + f];
    float2 s0 = __half22float2(*(__half2*)&sv.x);
    float2 s1 = __half22float2(*(__half2*)&sv.y);
    float4 acc = make_float4(s0.x * w0, s0.y * w0, s1.x * w0, s1.y * w0);

    const int beg = g_off[n], end = g_off[n + 1];
    for (int base = beg; base < end; base += 32) {
        int idx = base + lane;
        int2 ew = (idx < end) ? g_csr[idx] : make_int2(0, 0);
        const int cnt = min(32, end - base);
        int j = 0;
        for (; j + 8 <= cnt; j += 8) {
            uint2 v[8];
            float wt[8];
            #pragma unroll
            for (int q = 0; q < 8; q++) {
                int   s = __shfl_sync(0xffffffffu, ew.x, j + q);
                wt[q]   = __int_as_float(__shfl_sync(0xffffffffu, ew.y, j + q));
                v[q]    = *(const uint2*)&g_h1h[(size_t)s * H_SIZE + f];
            }
            #pragma unroll
            for (int q = 0; q < 8; q++) {
                float2 a = __half22float2(*(__half2*)&v[q].x);
                float2 b = __half22float2(*(__half2*)&v[q].y);
                acc.x = fmaf(wt[q], a.x, acc.x);
                acc.y = fmaf(wt[q], a.y, acc.y);
                acc.z = fmaf(wt[q], b.x, acc.z);
                acc.w = fmaf(wt[q], b.y, acc.w);
            }
        }
        if (j + 4 <= cnt) {
            uint2 v[4];
            float wt[4];
            #pragma unroll
            for (int q = 0; q < 4; q++) {
                int   s = __shfl_sync(0xffffffffu, ew.x, j + q);
                wt[q]   = __int_as_float(__shfl_sync(0xffffffffu, ew.y, j + q));
                v[q]    = *(const uint2*)&g_h1h[(size_t)s * H_SIZE + f];
            }
            #pragma unroll
            for (int q = 0; q < 4; q++) {
                float2 a = __half22float2(*(__half2*)&v[q].x);
                float2 b = __half22float2(*(__half2*)&v[q].y);
                acc.x = fmaf(wt[q], a.x, acc.x);
                acc.y = fmaf(wt[q], a.y, acc.y);
                acc.z = fmaf(wt[q], b.x, acc.z);
                acc.w = fmaf(wt[q], b.y, acc.w);
            }
            j += 4;
        }
        for (; j < cnt; j++) {
            int   s  = __shfl_sync(0xffffffffu, ew.x, j);
            float wt = __int_as_float(__shfl_sync(0xffffffffu, ew.y, j));
            uint2 v  = *(const uint2*)&g_h1h[(size_t)s * H_SIZE + f];
            float2 a = __half22float2(*(__half2*)&v.x);
            float2 b = __half22float2(*(__half2*)&v.y);
            acc.x = fmaf(wt, a.x, acc.x); acc.y = fmaf(wt, a.y, acc.y);
            acc.z = fmaf(wt, b.x, acc.z); acc.w = fmaf(wt, b.y, acc.w);
        }
    }

    float4 bb = *(const float4*)&b1[f];
    acc.x = fmaxf(acc.x + bb.x, 0.0f);
    acc.y = fmaxf(acc.y + bb.y, 0.0f);
    acc.z = fmaxf(acc.z + bb.z, 0.0f);
    acc.w = fmaxf(acc.w + bb.w, 0.0f);
    *(float4*)&g_agg1[(size_t)n * H_SIZE + f] = acc;
}

// ---------------- fused: layer-2 gather + bias + log_softmax ----------------
__global__ __launch_bounds__(256) void agg2_final_kernel(
    const float* __restrict__ b2, float* __restrict__ out)
{
    int warp = (blockIdx.x * blockDim.x + threadIdx.x) >> 5;
    int lane = threadIdx.x & 31;
    if (warp >= N_NODES) return;

    const float di = g_dinv[warp];
    const float w0 = di * di;
    const float* hrow = &g_h2[(size_t)warp * OUT_SIZE];
    float v0 = hrow[lane]      * w0;
    float v1 = hrow[lane + 32] * w0;

    const int beg = g_off[warp], end = g_off[warp + 1];
    for (int base = beg; base < end; base += 32) {
        int idx = base + lane;
        int2 ew = (idx < end) ? g_csr[idx] : make_int2(0, 0);
        const int cnt = min(32, end - base);
        int j = 0;
        for (; j + 4 <= cnt; j += 4) {
            float a0[4], a1[4], wt[4];
            #pragma unroll
            for (int q = 0; q < 4; q++) {
                int   s = __shfl_sync(0xffffffffu, ew.x, j + q);
                wt[q]   = __int_as_float(__shfl_sync(0xffffffffu, ew.y, j + q));
                const float* r = &g_h2[(size_t)s * OUT_SIZE];
                a0[q] = r[lane];
                a1[q] = r[lane + 32];
            }
            #pragma unroll
            for (int q = 0; q < 4; q++) {
                v0 = fmaf(wt[q], a0[q], v0);
                v1 = fmaf(wt[q], a1[q], v1);
            }
        }
        for (; j < cnt; j++) {
            int   s  = __shfl_sync(0xffffffffu, ew.x, j);
            float wt = __int_as_float(__shfl_sync(0xffffffffu, ew.y, j));
            const float* r = &g_h2[(size_t)s * OUT_SIZE];
            v0 = fmaf(wt, r[lane], v0);
            v1 = fmaf(wt, r[lane + 32], v1);
        }
    }

    v0 += b2[lane];
    v1 += b2[lane + 32];
    out[(size_t)warp * OUT_SIZE + lane]      = v0;
    out[(size_t)warp * OUT_SIZE + lane + 32] = v1;

    float m = fmaxf(v0, v1);
    #pragma unroll
    for (int o = 16; o; o >>= 1) m = fmaxf(m, __shfl_xor_sync(0xffffffffu, m, o));
    float s = __expf(v0 - m) + __expf(v1 - m);
    #pragma unroll
    for (int o = 16; o; o >>= 1) s += __shfl_xor_sync(0xffffffffu, s, o);
    float lse = m + __logf(s);
    float* out2 = out + (size_t)N_NODES * OUT_SIZE;
    out2[(size_t)warp * OUT_SIZE + lane]      = v0 - lse;
    out2[(size_t)warp * OUT_SIZE + lane + 32] = v1 - lse;
}

// ---------------- launch ----------------
extern "C" void kernel_launch(void* const* d_in, const int* in_sizes, int n_in,
                              void* d_out, int out_size)
{
    const float* x  = (const float*)d_in[0];
    const int*   ei = (const int*)  d_in[1];
    const float* W1 = (const float*)d_in[2];
    const float* b1 = (const float*)d_in[3];
    const float* W2 = (const float*)d_in[4];
    const float* b2 = (const float*)d_in[5];
    float* out = (float*)d_out;

    const int* src = ei;
    const int* dst = ei + N_EDGES;

    void *p_h1h, *p_agg1, *p_h2;
    cudaGetSymbolAddress(&p_h1h,  g_h1h);
    cudaGetSymbolAddress(&p_agg1, g_agg1);
    cudaGetSymbolAddress(&p_h2,   g_h2);

    const int SMEM1 = (2 * 128 * 40 + 2 * 32 * 132) * 4;  // 74752 B
    const int SMEM2 = (2 * 128 * 40 + 2 * 32 * 68)  * 4;  // 58368 B
    cudaFuncSetAttribute(gemm_tf32_kernel<128, 128, 256, 4, 1, true>,
                         cudaFuncAttributeMaxDynamicSharedMemorySize, SMEM1);
    cudaFuncSetAttribute(gemm_tf32_kernel<128, 64, 128, 2, 4, false>,
                         cudaFuncAttributeMaxDynamicSharedMemorySize, SMEM2);

    // one-time side-stream resources (no device memory; work per call identical)
    static cudaStream_t s2 = nullptr;
    static cudaEvent_t evFork = nullptr, evJoin = nullptr;
    if (s2 == nullptr) {
        cudaStreamCreateWithFlags(&s2, cudaStreamNonBlocking);
        cudaEventCreateWithFlags(&evFork, cudaEventDisableTiming);
        cudaEventCreateWithFlags(&evJoin, cudaEventDisableTiming);
    }

    // ---- fork: CSR build + h2 zero on s2, concurrent with GEMM1 ----
    cudaEventRecord(evFork, 0);
    cudaStreamWaitEvent(s2, evFork, 0);

    zero_h2_kernel<<<(N_NODES * OUT_SIZE / 4 + 255) / 256, 256, 0, s2>>>();
    {
        void* args[] = { (void*)&src, (void*)&dst };
        cudaLaunchCooperativeKernel((void*)csr_build_kernel,
                                    dim3(148), dim3(256), args, 0, s2);
    }
    cudaEventRecord(evJoin, s2);

    // ---- layer 1 GEMM (fp16 output; overlaps with s2) ----
    {
        dim3 grid(H_SIZE / 128, (N_NODES + 127) / 128);
        gemm_tf32_kernel<128, 128, 256, 4, 1, true><<<grid, 256, SMEM1>>>(
            x, W1, p_h1h, N_NODES, H_SIZE, IN_SIZE);
    }

    // ---- join, then agg1 (fp16 gathers, fp32 accumulate) ----
    cudaStreamWaitEvent(0, evJoin, 0);
    agg1_kernel<<<N_NODES, 128>>>(b1);

    // ---- layer 2 GEMM, split-K=4 (red.add into zeroed h2) ----
    {
        dim3 grid(OUT_SIZE / 64, (N_NODES + 127) / 128, 4);
        gemm_tf32_kernel<128, 64, 128, 2, 4, false><<<grid, 128, SMEM2>>>(
            (const float*)p_agg1, W2, p_h2, N_NODES, OUT_SIZE, H_SIZE);
    }

    // ---- fused layer-2 gather + bias + log_softmax ----
    agg2_final_kernel<<<(N_NODES * 32 + 255) / 256, 256>>>(b2, out);
}

// round 13
// speedup vs baseline: 3.0322x; 1.2354x over previous
#include <cuda_runtime.h>
#include <cuda_fp16.h>
#include <cooperative_groups.h>
#include <math.h>

namespace cg = cooperative_groups;

#define N_NODES  10000
#define IN_SIZE  512
#define H_SIZE   512
#define OUT_SIZE 64
#define N_EDGES  163840

// ---------------- scratch (no allocations allowed) ----------------
__device__ int    g_cnt [N_NODES];
__device__ int    g_pos [N_NODES];
__device__ int    g_off [N_NODES + 1];
__device__ int2   g_csr [N_EDGES];        // (src, norm-as-bits)
__device__ float  g_dinv[N_NODES];
__device__ __half g_w1t [H_SIZE * IN_SIZE];   // W1^T as half  [N][K]
__device__ __half g_w2t [OUT_SIZE * H_SIZE];  // W2^T as half  [N][K]
__device__ __half g_h1h [N_NODES * H_SIZE];   // x@W1 in fp16 (gather payload)
__device__ float  g_agg1[N_NODES * H_SIZE];   // relu(Â h1 + b1)
__device__ float  g_h2  [N_NODES * OUT_SIZE]; // agg1@W2 (split-K accumulated)

// ---------------- fused CSR build (cooperative) ----------------
__global__ __launch_bounds__(256) void csr_build_kernel(
    const int* __restrict__ src, const int* __restrict__ dst)
{
    cg::grid_group grid = cg::this_grid();
    const int tid = blockIdx.x * blockDim.x + threadIdx.x;
    const int nth = gridDim.x * blockDim.x;

    for (int n = tid; n < N_NODES; n += nth) { g_cnt[n] = 0; g_pos[n] = 0; }
    grid.sync();

    for (int e = tid; e < N_EDGES; e += nth) atomicAdd(&g_cnt[dst[e]], 1);
    grid.sync();

    for (int n = tid; n < N_NODES; n += nth)
        g_dinv[n] = rsqrtf((float)(g_cnt[n] + 1));

    if (blockIdx.x == 0) {
        __shared__ int s[256];
        const int t = threadIdx.x;
        const int CH = (N_NODES + 255) / 256;
        int base = t * CH;
        int sum = 0;
        for (int i = 0; i < CH; i++) {
            int idx = base + i;
            if (idx < N_NODES) sum += g_cnt[idx];
        }
        s[t] = sum;
        __syncthreads();
        for (int o = 1; o < 256; o <<= 1) {
            int v = (t >= o) ? s[t - o] : 0;
            __syncthreads();
            s[t] += v;
            __syncthreads();
        }
        int run = s[t] - sum;
        for (int i = 0; i < CH; i++) {
            int idx = base + i;
            if (idx < N_NODES) { g_off[idx] = run; run += g_cnt[idx]; }
        }
        if (t == 255) g_off[N_NODES] = N_EDGES;
    }
    grid.sync();

    for (int e = tid; e < N_EDGES; e += nth) {
        int sN = src[e], d = dst[e];
        int slot = g_off[d] + atomicAdd(&g_pos[d], 1);
        g_csr[slot] = make_int2(sN, __float_as_int(g_dinv[sN] * g_dinv[d]));
    }
}

// ---------------- zero h2 (needed for split-K red.add) ----------------
__global__ void zero_h2_kernel() {
    int i = blockIdx.x * blockDim.x + threadIdx.x;
    if (i < N_NODES * OUT_SIZE / 4)
        ((float4*)g_h2)[i] = make_float4(0.f, 0.f, 0.f, 0.f);
}

// ---------------- weight transpose + fp16 convert:  W[K][N] -> WT[N][K] ----------------
__global__ __launch_bounds__(256) void transpose_cvt_kernel(
    const float* __restrict__ in, __half* __restrict__ out, int K, int N)
{
    __shared__ __half tile[32][33];
    const int bn = blockIdx.x * 32;   // n base
    const int bk = blockIdx.y * 32;   // k base
    const int tx = threadIdx.x;       // 0..31
    const int ty = threadIdx.y;       // 0..7
    for (int i = ty; i < 32; i += 8)
        tile[i][tx] = __float2half_rn(in[(size_t)(bk + i) * N + bn + tx]);
    __syncthreads();
    for (int i = ty; i < 32; i += 8)
        out[(size_t)(bn + i) * K + bk + tx] = tile[tx][i];
}

__device__ __forceinline__ void red_add_v2(float* p, float2 v) {
    asm volatile("red.global.add.v2.f32 [%0], {%1, %2};"
                 :: "l"(p), "f"(v.x), "f"(v.y) : "memory");
}

// ---------------- fp16 m16n8k16 MMA (fp32 accumulate) ----------------
__device__ __forceinline__ void mma_f16(float* d,
    unsigned a0, unsigned a1, unsigned a2, unsigned a3,
    unsigned b0, unsigned b1)
{
    asm volatile(
        "mma.sync.aligned.m16n8k16.row.col.f32.f16.f16.f32 "
        "{%0,%1,%2,%3}, {%4,%5,%6,%7}, {%8,%9}, {%0,%1,%2,%3};"
        : "+f"(d[0]), "+f"(d[1]), "+f"(d[2]), "+f"(d[3])
        : "r"(a0), "r"(a1), "r"(a2), "r"(a3), "r"(b0), "r"(b1));
}

// A: fp32 [M][K] (converted to fp16 during smem staging).
// Bt: fp16 [N][K] (pre-transposed weights).
// HALF_OUT: C is __half*. SPLIT>1: red.add into fp32 C (pre-zeroed).
template<int BM, int BN, int T, int WN, int SPLIT, bool HALF_OUT>
__global__ __launch_bounds__(T) void gemm_f16_kernel(
    const float* __restrict__ A, const __half* __restrict__ Bt,
    void* __restrict__ Cv, int M, int N, int K)
{
    constexpr int BK = 32;
    constexpr int STR = 40;             // half stride: bank = (20*row + lc) mod 32 -> conflict-free
    constexpr int NA  = BM * BK / (4 * T);   // float4 A loads / thread / tile
    constexpr int NBH = BK * BN / (8 * T);   // uint4 (8-half) B loads / thread / tile

    extern __shared__ char smemraw[];
    __half* AsBase = (__half*)smemraw;            // [2][BM][STR]
    __half* BsBase = AsBase + 2 * BM * STR;       // [2][BN][STR]

    const int tid  = threadIdx.x;
    const int wid  = tid >> 5;
    const int lane = tid & 31;
    const int lr   = lane >> 2;
    const int lc   = lane & 3;
    const int wm   = wid / WN;
    const int wn   = wid % WN;
    const int wrow = wm * 64;
    const int wcol = wn * 32;
    const int brow = blockIdx.y * BM;
    const int bcol = blockIdx.x * BN;
    const int k0   = blockIdx.z * (K / SPLIT);

    float acc[4][4][4];
    #pragma unroll
    for (int i = 0; i < 4; i++)
        #pragma unroll
        for (int j = 0; j < 4; j++)
            #pragma unroll
            for (int q = 0; q < 4; q++) acc[i][j][q] = 0.0f;

    float4 ra[NA];
    uint4  rb[NBH];

    auto ldg_tile = [&](int kk) {
        #pragma unroll
        for (int p = 0; p < NA; p++) {
            int idx = tid + p * T;
            int r = idx >> 3, c4 = (idx & 7) << 2;
            int grow = brow + r;
            ra[p] = (grow < M) ? *(const float4*)&A[(size_t)grow * K + kk + c4]
                               : make_float4(0.f, 0.f, 0.f, 0.f);
        }
        #pragma unroll
        for (int p = 0; p < NBH; p++) {
            int idx = tid + p * T;
            int nrow = idx >> 2, k8 = (idx & 3) << 3;
            rb[p] = *(const uint4*)&Bt[(size_t)(bcol + nrow) * K + kk + k8];
        }
    };

    auto sts_tile = [&](int buf) {
        __half* as = AsBase + buf * BM * STR;
        __half* bs = BsBase + buf * BN * STR;
        #pragma unroll
        for (int p = 0; p < NA; p++) {
            int idx = tid + p * T;
            int r = idx >> 3, c4 = (idx & 7) << 2;
            __half2 h01 = __floats2half2_rn(ra[p].x, ra[p].y);
            __half2 h23 = __floats2half2_rn(ra[p].z, ra[p].w);
            uint2 pk;
            pk.x = *(unsigned*)&h01;
            pk.y = *(unsigned*)&h23;
            *(uint2*)&as[r * STR + c4] = pk;
        }
        #pragma unroll
        for (int p = 0; p < NBH; p++) {
            int idx = tid + p * T;
            int nrow = idx >> 2, k8 = (idx & 3) << 3;
            *(uint4*)&bs[nrow * STR + k8] = rb[p];
        }
    };

    auto compute = [&](int buf) {
        const __half* as = AsBase + buf * BM * STR;
        const __half* bs = BsBase + buf * BN * STR;
        #pragma unroll
        for (int s = 0; s < 2; s++) {           // two k16 steps per BK=32 tile
            const int kb = s * 16 + lc * 2;
            unsigned a0[4], a1[4], a2[4], a3[4];
            #pragma unroll
            for (int i = 0; i < 4; i++) {
                const __half* p0 = &as[(wrow + i * 16 + lr) * STR + kb];
                a0[i] = *(const unsigned*)p0;            // (row,   k)
                a1[i] = *(const unsigned*)(p0 + 8 * STR);// (row+8, k)
                a2[i] = *(const unsigned*)(p0 + 8);      // (row,   k+8)
                a3[i] = *(const unsigned*)(p0 + 8 * STR + 8);
            }
            unsigned b0[4], b1[4];
            #pragma unroll
            for (int j = 0; j < 4; j++) {
                const __half* p = &bs[(wcol + j * 8 + lr) * STR + kb];
                b0[j] = *(const unsigned*)p;
                b1[j] = *(const unsigned*)(p + 8);
            }
            #pragma unroll
            for (int i = 0; i < 4; i++)
                #pragma unroll
                for (int j = 0; j < 4; j++)
                    mma_f16(acc[i][j], a0[i], a1[i], a2[i], a3[i], b0[j], b1[j]);
        }
    };

    ldg_tile(k0);
    sts_tile(0);
    __syncthreads();
    int buf = 0;
    const int ntiles = K / SPLIT / BK;
    for (int t = 0; t < ntiles; t++) {
        if (t + 1 < ntiles) ldg_tile(k0 + (t + 1) * BK);
        compute(buf);
        if (t + 1 < ntiles) {
            sts_tile(buf ^ 1);
            __syncthreads();
            buf ^= 1;
        }
    }

    #pragma unroll
    for (int i = 0; i < 4; i++) {
        int r0 = brow + wrow + i * 16 + lr;
        #pragma unroll
        for (int half = 0; half < 2; half++) {
            int r = r0 + half * 8;
            if (r < M) {
                #pragma unroll
                for (int j = 0; j < 4; j++) {
                    int cc = bcol + wcol + j * 8 + lc * 2;
                    float2 v = make_float2(acc[i][j][half * 2 + 0], acc[i][j][half * 2 + 1]);
                    if (HALF_OUT) {
                        __half* C = (__half*)Cv;
                        *(__half2*)&C[(size_t)r * N + cc] = __floats2half2_rn(v.x, v.y);
                    } else if (SPLIT == 1) {
                        float* C = (float*)Cv;
                        *(float2*)&C[(size_t)r * N + cc] = v;
                    } else {
                        float* C = (float*)Cv;
                        red_add_v2(&C[(size_t)r * N + cc], v);
                    }
                }
            }
        }
    }
}

// ---------------- gather aggregation, layer 1 (512 feat, fp16 payload) ----------------
// 64 threads per node (8 halves = uint4 each); 2 nodes per 128-thread block.
// Edges loaded coalesced per warp, shfl-distributed; 4-deep pipelined gathers.
__global__ __launch_bounds__(128) void agg1_kernel(const float* __restrict__ b1) {
    const int tid  = threadIdx.x;
    const int n    = blockIdx.x * 2 + (tid >> 6);
    const int lane = tid & 31;
    const int f    = (tid & 63) * 8;       // half index
    const float di = g_dinv[n];
    const float w0 = di * di;

    const __half* hbase = g_h1h + f;
    float acc[8];
    {
        uint4 sv = *(const uint4*)&hbase[n * H_SIZE];
        float2 p0 = __half22float2(*(__half2*)&sv.x);
        float2 p1 = __half22float2(*(__half2*)&sv.y);
        float2 p2 = __half22float2(*(__half2*)&sv.z);
        float2 p3 = __half22float2(*(__half2*)&sv.w);
        acc[0] = p0.x * w0; acc[1] = p0.y * w0;
        acc[2] = p1.x * w0; acc[3] = p1.y * w0;
        acc[4] = p2.x * w0; acc[5] = p2.y * w0;
        acc[6] = p3.x * w0; acc[7] = p3.y * w0;
    }

    const int beg = g_off[n], end = g_off[n + 1];
    for (int base = beg; base < end; base += 32) {
        int idx = base + lane;
        int2 ew = (idx < end) ? g_csr[idx] : make_int2(0, 0);
        const int cnt = min(32, end - base);
        int j = 0;
        for (; j + 4 <= cnt; j += 4) {
            uint4 v[4];
            float wt[4];
            #pragma unroll
            for (int q = 0; q < 4; q++) {
                int   s = __shfl_sync(0xffffffffu, ew.x, j + q);
                wt[q]   = __int_as_float(__shfl_sync(0xffffffffu, ew.y, j + q));
                v[q]    = *(const uint4*)&hbase[s * H_SIZE];
            }
            #pragma unroll
            for (int q = 0; q < 4; q++) {
                float2 p0 = __half22float2(*(__half2*)&v[q].x);
                float2 p1 = __half22float2(*(__half2*)&v[q].y);
                float2 p2 = __half22float2(*(__half2*)&v[q].z);
                float2 p3 = __half22float2(*(__half2*)&v[q].w);
                acc[0] = fmaf(wt[q], p0.x, acc[0]); acc[1] = fmaf(wt[q], p0.y, acc[1]);
                acc[2] = fmaf(wt[q], p1.x, acc[2]); acc[3] = fmaf(wt[q], p1.y, acc[3]);
                acc[4] = fmaf(wt[q], p2.x, acc[4]); acc[5] = fmaf(wt[q], p2.y, acc[5]);
                acc[6] = fmaf(wt[q], p3.x, acc[6]); acc[7] = fmaf(wt[q], p3.y, acc[7]);
            }
        }
        for (; j < cnt; j++) {
            int   s  = __shfl_sync(0xffffffffu, ew.x, j);
            float wt = __int_as_float(__shfl_sync(0xffffffffu, ew.y, j));
            uint4 v  = *(const uint4*)&hbase[s * H_SIZE];
            float2 p0 = __half22float2(*(__half2*)&v.x);
            float2 p1 = __half22float2(*(__half2*)&v.y);
            float2 p2 = __half22float2(*(__half2*)&v.z);
            float2 p3 = __half22float2(*(__half2*)&v.w);
            acc[0] = fmaf(wt, p0.x, acc[0]); acc[1] = fmaf(wt, p0.y, acc[1]);
            acc[2] = fmaf(wt, p1.x, acc[2]); acc[3] = fmaf(wt, p1.y, acc[3]);
            acc[4] = fmaf(wt, p2.x, acc[4]); acc[5] = fmaf(wt, p2.y, acc[5]);
            acc[6] = fmaf(wt, p3.x, acc[6]); acc[7] = fmaf(wt, p3.y, acc[7]);
        }
    }

    float4 ba = *(const float4*)&b1[f];
    float4 bbv = *(const float4*)&b1[f + 4];
    float* op = &g_agg1[(size_t)n * H_SIZE + f];
    float4 o0 = make_float4(fmaxf(acc[0] + ba.x, 0.f), fmaxf(acc[1] + ba.y, 0.f),
                            fmaxf(acc[2] + ba.z, 0.f), fmaxf(acc[3] + ba.w, 0.f));
    float4 o1 = make_float4(fmaxf(acc[4] + bbv.x, 0.f), fmaxf(acc[5] + bbv.y, 0.f),
                            fmaxf(acc[6] + bbv.z, 0.f), fmaxf(acc[7] + bbv.w, 0.f));
    *(float4*)op = o0;
    *(float4*)(op + 4) = o1;
}

// ---------------- fused: layer-2 gather + bias + log_softmax ----------------
__global__ __launch_bounds__(256) void agg2_final_kernel(
    const float* __restrict__ b2, float* __restrict__ out)
{
    int warp = (blockIdx.x * blockDim.x + threadIdx.x) >> 5;
    int lane = threadIdx.x & 31;
    if (warp >= N_NODES) return;

    const float di = g_dinv[warp];
    const float w0 = di * di;
    const float* hrow = &g_h2[(size_t)warp * OUT_SIZE];
    float v0 = hrow[lane]      * w0;
    float v1 = hrow[lane + 32] * w0;

    const int beg = g_off[warp], end = g_off[warp + 1];
    for (int base = beg; base < end; base += 32) {
        int idx = base + lane;
        int2 ew = (idx < end) ? g_csr[idx] : make_int2(0, 0);
        const int cnt = min(32, end - base);
        int j = 0;
        for (; j + 4 <= cnt; j += 4) {
            float a0[4], a1[4], wt[4];
            #pragma unroll
            for (int q = 0; q < 4; q++) {
                int   s = __shfl_sync(0xffffffffu, ew.x, j + q);
                wt[q]   = __int_as_float(__shfl_sync(0xffffffffu, ew.y, j + q));
                const float* r = &g_h2[(size_t)s * OUT_SIZE];
                a0[q] = r[lane];
                a1[q] = r[lane + 32];
            }
            #pragma unroll
            for (int q = 0; q < 4; q++) {
                v0 = fmaf(wt[q], a0[q], v0);
                v1 = fmaf(wt[q], a1[q], v1);
            }
        }
        for (; j < cnt; j++) {
            int   s  = __shfl_sync(0xffffffffu, ew.x, j);
            float wt = __int_as_float(__shfl_sync(0xffffffffu, ew.y, j));
            const float* r = &g_h2[(size_t)s * OUT_SIZE];
            v0 = fmaf(wt, r[lane], v0);
            v1 = fmaf(wt, r[lane + 32], v1);
        }
    }

    v0 += b2[lane];
    v1 += b2[lane + 32];
    out[(size_t)warp * OUT_SIZE + lane]      = v0;
    out[(size_t)warp * OUT_SIZE + lane + 32] = v1;

    float m = fmaxf(v0, v1);
    #pragma unroll
    for (int o = 16; o; o >>= 1) m = fmaxf(m, __shfl_xor_sync(0xffffffffu, m, o));
    float s = __expf(v0 - m) + __expf(v1 - m);
    #pragma unroll
    for (int o = 16; o; o >>= 1) s += __shfl_xor_sync(0xffffffffu, s, o);
    float lse = m + __logf(s);
    float* out2 = out + (size_t)N_NODES * OUT_SIZE;
    out2[(size_t)warp * OUT_SIZE + lane]      = v0 - lse;
    out2[(size_t)warp * OUT_SIZE + lane + 32] = v1 - lse;
}

// ---------------- launch ----------------
extern "C" void kernel_launch(void* const* d_in, const int* in_sizes, int n_in,
                              void* d_out, int out_size)
{
    const float* x  = (const float*)d_in[0];
    const int*   ei = (const int*)  d_in[1];
    const float* W1 = (const float*)d_in[2];
    const float* b1 = (const float*)d_in[3];
    const float* W2 = (const float*)d_in[4];
    const float* b2 = (const float*)d_in[5];
    float* out = (float*)d_out;

    const int* src = ei;
    const int* dst = ei + N_EDGES;

    void *p_w1t, *p_w2t, *p_h1h, *p_agg1, *p_h2;
    cudaGetSymbolAddress(&p_w1t,  g_w1t);
    cudaGetSymbolAddress(&p_w2t,  g_w2t);
    cudaGetSymbolAddress(&p_h1h,  g_h1h);
    cudaGetSymbolAddress(&p_agg1, g_agg1);
    cudaGetSymbolAddress(&p_h2,   g_h2);

    const int SMEM1 = (2 * 128 * 40 + 2 * 128 * 40) * 2;  // 40960 B
    const int SMEM2 = (2 * 128 * 40 + 2 * 64 * 40)  * 2;  // 30720 B
    cudaFuncSetAttribute(gemm_f16_kernel<128, 128, 256, 4, 1, true>,
                         cudaFuncAttributeMaxDynamicSharedMemorySize, SMEM1);
    cudaFuncSetAttribute(gemm_f16_kernel<128, 64, 128, 2, 4, false>,
                         cudaFuncAttributeMaxDynamicSharedMemorySize, SMEM2);

    // one-time side-stream resources (no device memory; work per call identical)
    static cudaStream_t s2 = nullptr;
    static cudaEvent_t evFork = nullptr, evJoin = nullptr;
    if (s2 == nullptr) {
        cudaStreamCreateWithFlags(&s2, cudaStreamNonBlocking);
        cudaEventCreateWithFlags(&evFork, cudaEventDisableTiming);
        cudaEventCreateWithFlags(&evJoin, cudaEventDisableTiming);
    }

    // ---- fork: CSR build + h2 zero on s2, concurrent with weight prep + GEMM1 ----
    cudaEventRecord(evFork, 0);
    cudaStreamWaitEvent(s2, evFork, 0);

    zero_h2_kernel<<<(N_NODES * OUT_SIZE / 4 + 255) / 256, 256, 0, s2>>>();
    {
        void* args[] = { (void*)&src, (void*)&dst };
        cudaLaunchCooperativeKernel((void*)csr_build_kernel,
                                    dim3(148), dim3(256), args, 0, s2);
    }
    cudaEventRecord(evJoin, s2);

    // ---- weight transpose + fp16 convert (stream 0, feeds GEMM1/GEMM2) ----
    transpose_cvt_kernel<<<dim3(H_SIZE / 32, IN_SIZE / 32), dim3(32, 8)>>>(
        W1, (__half*)p_w1t, IN_SIZE, H_SIZE);
    transpose_cvt_kernel<<<dim3(OUT_SIZE / 32, H_SIZE / 32), dim3(32, 8)>>>(
        W2, (__half*)p_w2t, H_SIZE, OUT_SIZE);

    // ---- layer 1 GEMM (fp16 MMA, fp16 output; overlaps with s2) ----
    {
        dim3 grid(H_SIZE / 128, (N_NODES + 127) / 128);
        gemm_f16_kernel<128, 128, 256, 4, 1, true><<<grid, 256, SMEM1>>>(
            x, (const __half*)p_w1t, p_h1h, N_NODES, H_SIZE, IN_SIZE);
    }

    // ---- join, then agg1 (fp16 gathers, fp32 accumulate) ----
    cudaStreamWaitEvent(0, evJoin, 0);
    agg1_kernel<<<N_NODES / 2, 128>>>(b1);

    // ---- layer 2 GEMM, fp16 MMA, split-K=4 (red.add into zeroed h2) ----
    {
        dim3 grid(OUT_SIZE / 64, (N_NODES + 127) / 128, 4);
        gemm_f16_kernel<128, 64, 128, 2, 4, false><<<grid, 128, SMEM2>>>(
            (const float*)p_agg1, (const __half*)p_w2t, p_h2,
            N_NODES, OUT_SIZE, H_SIZE);
    }

    // ---- fused layer-2 gather + bias + log_softmax ----
    agg2_final_kernel<<<(N_NODES * 32 + 255) / 256, 256>>>(b2, out);
}

// round 14
// speedup vs baseline: 3.0378x; 1.0018x over previous
#include <cuda_runtime.h>
#include <cuda_fp16.h>
#include <cooperative_groups.h>
#include <math.h>

namespace cg = cooperative_groups;

#define N_NODES  10000
#define IN_SIZE  512
#define H_SIZE   512
#define OUT_SIZE 64
#define N_EDGES  163840

// ---------------- scratch (no allocations allowed) ----------------
__device__ int    g_cnt [N_NODES];
__device__ int    g_pos [N_NODES];
__device__ int    g_off [N_NODES + 1];
__device__ int2   g_csr [N_EDGES];        // (src, norm-as-bits)
__device__ float  g_dinv[N_NODES];
__device__ __half g_w1t [H_SIZE * IN_SIZE];   // W1^T as half  [N][K]
__device__ __half g_w2t [OUT_SIZE * H_SIZE];  // W2^T as half  [N][K]
__device__ __half g_h1h [N_NODES * H_SIZE];   // x@W1 in fp16 (gather payload)
__device__ float  g_agg1[N_NODES * H_SIZE];   // relu(Â h1 + b1)
__device__ float  g_h2  [N_NODES * OUT_SIZE]; // agg1@W2 (split-K accumulated)

// ---------------- fused CSR build + h2 zero (cooperative) ----------------
__global__ __launch_bounds__(256) void csr_build_kernel(
    const int* __restrict__ src, const int* __restrict__ dst)
{
    cg::grid_group grid = cg::this_grid();
    const int tid = blockIdx.x * blockDim.x + threadIdx.x;
    const int nth = gridDim.x * blockDim.x;

    // phase 1: zero counters + h2 (split-K target)
    for (int n = tid; n < N_NODES; n += nth) { g_cnt[n] = 0; g_pos[n] = 0; }
    for (int i = tid; i < N_NODES * OUT_SIZE / 4; i += nth)
        ((float4*)g_h2)[i] = make_float4(0.f, 0.f, 0.f, 0.f);
    grid.sync();

    for (int e = tid; e < N_EDGES; e += nth) atomicAdd(&g_cnt[dst[e]], 1);
    grid.sync();

    for (int n = tid; n < N_NODES; n += nth)
        g_dinv[n] = rsqrtf((float)(g_cnt[n] + 1));

    if (blockIdx.x == 0) {
        __shared__ int s[256];
        const int t = threadIdx.x;
        const int CH = (N_NODES + 255) / 256;
        int base = t * CH;
        int sum = 0;
        for (int i = 0; i < CH; i++) {
            int idx = base + i;
            if (idx < N_NODES) sum += g_cnt[idx];
        }
        s[t] = sum;
        __syncthreads();
        for (int o = 1; o < 256; o <<= 1) {
            int v = (t >= o) ? s[t - o] : 0;
            __syncthreads();
            s[t] += v;
            __syncthreads();
        }
        int run = s[t] - sum;
        for (int i = 0; i < CH; i++) {
            int idx = base + i;
            if (idx < N_NODES) { g_off[idx] = run; run += g_cnt[idx]; }
        }
        if (t == 255) g_off[N_NODES] = N_EDGES;
    }
    grid.sync();

    for (int e = tid; e < N_EDGES; e += nth) {
        int sN = src[e], d = dst[e];
        int slot = g_off[d] + atomicAdd(&g_pos[d], 1);
        g_csr[slot] = make_int2(sN, __float_as_int(g_dinv[sN] * g_dinv[d]));
    }
}

// ---------------- fused weight transpose + fp16 convert (both W1 and W2) ----------------
// blocks 0..255: W1 (512x512); blocks 256..287: W2 (512x64)
__global__ __launch_bounds__(256) void transpose_both_kernel(
    const float* __restrict__ W1, const float* __restrict__ W2)
{
    __shared__ __half tile[32][33];
    int b = blockIdx.x;
    const float* in;
    __half* out;
    int K, N, bn, bk;
    if (b < 256) {
        in = W1; out = g_w1t; K = IN_SIZE; N = H_SIZE;
        bn = (b & 15) * 32; bk = (b >> 4) * 32;
    } else {
        b -= 256;
        in = W2; out = g_w2t; K = H_SIZE; N = OUT_SIZE;
        bn = (b & 1) * 32; bk = (b >> 1) * 32;
    }
    const int tx = threadIdx.x & 31;
    const int ty = threadIdx.x >> 5;   // 0..7
    for (int i = ty; i < 32; i += 8)
        tile[i][tx] = __float2half_rn(in[(size_t)(bk + i) * N + bn + tx]);
    __syncthreads();
    for (int i = ty; i < 32; i += 8)
        out[(size_t)(bn + i) * K + bk + tx] = tile[tx][i];
}

__device__ __forceinline__ void red_add_v2(float* p, float2 v) {
    asm volatile("red.global.add.v2.f32 [%0], {%1, %2};"
                 :: "l"(p), "f"(v.x), "f"(v.y) : "memory");
}

// ---------------- fp16 m16n8k16 MMA (fp32 accumulate) ----------------
__device__ __forceinline__ void mma_f16(float* d,
    unsigned a0, unsigned a1, unsigned a2, unsigned a3,
    unsigned b0, unsigned b1)
{
    asm volatile(
        "mma.sync.aligned.m16n8k16.row.col.f32.f16.f16.f32 "
        "{%0,%1,%2,%3}, {%4,%5,%6,%7}, {%8,%9}, {%0,%1,%2,%3};"
        : "+f"(d[0]), "+f"(d[1]), "+f"(d[2]), "+f"(d[3])
        : "r"(a0), "r"(a1), "r"(a2), "r"(a3), "r"(b0), "r"(b1));
}

// A: fp32 [M][K] (converted to fp16 during smem staging).
// Bt: fp16 [N][K] (pre-transposed weights).
// HALF_OUT: C is __half*. SPLIT>1: red.add into fp32 C (pre-zeroed).
template<int BM, int BN, int T, int WN, int SPLIT, bool HALF_OUT>
__global__ __launch_bounds__(T) void gemm_f16_kernel(
    const float* __restrict__ A, const __half* __restrict__ Bt,
    void* __restrict__ Cv, int M, int N, int K)
{
    constexpr int BK = 32;
    constexpr int STR = 40;             // half stride: conflict-free frag loads
    constexpr int NA  = BM * BK / (4 * T);   // float4 A loads / thread / tile
    constexpr int NBH = BK * BN / (8 * T);   // uint4 (8-half) B loads / thread / tile

    extern __shared__ char smemraw[];
    __half* AsBase = (__half*)smemraw;            // [2][BM][STR]
    __half* BsBase = AsBase + 2 * BM * STR;       // [2][BN][STR]

    const int tid  = threadIdx.x;
    const int wid  = tid >> 5;
    const int lane = tid & 31;
    const int lr   = lane >> 2;
    const int lc   = lane & 3;
    const int wm   = wid / WN;
    const int wn   = wid % WN;
    const int wrow = wm * 64;
    const int wcol = wn * 32;
    const int brow = blockIdx.y * BM;
    const int bcol = blockIdx.x * BN;
    const int k0   = blockIdx.z * (K / SPLIT);

    float acc[4][4][4];
    #pragma unroll
    for (int i = 0; i < 4; i++)
        #pragma unroll
        for (int j = 0; j < 4; j++)
            #pragma unroll
            for (int q = 0; q < 4; q++) acc[i][j][q] = 0.0f;

    float4 ra[NA];
    uint4  rb[NBH];

    auto ldg_tile = [&](int kk) {
        #pragma unroll
        for (int p = 0; p < NA; p++) {
            int idx = tid + p * T;
            int r = idx >> 3, c4 = (idx & 7) << 2;
            int grow = brow + r;
            ra[p] = (grow < M) ? *(const float4*)&A[(size_t)grow * K + kk + c4]
                               : make_float4(0.f, 0.f, 0.f, 0.f);
        }
        #pragma unroll
        for (int p = 0; p < NBH; p++) {
            int idx = tid + p * T;
            int nrow = idx >> 2, k8 = (idx & 3) << 3;
            rb[p] = *(const uint4*)&Bt[(size_t)(bcol + nrow) * K + kk + k8];
        }
    };

    auto sts_tile = [&](int buf) {
        __half* as = AsBase + buf * BM * STR;
        __half* bs = BsBase + buf * BN * STR;
        #pragma unroll
        for (int p = 0; p < NA; p++) {
            int idx = tid + p * T;
            int r = idx >> 3, c4 = (idx & 7) << 2;
            __half2 h01 = __floats2half2_rn(ra[p].x, ra[p].y);
            __half2 h23 = __floats2half2_rn(ra[p].z, ra[p].w);
            uint2 pk;
            pk.x = *(unsigned*)&h01;
            pk.y = *(unsigned*)&h23;
            *(uint2*)&as[r * STR + c4] = pk;
        }
        #pragma unroll
        for (int p = 0; p < NBH; p++) {
            int idx = tid + p * T;
            int nrow = idx >> 2, k8 = (idx & 3) << 3;
            *(uint4*)&bs[nrow * STR + k8] = rb[p];
        }
    };

    auto compute = [&](int buf) {
        const __half* as = AsBase + buf * BM * STR;
        const __half* bs = BsBase + buf * BN * STR;
        #pragma unroll
        for (int s = 0; s < 2; s++) {           // two k16 steps per BK=32 tile
            const int kb = s * 16 + lc * 2;
            unsigned a0[4], a1[4], a2[4], a3[4];
            #pragma unroll
            for (int i = 0; i < 4; i++) {
                const __half* p0 = &as[(wrow + i * 16 + lr) * STR + kb];
                a0[i] = *(const unsigned*)p0;
                a1[i] = *(const unsigned*)(p0 + 8 * STR);
                a2[i] = *(const unsigned*)(p0 + 8);
                a3[i] = *(const unsigned*)(p0 + 8 * STR + 8);
            }
            unsigned b0[4], b1[4];
            #pragma unroll
            for (int j = 0; j < 4; j++) {
                const __half* p = &bs[(wcol + j * 8 + lr) * STR + kb];
                b0[j] = *(const unsigned*)p;
                b1[j] = *(const unsigned*)(p + 8);
            }
            #pragma unroll
            for (int i = 0; i < 4; i++)
                #pragma unroll
                for (int j = 0; j < 4; j++)
                    mma_f16(acc[i][j], a0[i], a1[i], a2[i], a3[i], b0[j], b1[j]);
        }
    };

    ldg_tile(k0);
    sts_tile(0);
    __syncthreads();
    int buf = 0;
    const int ntiles = K / SPLIT / BK;
    for (int t = 0; t < ntiles; t++) {
        if (t + 1 < ntiles) ldg_tile(k0 + (t + 1) * BK);
        compute(buf);
        if (t + 1 < ntiles) {
            sts_tile(buf ^ 1);
            __syncthreads();
            buf ^= 1;
        }
    }

    #pragma unroll
    for (int i = 0; i < 4; i++) {
        int r0 = brow + wrow + i * 16 + lr;
        #pragma unroll
        for (int half = 0; half < 2; half++) {
            int r = r0 + half * 8;
            if (r < M) {
                #pragma unroll
                for (int j = 0; j < 4; j++) {
                    int cc = bcol + wcol + j * 8 + lc * 2;
                    float2 v = make_float2(acc[i][j][half * 2 + 0], acc[i][j][half * 2 + 1]);
                    if (HALF_OUT) {
                        __half* C = (__half*)Cv;
                        *(__half2*)&C[(size_t)r * N + cc] = __floats2half2_rn(v.x, v.y);
                    } else if (SPLIT == 1) {
                        float* C = (float*)Cv;
                        *(float2*)&C[(size_t)r * N + cc] = v;
                    } else {
                        float* C = (float*)Cv;
                        red_add_v2(&C[(size_t)r * N + cc], v);
                    }
                }
            }
        }
    }
}

// ---------------- gather aggregation, layer 1 (512 feat, fp16 payload) ----------------
// 64 threads per node (8 halves = uint4 each); 2 nodes per 128-thread block.
__global__ __launch_bounds__(128) void agg1_kernel(const float* __restrict__ b1) {
    const int tid  = threadIdx.x;
    const int n    = blockIdx.x * 2 + (tid >> 6);
    const int lane = tid & 31;
    const int f    = (tid & 63) * 8;       // half index
    const float di = g_dinv[n];
    const float w0 = di * di;

    const __half* hbase = g_h1h + f;
    float acc[8];
    {
        uint4 sv = *(const uint4*)&hbase[n * H_SIZE];
        float2 p0 = __half22float2(*(__half2*)&sv.x);
        float2 p1 = __half22float2(*(__half2*)&sv.y);
        float2 p2 = __half22float2(*(__half2*)&sv.z);
        float2 p3 = __half22float2(*(__half2*)&sv.w);
        acc[0] = p0.x * w0; acc[1] = p0.y * w0;
        acc[2] = p1.x * w0; acc[3] = p1.y * w0;
        acc[4] = p2.x * w0; acc[5] = p2.y * w0;
        acc[6] = p3.x * w0; acc[7] = p3.y * w0;
    }

    const int beg = g_off[n], end = g_off[n + 1];
    for (int base = beg; base < end; base += 32) {
        int idx = base + lane;
        int2 ew = (idx < end) ? g_csr[idx] : make_int2(0, 0);
        const int cnt = min(32, end - base);
        int j = 0;
        for (; j + 4 <= cnt; j += 4) {
            uint4 v[4];
            float wt[4];
            #pragma unroll
            for (int q = 0; q < 4; q++) {
                int   s = __shfl_sync(0xffffffffu, ew.x, j + q);
                wt[q]   = __int_as_float(__shfl_sync(0xffffffffu, ew.y, j + q));
                v[q]    = *(const uint4*)&hbase[s * H_SIZE];
            }
            #pragma unroll
            for (int q = 0; q < 4; q++) {
                float2 p0 = __half22float2(*(__half2*)&v[q].x);
                float2 p1 = __half22float2(*(__half2*)&v[q].y);
                float2 p2 = __half22float2(*(__half2*)&v[q].z);
                float2 p3 = __half22float2(*(__half2*)&v[q].w);
                acc[0] = fmaf(wt[q], p0.x, acc[0]); acc[1] = fmaf(wt[q], p0.y, acc[1]);
                acc[2] = fmaf(wt[q], p1.x, acc[2]); acc[3] = fmaf(wt[q], p1.y, acc[3]);
                acc[4] = fmaf(wt[q], p2.x, acc[4]); acc[5] = fmaf(wt[q], p2.y, acc[5]);
                acc[6] = fmaf(wt[q], p3.x, acc[6]); acc[7] = fmaf(wt[q], p3.y, acc[7]);
            }
        }
        for (; j < cnt; j++) {
            int   s  = __shfl_sync(0xffffffffu, ew.x, j);
            float wt = __int_as_float(__shfl_sync(0xffffffffu, ew.y, j));
            uint4 v  = *(const uint4*)&hbase[s * H_SIZE];
            float2 p0 = __half22float2(*(__half2*)&v.x);
            float2 p1 = __half22float2(*(__half2*)&v.y);
            float2 p2 = __half22float2(*(__half2*)&v.z);
            float2 p3 = __half22float2(*(__half2*)&v.w);
            acc[0] = fmaf(wt, p0.x, acc[0]); acc[1] = fmaf(wt, p0.y, acc[1]);
            acc[2] = fmaf(wt, p1.x, acc[2]); acc[3] = fmaf(wt, p1.y, acc[3]);
            acc[4] = fmaf(wt, p2.x, acc[4]); acc[5] = fmaf(wt, p2.y, acc[5]);
            acc[6] = fmaf(wt, p3.x, acc[6]); acc[7] = fmaf(wt, p3.y, acc[7]);
        }
    }

    float4 ba = *(const float4*)&b1[f];
    float4 bbv = *(const float4*)&b1[f + 4];
    float* op = &g_agg1[(size_t)n * H_SIZE + f];
    float4 o0 = make_float4(fmaxf(acc[0] + ba.x, 0.f), fmaxf(acc[1] + ba.y, 0.f),
                            fmaxf(acc[2] + ba.z, 0.f), fmaxf(acc[3] + ba.w, 0.f));
    float4 o1 = make_float4(fmaxf(acc[4] + bbv.x, 0.f), fmaxf(acc[5] + bbv.y, 0.f),
                            fmaxf(acc[6] + bbv.z, 0.f), fmaxf(acc[7] + bbv.w, 0.f));
    *(float4*)op = o0;
    *(float4*)(op + 4) = o1;
}

// ---------------- fused: layer-2 gather + bias + log_softmax ----------------
__global__ __launch_bounds__(256) void agg2_final_kernel(
    const float* __restrict__ b2, float* __restrict__ out)
{
    int warp = (blockIdx.x * blockDim.x + threadIdx.x) >> 5;
    int lane = threadIdx.x & 31;
    if (warp >= N_NODES) return;

    const float di = g_dinv[warp];
    const float w0 = di * di;
    const float* hrow = &g_h2[(size_t)warp * OUT_SIZE];
    float v0 = hrow[lane]      * w0;
    float v1 = hrow[lane + 32] * w0;

    const int beg = g_off[warp], end = g_off[warp + 1];
    for (int base = beg; base < end; base += 32) {
        int idx = base + lane;
        int2 ew = (idx < end) ? g_csr[idx] : make_int2(0, 0);
        const int cnt = min(32, end - base);
        int j = 0;
        for (; j + 4 <= cnt; j += 4) {
            float a0[4], a1[4], wt[4];
            #pragma unroll
            for (int q = 0; q < 4; q++) {
                int   s = __shfl_sync(0xffffffffu, ew.x, j + q);
                wt[q]   = __int_as_float(__shfl_sync(0xffffffffu, ew.y, j + q));
                const float* r = &g_h2[(size_t)s * OUT_SIZE];
                a0[q] = r[lane];
                a1[q] = r[lane + 32];
            }
            #pragma unroll
            for (int q = 0; q < 4; q++) {
                v0 = fmaf(wt[q], a0[q], v0);
                v1 = fmaf(wt[q], a1[q], v1);
            }
        }
        for (; j < cnt; j++) {
            int   s  = __shfl_sync(0xffffffffu, ew.x, j);
            float wt = __int_as_float(__shfl_sync(0xffffffffu, ew.y, j));
            const float* r = &g_h2[(size_t)s * OUT_SIZE];
            v0 = fmaf(wt, r[lane], v0);
            v1 = fmaf(wt, r[lane + 32], v1);
        }
    }

    v0 += b2[lane];
    v1 += b2[lane + 32];
    out[(size_t)warp * OUT_SIZE + lane]      = v0;
    out[(size_t)warp * OUT_SIZE + lane + 32] = v1;

    float m = fmaxf(v0, v1);
    #pragma unroll
    for (int o = 16; o; o >>= 1) m = fmaxf(m, __shfl_xor_sync(0xffffffffu, m, o));
    float s = __expf(v0 - m) + __expf(v1 - m);
    #pragma unroll
    for (int o = 16; o; o >>= 1) s += __shfl_xor_sync(0xffffffffu, s, o);
    float lse = m + __logf(s);
    float* out2 = out + (size_t)N_NODES * OUT_SIZE;
    out2[(size_t)warp * OUT_SIZE + lane]      = v0 - lse;
    out2[(size_t)warp * OUT_SIZE + lane + 32] = v1 - lse;
}

// ---------------- launch ----------------
extern "C" void kernel_launch(void* const* d_in, const int* in_sizes, int n_in,
                              void* d_out, int out_size)
{
    const float* x  = (const float*)d_in[0];
    const int*   ei = (const int*)  d_in[1];
    const float* W1 = (const float*)d_in[2];
    const float* b1 = (const float*)d_in[3];
    const float* W2 = (const float*)d_in[4];
    const float* b2 = (const float*)d_in[5];
    float* out = (float*)d_out;

    const int* src = ei;
    const int* dst = ei + N_EDGES;

    void *p_w1t, *p_w2t, *p_h1h, *p_agg1, *p_h2;
    cudaGetSymbolAddress(&p_w1t,  g_w1t);
    cudaGetSymbolAddress(&p_w2t,  g_w2t);
    cudaGetSymbolAddress(&p_h1h,  g_h1h);
    cudaGetSymbolAddress(&p_agg1, g_agg1);
    cudaGetSymbolAddress(&p_h2,   g_h2);

    const int SMEM1 = (2 * 128 * 40 + 2 * 128 * 40) * 2;  // 40960 B
    const int SMEM2 = (2 * 128 * 40 + 2 * 64 * 40)  * 2;  // 30720 B
    cudaFuncSetAttribute(gemm_f16_kernel<128, 128, 256, 4, 1, true>,
                         cudaFuncAttributeMaxDynamicSharedMemorySize, SMEM1);
    cudaFuncSetAttribute(gemm_f16_kernel<128, 64, 128, 2, 4, false>,
                         cudaFuncAttributeMaxDynamicSharedMemorySize, SMEM2);

    // one-time side-stream resources (no device memory; work per call identical)
    static cudaStream_t s2 = nullptr;
    static cudaEvent_t evFork = nullptr, evJoin = nullptr;
    if (s2 == nullptr) {
        cudaStreamCreateWithFlags(&s2, cudaStreamNonBlocking);
        cudaEventCreateWithFlags(&evFork, cudaEventDisableTiming);
        cudaEventCreateWithFlags(&evJoin, cudaEventDisableTiming);
    }

    // ---- fork: CSR build (incl. h2 zero) on s2, concurrent with weight prep + GEMM1 ----
    cudaEventRecord(evFork, 0);
    cudaStreamWaitEvent(s2, evFork, 0);
    {
        void* args[] = { (void*)&src, (void*)&dst };
        cudaLaunchCooperativeKernel((void*)csr_build_kernel,
                                    dim3(148), dim3(256), args, 0, s2);
    }
    cudaEventRecord(evJoin, s2);

    // ---- fused weight transpose + fp16 convert (one launch, 288 blocks) ----
    transpose_both_kernel<<<288, 256>>>(W1, W2);

    // ---- layer 1 GEMM (fp16 MMA, fp16 output; overlaps with s2) ----
    {
        dim3 grid(H_SIZE / 128, (N_NODES + 127) / 128);
        gemm_f16_kernel<128, 128, 256, 4, 1, true><<<grid, 256, SMEM1>>>(
            x, (const __half*)p_w1t, p_h1h, N_NODES, H_SIZE, IN_SIZE);
    }

    // ---- join, then agg1 (fp16 gathers, fp32 accumulate) ----
    cudaStreamWaitEvent(0, evJoin, 0);
    agg1_kernel<<<N_NODES / 2, 128>>>(b1);

    // ---- layer 2 GEMM, fp16 MMA, split-K=4 (red.add into zeroed h2) ----
    {
        dim3 grid(OUT_SIZE / 64, (N_NODES + 127) / 128, 4);
        gemm_f16_kernel<128, 64, 128, 2, 4, false><<<grid, 128, SMEM2>>>(
            (const float*)p_agg1, (const __half*)p_w2t, p_h2,
            N_NODES, OUT_SIZE, H_SIZE);
    }

    // ---- fused layer-2 gather + bias + log_softmax ----
    agg2_final_kernel<<<(N_NODES * 32 + 255) / 256, 256>>>(b2, out);
}

// round 15
// speedup vs baseline: 3.4518x; 1.1363x over previous
#include <cuda_runtime.h>
#include <cuda_fp16.h>
#include <math.h>

#define N_NODES  10000
#define IN_SIZE  512
#define H_SIZE   512
#define OUT_SIZE 64
#define N_EDGES  163840

// ---------------- scratch (no allocations allowed) ----------------
__device__ int    g_cnt [N_NODES];
__device__ int    g_pos [N_NODES];
__device__ int    g_off [N_NODES + 1];
__device__ int2   g_csr [N_EDGES];        // (src, norm-as-bits)
__device__ float  g_dinv[N_NODES];
__device__ __half g_w1t [H_SIZE * IN_SIZE];   // W1^T as half  [N][K]
__device__ __half g_w2t [OUT_SIZE * H_SIZE];  // W2^T as half  [N][K]
__device__ __half g_h1h [N_NODES * H_SIZE];   // x@W1 in fp16 (gather payload)
__device__ float  g_agg1[N_NODES * H_SIZE];   // relu(Â h1 + b1)
__device__ float  g_h2  [N_NODES * OUT_SIZE]; // agg1@W2 (split-K accumulated)

// ---------------- CSR build: plain (non-cooperative) phase kernels ----------------
__global__ __launch_bounds__(256) void prep_kernel() {
    int tid = blockIdx.x * blockDim.x + threadIdx.x;
    int nth = gridDim.x * blockDim.x;
    for (int n = tid; n < N_NODES; n += nth) { g_cnt[n] = 0; g_pos[n] = 0; }
    for (int i = tid; i < N_NODES * OUT_SIZE / 4; i += nth)
        ((float4*)g_h2)[i] = make_float4(0.f, 0.f, 0.f, 0.f);
}

__global__ __launch_bounds__(256) void count_kernel(const int* __restrict__ dst) {
    int e = blockIdx.x * blockDim.x + threadIdx.x;
    if (e < N_EDGES) atomicAdd(&g_cnt[dst[e]], 1);
}

// all blocks: dinv; block 0 additionally: exclusive scan -> g_off
__global__ __launch_bounds__(256) void scan_dinv_kernel() {
    int tid = blockIdx.x * blockDim.x + threadIdx.x;
    int nth = gridDim.x * blockDim.x;
    for (int n = tid; n < N_NODES; n += nth)
        g_dinv[n] = rsqrtf((float)(g_cnt[n] + 1));   // +1 self-loop

    if (blockIdx.x == 0) {
        __shared__ int s[256];
        const int t = threadIdx.x;
        const int CH = (N_NODES + 255) / 256;   // 40
        int base = t * CH;
        int sum = 0;
        for (int i = 0; i < CH; i++) {
            int idx = base + i;
            if (idx < N_NODES) sum += g_cnt[idx];
        }
        s[t] = sum;
        __syncthreads();
        for (int o = 1; o < 256; o <<= 1) {
            int v = (t >= o) ? s[t - o] : 0;
            __syncthreads();
            s[t] += v;
            __syncthreads();
        }
        int run = s[t] - sum;
        for (int i = 0; i < CH; i++) {
            int idx = base + i;
            if (idx < N_NODES) { g_off[idx] = run; run += g_cnt[idx]; }
        }
        if (t == 255) g_off[N_NODES] = N_EDGES;
    }
}

__global__ __launch_bounds__(256) void fill_kernel(
    const int* __restrict__ src, const int* __restrict__ dst)
{
    int e = blockIdx.x * blockDim.x + threadIdx.x;
    if (e >= N_EDGES) return;
    int sN = src[e], d = dst[e];
    int slot = g_off[d] + atomicAdd(&g_pos[d], 1);
    g_csr[slot] = make_int2(sN, __float_as_int(g_dinv[sN] * g_dinv[d]));
}

// ---------------- fused weight transpose + fp16 convert (both W1 and W2) ----------------
// blocks 0..255: W1 (512x512); blocks 256..287: W2 (512x64)
__global__ __launch_bounds__(256) void transpose_both_kernel(
    const float* __restrict__ W1, const float* __restrict__ W2)
{
    __shared__ __half tile[32][33];
    int b = blockIdx.x;
    const float* in;
    __half* out;
    int K, N, bn, bk;
    if (b < 256) {
        in = W1; out = g_w1t; K = IN_SIZE; N = H_SIZE;
        bn = (b & 15) * 32; bk = (b >> 4) * 32;
    } else {
        b -= 256;
        in = W2; out = g_w2t; K = H_SIZE; N = OUT_SIZE;
        bn = (b & 1) * 32; bk = (b >> 1) * 32;
    }
    const int tx = threadIdx.x & 31;
    const int ty = threadIdx.x >> 5;   // 0..7
    for (int i = ty; i < 32; i += 8)
        tile[i][tx] = __float2half_rn(in[(size_t)(bk + i) * N + bn + tx]);
    __syncthreads();
    for (int i = ty; i < 32; i += 8)
        out[(size_t)(bn + i) * K + bk + tx] = tile[tx][i];
}

__device__ __forceinline__ void red_add_v2(float* p, float2 v) {
    asm volatile("red.global.add.v2.f32 [%0], {%1, %2};"
                 :: "l"(p), "f"(v.x), "f"(v.y) : "memory");
}

// ---------------- fp16 m16n8k16 MMA (fp32 accumulate) ----------------
__device__ __forceinline__ void mma_f16(float* d,
    unsigned a0, unsigned a1, unsigned a2, unsigned a3,
    unsigned b0, unsigned b1)
{
    asm volatile(
        "mma.sync.aligned.m16n8k16.row.col.f32.f16.f16.f32 "
        "{%0,%1,%2,%3}, {%4,%5,%6,%7}, {%8,%9}, {%0,%1,%2,%3};"
        : "+f"(d[0]), "+f"(d[1]), "+f"(d[2]), "+f"(d[3])
        : "r"(a0), "r"(a1), "r"(a2), "r"(a3), "r"(b0), "r"(b1));
}

// A: fp32 [M][K] (converted to fp16 during smem staging).
// Bt: fp16 [N][K] (pre-transposed weights).
// HALF_OUT: C is __half*. SPLIT>1: red.add into fp32 C (pre-zeroed).
template<int BM, int BN, int T, int WN, int SPLIT, bool HALF_OUT>
__global__ __launch_bounds__(T) void gemm_f16_kernel(
    const float* __restrict__ A, const __half* __restrict__ Bt,
    void* __restrict__ Cv, int M, int N, int K)
{
    constexpr int BK = 32;
    constexpr int STR = 40;             // half stride: conflict-free frag loads
    constexpr int NA  = BM * BK / (4 * T);   // float4 A loads / thread / tile
    constexpr int NBH = BK * BN / (8 * T);   // uint4 (8-half) B loads / thread / tile

    extern __shared__ char smemraw[];
    __half* AsBase = (__half*)smemraw;            // [2][BM][STR]
    __half* BsBase = AsBase + 2 * BM * STR;       // [2][BN][STR]

    const int tid  = threadIdx.x;
    const int wid  = tid >> 5;
    const int lane = tid & 31;
    const int lr   = lane >> 2;
    const int lc   = lane & 3;
    const int wm   = wid / WN;
    const int wn   = wid % WN;
    const int wrow = wm * 64;
    const int wcol = wn * 32;
    const int brow = blockIdx.y * BM;
    const int bcol = blockIdx.x * BN;
    const int k0   = blockIdx.z * (K / SPLIT);

    float acc[4][4][4];
    #pragma unroll
    for (int i = 0; i < 4; i++)
        #pragma unroll
        for (int j = 0; j < 4; j++)
            #pragma unroll
            for (int q = 0; q < 4; q++) acc[i][j][q] = 0.0f;

    float4 ra[NA];
    uint4  rb[NBH];

    auto ldg_tile = [&](int kk) {
        #pragma unroll
        for (int p = 0; p < NA; p++) {
            int idx = tid + p * T;
            int r = idx >> 3, c4 = (idx & 7) << 2;
            int grow = brow + r;
            ra[p] = (grow < M) ? *(const float4*)&A[(size_t)grow * K + kk + c4]
                               : make_float4(0.f, 0.f, 0.f, 0.f);
        }
        #pragma unroll
        for (int p = 0; p < NBH; p++) {
            int idx = tid + p * T;
            int nrow = idx >> 2, k8 = (idx & 3) << 3;
            rb[p] = *(const uint4*)&Bt[(size_t)(bcol + nrow) * K + kk + k8];
        }
    };

    auto sts_tile = [&](int buf) {
        __half* as = AsBase + buf * BM * STR;
        __half* bs = BsBase + buf * BN * STR;
        #pragma unroll
        for (int p = 0; p < NA; p++) {
            int idx = tid + p * T;
            int r = idx >> 3, c4 = (idx & 7) << 2;
            __half2 h01 = __floats2half2_rn(ra[p].x, ra[p].y);
            __half2 h23 = __floats2half2_rn(ra[p].z, ra[p].w);
            uint2 pk;
            pk.x = *(unsigned*)&h01;
            pk.y = *(unsigned*)&h23;
            *(uint2*)&as[r * STR + c4] = pk;
        }
        #pragma unroll
        for (int p = 0; p < NBH; p++) {
            int idx = tid + p * T;
            int nrow = idx >> 2, k8 = (idx & 3) << 3;
            *(uint4*)&bs[nrow * STR + k8] = rb[p];
        }
    };

    auto compute = [&](int buf) {
        const __half* as = AsBase + buf * BM * STR;
        const __half* bs = BsBase + buf * BN * STR;
        #pragma unroll
        for (int s = 0; s < 2; s++) {           // two k16 steps per BK=32 tile
            const int kb = s * 16 + lc * 2;
            unsigned a0[4], a1[4], a2[4], a3[4];
            #pragma unroll
            for (int i = 0; i < 4; i++) {
                const __half* p0 = &as[(wrow + i * 16 + lr) * STR + kb];
                a0[i] = *(const unsigned*)p0;
                a1[i] = *(const unsigned*)(p0 + 8 * STR);
                a2[i] = *(const unsigned*)(p0 + 8);
                a3[i] = *(const unsigned*)(p0 + 8 * STR + 8);
            }
            unsigned b0[4], b1[4];
            #pragma unroll
            for (int j = 0; j < 4; j++) {
                const __half* p = &bs[(wcol + j * 8 + lr) * STR + kb];
                b0[j] = *(const unsigned*)p;
                b1[j] = *(const unsigned*)(p + 8);
            }
            #pragma unroll
            for (int i = 0; i < 4; i++)
                #pragma unroll
                for (int j = 0; j < 4; j++)
                    mma_f16(acc[i][j], a0[i], a1[i], a2[i], a3[i], b0[j], b1[j]);
        }
    };

    ldg_tile(k0);
    sts_tile(0);
    __syncthreads();
    int buf = 0;
    const int ntiles = K / SPLIT / BK;
    for (int t = 0; t < ntiles; t++) {
        if (t + 1 < ntiles) ldg_tile(k0 + (t + 1) * BK);
        compute(buf);
        if (t + 1 < ntiles) {
            sts_tile(buf ^ 1);
            __syncthreads();
            buf ^= 1;
        }
    }

    #pragma unroll
    for (int i = 0; i < 4; i++) {
        int r0 = brow + wrow + i * 16 + lr;
        #pragma unroll
        for (int half = 0; half < 2; half++) {
            int r = r0 + half * 8;
            if (r < M) {
                #pragma unroll
                for (int j = 0; j < 4; j++) {
                    int cc = bcol + wcol + j * 8 + lc * 2;
                    float2 v = make_float2(acc[i][j][half * 2 + 0], acc[i][j][half * 2 + 1]);
                    if (HALF_OUT) {
                        __half* C = (__half*)Cv;
                        *(__half2*)&C[(size_t)r * N + cc] = __floats2half2_rn(v.x, v.y);
                    } else if (SPLIT == 1) {
                        float* C = (float*)Cv;
                        *(float2*)&C[(size_t)r * N + cc] = v;
                    } else {
                        float* C = (float*)Cv;
                        red_add_v2(&C[(size_t)r * N + cc], v);
                    }
                }
            }
        }
    }
}

// ---------------- gather aggregation, layer 1 (512 feat, fp16 payload) ----------------
// block = one dst node, 128 threads (4 halves = uint2 each).  [R12-proven shape]
__global__ __launch_bounds__(128) void agg1_kernel(const float* __restrict__ b1) {
    const int n    = blockIdx.x;
    const int lane = threadIdx.x & 31;
    const int f    = threadIdx.x * 4;       // half index
    const float di = g_dinv[n];
    const float w0 = di * di;

    uint2 sv = *(const uint2*)&g_h1h[(size_t)n * H_SIZE + f];
    float2 s0 = __half22float2(*(__half2*)&sv.x);
    float2 s1 = __half22float2(*(__half2*)&sv.y);
    float4 acc = make_float4(s0.x * w0, s0.y * w0, s1.x * w0, s1.y * w0);

    const int beg = g_off[n], end = g_off[n + 1];
    for (int base = beg; base < end; base += 32) {
        int idx = base + lane;
        int2 ew = (idx < end) ? g_csr[idx] : make_int2(0, 0);
        const int cnt = min(32, end - base);
        int j = 0;
        for (; j + 8 <= cnt; j += 8) {
            uint2 v[8];
            float wt[8];
            #pragma unroll
            for (int q = 0; q < 8; q++) {
                int   s = __shfl_sync(0xffffffffu, ew.x, j + q);
                wt[q]   = __int_as_float(__shfl_sync(0xffffffffu, ew.y, j + q));
                v[q]    = *(const uint2*)&g_h1h[(size_t)s * H_SIZE + f];
            }
            #pragma unroll
            for (int q = 0; q < 8; q++) {
                float2 a = __half22float2(*(__half2*)&v[q].x);
                float2 b = __half22float2(*(__half2*)&v[q].y);
                acc.x = fmaf(wt[q], a.x, acc.x);
                acc.y = fmaf(wt[q], a.y, acc.y);
                acc.z = fmaf(wt[q], b.x, acc.z);
                acc.w = fmaf(wt[q], b.y, acc.w);
            }
        }
        if (j + 4 <= cnt) {
            uint2 v[4];
            float wt[4];
            #pragma unroll
            for (int q = 0; q < 4; q++) {
                int   s = __shfl_sync(0xffffffffu, ew.x, j + q);
                wt[q]   = __int_as_float(__shfl_sync(0xffffffffu, ew.y, j + q));
                v[q]    = *(const uint2*)&g_h1h[(size_t)s * H_SIZE + f];
            }
            #pragma unroll
            for (int q = 0; q < 4; q++) {
                float2 a = __half22float2(*(__half2*)&v[q].x);
                float2 b = __half22float2(*(__half2*)&v[q].y);
                acc.x = fmaf(wt[q], a.x, acc.x);
                acc.y = fmaf(wt[q], a.y, acc.y);
                acc.z = fmaf(wt[q], b.x, acc.z);
                acc.w = fmaf(wt[q], b.y, acc.w);
            }
            j += 4;
        }
        for (; j < cnt; j++) {
            int   s  = __shfl_sync(0xffffffffu, ew.x, j);
            float wt = __int_as_float(__shfl_sync(0xffffffffu, ew.y, j));
            uint2 v  = *(const uint2*)&g_h1h[(size_t)s * H_SIZE + f];
            float2 a = __half22float2(*(__half2*)&v.x);
            float2 b = __half22float2(*(__half2*)&v.y);
            acc.x = fmaf(wt, a.x, acc.x); acc.y = fmaf(wt, a.y, acc.y);
            acc.z = fmaf(wt, b.x, acc.z); acc.w = fmaf(wt, b.y, acc.w);
        }
    }

    float4 bb = *(const float4*)&b1[f];
    acc.x = fmaxf(acc.x + bb.x, 0.0f);
    acc.y = fmaxf(acc.y + bb.y, 0.0f);
    acc.z = fmaxf(acc.z + bb.z, 0.0f);
    acc.w = fmaxf(acc.w + bb.w, 0.0f);
    *(float4*)&g_agg1[(size_t)n * H_SIZE + f] = acc;
}

// ---------------- fused: layer-2 gather + bias + log_softmax ----------------
__global__ __launch_bounds__(256) void agg2_final_kernel(
    const float* __restrict__ b2, float* __restrict__ out)
{
    int warp = (blockIdx.x * blockDim.x + threadIdx.x) >> 5;
    int lane = threadIdx.x & 31;
    if (warp >= N_NODES) return;

    const float di = g_dinv[warp];
    const float w0 = di * di;
    const float* hrow = &g_h2[(size_t)warp * OUT_SIZE];
    float v0 = hrow[lane]      * w0;
    float v1 = hrow[lane + 32] * w0;

    const int beg = g_off[warp], end = g_off[warp + 1];
    for (int base = beg; base < end; base += 32) {
        int idx = base + lane;
        int2 ew = (idx < end) ? g_csr[idx] : make_int2(0, 0);
        const int cnt = min(32, end - base);
        int j = 0;
        for (; j + 4 <= cnt; j += 4) {
            float a0[4], a1[4], wt[4];
            #pragma unroll
            for (int q = 0; q < 4; q++) {
                int   s = __shfl_sync(0xffffffffu, ew.x, j + q);
                wt[q]   = __int_as_float(__shfl_sync(0xffffffffu, ew.y, j + q));
                const float* r = &g_h2[(size_t)s * OUT_SIZE];
                a0[q] = r[lane];
                a1[q] = r[lane + 32];
            }
            #pragma unroll
            for (int q = 0; q < 4; q++) {
                v0 = fmaf(wt[q], a0[q], v0);
                v1 = fmaf(wt[q], a1[q], v1);
            }
        }
        for (; j < cnt; j++) {
            int   s  = __shfl_sync(0xffffffffu, ew.x, j);
            float wt = __int_as_float(__shfl_sync(0xffffffffu, ew.y, j));
            const float* r = &g_h2[(size_t)s * OUT_SIZE];
            v0 = fmaf(wt, r[lane], v0);
            v1 = fmaf(wt, r[lane + 32], v1);
        }
    }

    v0 += b2[lane];
    v1 += b2[lane + 32];
    out[(size_t)warp * OUT_SIZE + lane]      = v0;
    out[(size_t)warp * OUT_SIZE + lane + 32] = v1;

    float m = fmaxf(v0, v1);
    #pragma unroll
    for (int o = 16; o; o >>= 1) m = fmaxf(m, __shfl_xor_sync(0xffffffffu, m, o));
    float s = __expf(v0 - m) + __expf(v1 - m);
    #pragma unroll
    for (int o = 16; o; o >>= 1) s += __shfl_xor_sync(0xffffffffu, s, o);
    float lse = m + __logf(s);
    float* out2 = out + (size_t)N_NODES * OUT_SIZE;
    out2[(size_t)warp * OUT_SIZE + lane]      = v0 - lse;
    out2[(size_t)warp * OUT_SIZE + lane + 32] = v1 - lse;
}

// ---------------- launch ----------------
extern "C" void kernel_launch(void* const* d_in, const int* in_sizes, int n_in,
                              void* d_out, int out_size)
{
    const float* x  = (const float*)d_in[0];
    const int*   ei = (const int*)  d_in[1];
    const float* W1 = (const float*)d_in[2];
    const float* b1 = (const float*)d_in[3];
    const float* W2 = (const float*)d_in[4];
    const float* b2 = (const float*)d_in[5];
    float* out = (float*)d_out;

    const int* src = ei;
    const int* dst = ei + N_EDGES;

    void *p_w1t, *p_w2t, *p_h1h, *p_agg1, *p_h2;
    cudaGetSymbolAddress(&p_w1t,  g_w1t);
    cudaGetSymbolAddress(&p_w2t,  g_w2t);
    cudaGetSymbolAddress(&p_h1h,  g_h1h);
    cudaGetSymbolAddress(&p_agg1, g_agg1);
    cudaGetSymbolAddress(&p_h2,   g_h2);

    const int SMEM1 = (2 * 128 * 40 + 2 * 128 * 40) * 2;  // 40960 B
    const int SMEM2 = (2 * 128 * 40 + 2 * 64 * 40)  * 2;  // 30720 B
    cudaFuncSetAttribute(gemm_f16_kernel<128, 128, 256, 4, 1, true>,
                         cudaFuncAttributeMaxDynamicSharedMemorySize, SMEM1);
    cudaFuncSetAttribute(gemm_f16_kernel<128, 64, 128, 2, 4, false>,
                         cudaFuncAttributeMaxDynamicSharedMemorySize, SMEM2);

    // one-time side-stream resources (no device memory; work per call identical)
    static cudaStream_t s2 = nullptr;
    static cudaEvent_t evFork = nullptr, evJoin = nullptr;
    if (s2 == nullptr) {
        cudaStreamCreateWithFlags(&s2, cudaStreamNonBlocking);
        cudaEventCreateWithFlags(&evFork, cudaEventDisableTiming);
        cudaEventCreateWithFlags(&evJoin, cudaEventDisableTiming);
    }

    // ---- fork: CSR build (plain kernels, overlappable) on s2 ----
    cudaEventRecord(evFork, 0);
    cudaStreamWaitEvent(s2, evFork, 0);
    prep_kernel     <<<160, 256, 0, s2>>>();
    count_kernel    <<<(N_EDGES + 255) / 256, 256, 0, s2>>>(dst);
    scan_dinv_kernel<<<40, 256, 0, s2>>>();
    fill_kernel     <<<(N_EDGES + 255) / 256, 256, 0, s2>>>(src, dst);
    cudaEventRecord(evJoin, s2);

    // ---- stream 0: weight transpose + GEMM1 (overlaps with s2) ----
    transpose_both_kernel<<<288, 256>>>(W1, W2);
    {
        dim3 grid(H_SIZE / 128, (N_NODES + 127) / 128);
        gemm_f16_kernel<128, 128, 256, 4, 1, true><<<grid, 256, SMEM1>>>(
            x, (const __half*)p_w1t, p_h1h, N_NODES, H_SIZE, IN_SIZE);
    }

    // ---- join, then agg1 (fp16 gathers, fp32 accumulate) ----
    cudaStreamWaitEvent(0, evJoin, 0);
    agg1_kernel<<<N_NODES, 128>>>(b1);

    // ---- layer 2 GEMM, fp16 MMA, split-K=4 (red.add into zeroed h2) ----
    {
        dim3 grid(OUT_SIZE / 64, (N_NODES + 127) / 128, 4);
        gemm_f16_kernel<128, 64, 128, 2, 4, false><<<grid, 128, SMEM2>>>(
            (const float*)p_agg1, (const __half*)p_w2t, p_h2,
            N_NODES, OUT_SIZE, H_SIZE);
    }

    // ---- fused layer-2 gather + bias + log_softmax ----
    agg2_final_kernel<<<(N_NODES * 32 + 255) / 256, 256>>>(b2, out);
}

// round 16
// speedup vs baseline: 3.4761x; 1.0070x over previous
#include <cuda_runtime.h>
#include <cuda_fp16.h>
#include <math.h>

#define N_NODES  10000
#define IN_SIZE  512
#define H_SIZE   512
#define OUT_SIZE 64
#define N_EDGES  163840

// ---------------- scratch (no allocations allowed) ----------------
__device__ int    g_cnt [N_NODES];
__device__ int    g_pos [N_NODES];       // fill cursor, pre-seeded with CSR offset
__device__ int    g_off [N_NODES + 1];
__device__ int2   g_csr [N_EDGES];       // (src, norm-as-bits)
__device__ float  g_dinv[N_NODES];
__device__ __half g_w1t [H_SIZE * IN_SIZE];   // W1^T as half  [N][K]
__device__ __half g_w2t [OUT_SIZE * H_SIZE];  // W2^T as half  [N][K]
__device__ __half g_h1h [N_NODES * H_SIZE];   // x@W1 in fp16 (gather payload)
__device__ float  g_agg1[N_NODES * H_SIZE];   // relu(Â h1 + b1)
__device__ float  g_h2  [N_NODES * OUT_SIZE]; // agg1@W2 (split-K accumulated)

// ---------------- CSR build: plain (non-cooperative) phase kernels ----------------
__global__ __launch_bounds__(256) void prep_kernel() {
    int tid = blockIdx.x * blockDim.x + threadIdx.x;
    int nth = gridDim.x * blockDim.x;
    for (int n = tid; n < N_NODES; n += nth) g_cnt[n] = 0;
    for (int i = tid; i < N_NODES * OUT_SIZE / 4; i += nth)
        ((float4*)g_h2)[i] = make_float4(0.f, 0.f, 0.f, 0.f);
}

// 2 edges per thread, batched loads for MLP
__global__ __launch_bounds__(256) void count_kernel(const int* __restrict__ dst) {
    int t = blockIdx.x * blockDim.x + threadIdx.x;
    int e = t * 2;
    if (e + 1 < N_EDGES) {
        int2 d2 = *(const int2*)&dst[e];
        atomicAdd(&g_cnt[d2.x], 1);
        atomicAdd(&g_cnt[d2.y], 1);
    } else if (e < N_EDGES) {
        atomicAdd(&g_cnt[dst[e]], 1);
    }
}

// all blocks: dinv; block 0 additionally: exclusive scan -> g_off AND g_pos seed
__global__ __launch_bounds__(256) void scan_dinv_kernel() {
    int tid = blockIdx.x * blockDim.x + threadIdx.x;
    int nth = gridDim.x * blockDim.x;
    for (int n = tid; n < N_NODES; n += nth)
        g_dinv[n] = rsqrtf((float)(g_cnt[n] + 1));   // +1 self-loop

    if (blockIdx.x == 0) {
        __shared__ int s[256];
        const int t = threadIdx.x;
        const int CH = (N_NODES + 255) / 256;   // 40
        int base = t * CH;
        int sum = 0;
        for (int i = 0; i < CH; i++) {
            int idx = base + i;
            if (idx < N_NODES) sum += g_cnt[idx];
        }
        s[t] = sum;
        __syncthreads();
        for (int o = 1; o < 256; o <<= 1) {
            int v = (t >= o) ? s[t - o] : 0;
            __syncthreads();
            s[t] += v;
            __syncthreads();
        }
        int run = s[t] - sum;
        for (int i = 0; i < CH; i++) {
            int idx = base + i;
            if (idx < N_NODES) {
                g_off[idx] = run;
                g_pos[idx] = run;          // seed fill cursor with offset
                run += g_cnt[idx];
            }
        }
        if (t == 255) g_off[N_NODES] = N_EDGES;
    }
}

// 2 edges per thread; slot comes straight from pre-seeded cursor
__global__ __launch_bounds__(256) void fill_kernel(
    const int* __restrict__ src, const int* __restrict__ dst)
{
    int t = blockIdx.x * blockDim.x + threadIdx.x;
    int e = t * 2;
    if (e + 1 < N_EDGES) {
        int2 s2v = *(const int2*)&src[e];
        int2 d2v = *(const int2*)&dst[e];
        float ds0 = g_dinv[s2v.x], dd0 = g_dinv[d2v.x];
        float ds1 = g_dinv[s2v.y], dd1 = g_dinv[d2v.y];
        int slot0 = atomicAdd(&g_pos[d2v.x], 1);
        int slot1 = atomicAdd(&g_pos[d2v.y], 1);
        g_csr[slot0] = make_int2(s2v.x, __float_as_int(ds0 * dd0));
        g_csr[slot1] = make_int2(s2v.y, __float_as_int(ds1 * dd1));
    } else if (e < N_EDGES) {
        int sN = src[e], d = dst[e];
        int slot = atomicAdd(&g_pos[d], 1);
        g_csr[slot] = make_int2(sN, __float_as_int(g_dinv[sN] * g_dinv[d]));
    }
}

// ---------------- fused weight transpose + fp16 convert (both W1 and W2) ----------------
// blocks 0..255: W1 (512x512); blocks 256..287: W2 (512x64)
__global__ __launch_bounds__(256) void transpose_both_kernel(
    const float* __restrict__ W1, const float* __restrict__ W2)
{
    __shared__ __half tile[32][33];
    int b = blockIdx.x;
    const float* in;
    __half* out;
    int K, N, bn, bk;
    if (b < 256) {
        in = W1; out = g_w1t; K = IN_SIZE; N = H_SIZE;
        bn = (b & 15) * 32; bk = (b >> 4) * 32;
    } else {
        b -= 256;
        in = W2; out = g_w2t; K = H_SIZE; N = OUT_SIZE;
        bn = (b & 1) * 32; bk = (b >> 1) * 32;
    }
    const int tx = threadIdx.x & 31;
    const int ty = threadIdx.x >> 5;   // 0..7
    for (int i = ty; i < 32; i += 8)
        tile[i][tx] = __float2half_rn(in[(size_t)(bk + i) * N + bn + tx]);
    __syncthreads();
    for (int i = ty; i < 32; i += 8)
        out[(size_t)(bn + i) * K + bk + tx] = tile[tx][i];
}

__device__ __forceinline__ void red_add_v2(float* p, float2 v) {
    asm volatile("red.global.add.v2.f32 [%0], {%1, %2};"
                 :: "l"(p), "f"(v.x), "f"(v.y) : "memory");
}

// ---------------- fp16 m16n8k16 MMA (fp32 accumulate) ----------------
__device__ __forceinline__ void mma_f16(float* d,
    unsigned a0, unsigned a1, unsigned a2, unsigned a3,
    unsigned b0, unsigned b1)
{
    asm volatile(
        "mma.sync.aligned.m16n8k16.row.col.f32.f16.f16.f32 "
        "{%0,%1,%2,%3}, {%4,%5,%6,%7}, {%8,%9}, {%0,%1,%2,%3};"
        : "+f"(d[0]), "+f"(d[1]), "+f"(d[2]), "+f"(d[3])
        : "r"(a0), "r"(a1), "r"(a2), "r"(a3), "r"(b0), "r"(b1));
}

// A: fp32 [M][K] (converted to fp16 during smem staging).
// Bt: fp16 [N][K] (pre-transposed weights).
// HALF_OUT: C is __half*. SPLIT>1: red.add into fp32 C (pre-zeroed).
template<int BM, int BN, int T, int WN, int SPLIT, bool HALF_OUT>
__global__ __launch_bounds__(T) void gemm_f16_kernel(
    const float* __restrict__ A, const __half* __restrict__ Bt,
    void* __restrict__ Cv, int M, int N, int K)
{
    constexpr int BK = 32;
    constexpr int STR = 40;             // half stride: conflict-free frag loads
    constexpr int NA  = BM * BK / (4 * T);   // float4 A loads / thread / tile
    constexpr int NBH = BK * BN / (8 * T);   // uint4 (8-half) B loads / thread / tile

    extern __shared__ char smemraw[];
    __half* AsBase = (__half*)smemraw;            // [2][BM][STR]
    __half* BsBase = AsBase + 2 * BM * STR;       // [2][BN][STR]

    const int tid  = threadIdx.x;
    const int wid  = tid >> 5;
    const int lane = tid & 31;
    const int lr   = lane >> 2;
    const int lc   = lane & 3;
    const int wm   = wid / WN;
    const int wn   = wid % WN;
    const int wrow = wm * 64;
    const int wcol = wn * 32;
    const int brow = blockIdx.y * BM;
    const int bcol = blockIdx.x * BN;
    const int k0   = blockIdx.z * (K / SPLIT);

    float acc[4][4][4];
    #pragma unroll
    for (int i = 0; i < 4; i++)
        #pragma unroll
        for (int j = 0; j < 4; j++)
            #pragma unroll
            for (int q = 0; q < 4; q++) acc[i][j][q] = 0.0f;

    float4 ra[NA];
    uint4  rb[NBH];

    auto ldg_tile = [&](int kk) {
        #pragma unroll
        for (int p = 0; p < NA; p++) {
            int idx = tid + p * T;
            int r = idx >> 3, c4 = (idx & 7) << 2;
            int grow = brow + r;
            ra[p] = (grow < M) ? *(const float4*)&A[(size_t)grow * K + kk + c4]
                               : make_float4(0.f, 0.f, 0.f, 0.f);
        }
        #pragma unroll
        for (int p = 0; p < NBH; p++) {
            int idx = tid + p * T;
            int nrow = idx >> 2, k8 = (idx & 3) << 3;
            rb[p] = *(const uint4*)&Bt[(size_t)(bcol + nrow) * K + kk + k8];
        }
    };

    auto sts_tile = [&](int buf) {
        __half* as = AsBase + buf * BM * STR;
        __half* bs = BsBase + buf * BN * STR;
        #pragma unroll
        for (int p = 0; p < NA; p++) {
            int idx = tid + p * T;
            int r = idx >> 3, c4 = (idx & 7) << 2;
            __half2 h01 = __floats2half2_rn(ra[p].x, ra[p].y);
            __half2 h23 = __floats2half2_rn(ra[p].z, ra[p].w);
            uint2 pk;
            pk.x = *(unsigned*)&h01;
            pk.y = *(unsigned*)&h23;
            *(uint2*)&as[r * STR + c4] = pk;
        }
        #pragma unroll
        for (int p = 0; p < NBH; p++) {
            int idx = tid + p * T;
            int nrow = idx >> 2, k8 = (idx & 3) << 3;
            *(uint4*)&bs[nrow * STR + k8] = rb[p];
        }
    };

    auto compute = [&](int buf) {
        const __half* as = AsBase + buf * BM * STR;
        const __half* bs = BsBase + buf * BN * STR;
        #pragma unroll
        for (int s = 0; s < 2; s++) {           // two k16 steps per BK=32 tile
            const int kb = s * 16 + lc * 2;
            unsigned a0[4], a1[4], a2[4], a3[4];
            #pragma unroll
            for (int i = 0; i < 4; i++) {
                const __half* p0 = &as[(wrow + i * 16 + lr) * STR + kb];
                a0[i] = *(const unsigned*)p0;
                a1[i] = *(const unsigned*)(p0 + 8 * STR);
                a2[i] = *(const unsigned*)(p0 + 8);
                a3[i] = *(const unsigned*)(p0 + 8 * STR + 8);
            }
            unsigned b0[4], b1[4];
            #pragma unroll
            for (int j = 0; j < 4; j++) {
                const __half* p = &bs[(wcol + j * 8 + lr) * STR + kb];
                b0[j] = *(const unsigned*)p;
                b1[j] = *(const unsigned*)(p + 8);
            }
            #pragma unroll
            for (int i = 0; i < 4; i++)
                #pragma unroll
                for (int j = 0; j < 4; j++)
                    mma_f16(acc[i][j], a0[i], a1[i], a2[i], a3[i], b0[j], b1[j]);
        }
    };

    ldg_tile(k0);
    sts_tile(0);
    __syncthreads();
    int buf = 0;
    const int ntiles = K / SPLIT / BK;
    for (int t = 0; t < ntiles; t++) {
        if (t + 1 < ntiles) ldg_tile(k0 + (t + 1) * BK);
        compute(buf);
        if (t + 1 < ntiles) {
            sts_tile(buf ^ 1);
            __syncthreads();
            buf ^= 1;
        }
    }

    #pragma unroll
    for (int i = 0; i < 4; i++) {
        int r0 = brow + wrow + i * 16 + lr;
        #pragma unroll
        for (int half = 0; half < 2; half++) {
            int r = r0 + half * 8;
            if (r < M) {
                #pragma unroll
                for (int j = 0; j < 4; j++) {
                    int cc = bcol + wcol + j * 8 + lc * 2;
                    float2 v = make_float2(acc[i][j][half * 2 + 0], acc[i][j][half * 2 + 1]);
                    if (HALF_OUT) {
                        __half* C = (__half*)Cv;
                        *(__half2*)&C[(size_t)r * N + cc] = __floats2half2_rn(v.x, v.y);
                    } else if (SPLIT == 1) {
                        float* C = (float*)Cv;
                        *(float2*)&C[(size_t)r * N + cc] = v;
                    } else {
                        float* C = (float*)Cv;
                        red_add_v2(&C[(size_t)r * N + cc], v);
                    }
                }
            }
        }
    }
}

// ---------------- gather aggregation, layer 1 (512 feat, fp16 payload) ----------------
// block = one dst node, 128 threads (4 halves = uint2 each).  [R12-proven shape]
__global__ __launch_bounds__(128) void agg1_kernel(const float* __restrict__ b1) {
    const int n    = blockIdx.x;
    const int lane = threadIdx.x & 31;
    const int f    = threadIdx.x * 4;       // half index
    const float di = g_dinv[n];
    const float w0 = di * di;

    uint2 sv = *(const uint2*)&g_h1h[(size_t)n * H_SIZE + f];
    float2 s0 = __half22float2(*(__half2*)&sv.x);
    float2 s1 = __half22float2(*(__half2*)&sv.y);
    float4 acc = make_float4(s0.x * w0, s0.y * w0, s1.x * w0, s1.y * w0);

    const int beg = g_off[n], end = g_off[n + 1];
    for (int base = beg; base < end; base += 32) {
        int idx = base + lane;
        int2 ew = (idx < end) ? g_csr[idx] : make_int2(0, 0);
        const int cnt = min(32, end - base);
        int j = 0;
        for (; j + 8 <= cnt; j += 8) {
            uint2 v[8];
            float wt[8];
            #pragma unroll
            for (int q = 0; q < 8; q++) {
                int   s = __shfl_sync(0xffffffffu, ew.x, j + q);
                wt[q]   = __int_as_float(__shfl_sync(0xffffffffu, ew.y, j + q));
                v[q]    = *(const uint2*)&g_h1h[(size_t)s * H_SIZE + f];
            }
            #pragma unroll
            for (int q = 0; q < 8; q++) {
                float2 a = __half22float2(*(__half2*)&v[q].x);
                float2 b = __half22float2(*(__half2*)&v[q].y);
                acc.x = fmaf(wt[q], a.x, acc.x);
                acc.y = fmaf(wt[q], a.y, acc.y);
                acc.z = fmaf(wt[q], b.x, acc.z);
                acc.w = fmaf(wt[q], b.y, acc.w);
            }
        }
        if (j + 4 <= cnt) {
            uint2 v[4];
            float wt[4];
            #pragma unroll
            for (int q = 0; q < 4; q++) {
                int   s = __shfl_sync(0xffffffffu, ew.x, j + q);
                wt[q]   = __int_as_float(__shfl_sync(0xffffffffu, ew.y, j + q));
                v[q]    = *(const uint2*)&g_h1h[(size_t)s * H_SIZE + f];
            }
            #pragma unroll
            for (int q = 0; q < 4; q++) {
                float2 a = __half22float2(*(__half2*)&v[q].x);
                float2 b = __half22float2(*(__half2*)&v[q].y);
                acc.x = fmaf(wt[q], a.x, acc.x);
                acc.y = fmaf(wt[q], a.y, acc.y);
                acc.z = fmaf(wt[q], b.x, acc.z);
                acc.w = fmaf(wt[q], b.y, acc.w);
            }
            j += 4;
        }
        for (; j < cnt; j++) {
            int   s  = __shfl_sync(0xffffffffu, ew.x, j);
            float wt = __int_as_float(__shfl_sync(0xffffffffu, ew.y, j));
            uint2 v  = *(const uint2*)&g_h1h[(size_t)s * H_SIZE + f];
            float2 a = __half22float2(*(__half2*)&v.x);
            float2 b = __half22float2(*(__half2*)&v.y);
            acc.x = fmaf(wt, a.x, acc.x); acc.y = fmaf(wt, a.y, acc.y);
            acc.z = fmaf(wt, b.x, acc.z); acc.w = fmaf(wt, b.y, acc.w);
        }
    }

    float4 bb = *(const float4*)&b1[f];
    acc.x = fmaxf(acc.x + bb.x, 0.0f);
    acc.y = fmaxf(acc.y + bb.y, 0.0f);
    acc.z = fmaxf(acc.z + bb.z, 0.0f);
    acc.w = fmaxf(acc.w + bb.w, 0.0f);
    *(float4*)&g_agg1[(size_t)n * H_SIZE + f] = acc;
}

// ---------------- fused: layer-2 gather + bias + log_softmax ----------------
__global__ __launch_bounds__(256) void agg2_final_kernel(
    const float* __restrict__ b2, float* __restrict__ out)
{
    int warp = (blockIdx.x * blockDim.x + threadIdx.x) >> 5;
    int lane = threadIdx.x & 31;
    if (warp >= N_NODES) return;

    const float di = g_dinv[warp];
    const float w0 = di * di;
    const float* hrow = &g_h2[(size_t)warp * OUT_SIZE];
    float v0 = hrow[lane]      * w0;
    float v1 = hrow[lane + 32] * w0;

    const int beg = g_off[warp], end = g_off[warp + 1];
    for (int base = beg; base < end; base += 32) {
        int idx = base + lane;
        int2 ew = (idx < end) ? g_csr[idx] : make_int2(0, 0);
        const int cnt = min(32, end - base);
        int j = 0;
        for (; j + 4 <= cnt; j += 4) {
            float a0[4], a1[4], wt[4];
            #pragma unroll
            for (int q = 0; q < 4; q++) {
                int   s = __shfl_sync(0xffffffffu, ew.x, j + q);
                wt[q]   = __int_as_float(__shfl_sync(0xffffffffu, ew.y, j + q));
                const float* r = &g_h2[(size_t)s * OUT_SIZE];
                a0[q] = r[lane];
                a1[q] = r[lane + 32];
            }
            #pragma unroll
            for (int q = 0; q < 4; q++) {
                v0 = fmaf(wt[q], a0[q], v0);
                v1 = fmaf(wt[q], a1[q], v1);
            }
        }
        for (; j < cnt; j++) {
            int   s  = __shfl_sync(0xffffffffu, ew.x, j);
            float wt = __int_as_float(__shfl_sync(0xffffffffu, ew.y, j));
            const float* r = &g_h2[(size_t)s * OUT_SIZE];
            v0 = fmaf(wt, r[lane], v0);
            v1 = fmaf(wt, r[lane + 32], v1);
        }
    }

    v0 += b2[lane];
    v1 += b2[lane + 32];
    out[(size_t)warp * OUT_SIZE + lane]      = v0;
    out[(size_t)warp * OUT_SIZE + lane + 32] = v1;

    float m = fmaxf(v0, v1);
    #pragma unroll
    for (int o = 16; o; o >>= 1) m = fmaxf(m, __shfl_xor_sync(0xffffffffu, m, o));
    float s = __expf(v0 - m) + __expf(v1 - m);
    #pragma unroll
    for (int o = 16; o; o >>= 1) s += __shfl_xor_sync(0xffffffffu, s, o);
    float lse = m + __logf(s);
    float* out2 = out + (size_t)N_NODES * OUT_SIZE;
    out2[(size_t)warp * OUT_SIZE + lane]      = v0 - lse;
    out2[(size_t)warp * OUT_SIZE + lane + 32] = v1 - lse;
}

// ---------------- launch ----------------
extern "C" void kernel_launch(void* const* d_in, const int* in_sizes, int n_in,
                              void* d_out, int out_size)
{
    const float* x  = (const float*)d_in[0];
    const int*   ei = (const int*)  d_in[1];
    const float* W1 = (const float*)d_in[2];
    const float* b1 = (const float*)d_in[3];
    const float* W2 = (const float*)d_in[4];
    const float* b2 = (const float*)d_in[5];
    float* out = (float*)d_out;

    const int* src = ei;
    const int* dst = ei + N_EDGES;

    void *p_w1t, *p_w2t, *p_h1h, *p_agg1, *p_h2;
    cudaGetSymbolAddress(&p_w1t,  g_w1t);
    cudaGetSymbolAddress(&p_w2t,  g_w2t);
    cudaGetSymbolAddress(&p_h1h,  g_h1h);
    cudaGetSymbolAddress(&p_agg1, g_agg1);
    cudaGetSymbolAddress(&p_h2,   g_h2);

    const int SMEM1 = (2 * 128 * 40 + 2 * 128 * 40) * 2;  // 40960 B
    const int SMEM2 = (2 * 128 * 40 + 2 * 64 * 40)  * 2;  // 30720 B
    cudaFuncSetAttribute(gemm_f16_kernel<128, 128, 256, 4, 1, true>,
                         cudaFuncAttributeMaxDynamicSharedMemorySize, SMEM1);
    cudaFuncSetAttribute(gemm_f16_kernel<128, 64, 128, 2, 4, false>,
                         cudaFuncAttributeMaxDynamicSharedMemorySize, SMEM2);

    // one-time side-stream resources (no device memory; work per call identical)
    static cudaStream_t s2 = nullptr;
    static cudaEvent_t evFork = nullptr, evJoin = nullptr;
    if (s2 == nullptr) {
        cudaStreamCreateWithFlags(&s2, cudaStreamNonBlocking);
        cudaEventCreateWithFlags(&evFork, cudaEventDisableTiming);
        cudaEventCreateWithFlags(&evJoin, cudaEventDisableTiming);
    }

    // ---- fork: CSR build (plain kernels, overlappable) on s2 ----
    cudaEventRecord(evFork, 0);
    cudaStreamWaitEvent(s2, evFork, 0);
    prep_kernel     <<<148, 256, 0, s2>>>();
    count_kernel    <<<(N_EDGES / 2 + 255) / 256, 256, 0, s2>>>(dst);
    scan_dinv_kernel<<<40, 256, 0, s2>>>();
    fill_kernel     <<<(N_EDGES / 2 + 255) / 256, 256, 0, s2>>>(src, dst);
    cudaEventRecord(evJoin, s2);

    // ---- stream 0: weight transpose + GEMM1 (overlaps with s2) ----
    transpose_both_kernel<<<288, 256>>>(W1, W2);
    {
        dim3 grid(H_SIZE / 128, (N_NODES + 127) / 128);
        gemm_f16_kernel<128, 128, 256, 4, 1, true><<<grid, 256, SMEM1>>>(
            x, (const __half*)p_w1t, p_h1h, N_NODES, H_SIZE, IN_SIZE);
    }

    // ---- join, then agg1 (fp16 gathers, fp32 accumulate) ----
    cudaStreamWaitEvent(0, evJoin, 0);
    agg1_kernel<<<N_NODES, 128>>>(b1);

    // ---- layer 2 GEMM, fp16 MMA, split-K=4 (red.add into zeroed h2) ----
    {
        dim3 grid(OUT_SIZE / 64, (N_NODES + 127) / 128, 4);
        gemm_f16_kernel<128, 64, 128, 2, 4, false><<<grid, 128, SMEM2>>>(
            (const float*)p_agg1, (const __half*)p_w2t, p_h2,
            N_NODES, OUT_SIZE, H_SIZE);
    }

    // ---- fused layer-2 gather + bias + log_softmax ----
    agg2_final_kernel<<<(N_NODES * 32 + 255) / 256, 256>>>(b2, out);
}